// round 1
// baseline (speedup 1.0000x reference)
#include <cuda_runtime.h>
#include <math.h>

#define Bsz 256
#define Tt  256
#define Isz 128
#define Hsz 512
#define Csz 10
#define NG  2048   // 4*H

// ---------------- scratch (static device globals; no runtime alloc) ----------------
__device__ float g_Zx1[(size_t)Tt * Bsz * NG];          // 512 MB: x@Wx1+b1 for all t
__device__ float g_Zx2[(size_t)Tt * Bsz * NG];          // 512 MB: h1@Wx2+b2 for all t
__device__ float g_h1[(size_t)(Tt + 1) * Bsz * Hsz];    // h1 sequence, slot 0 = zeros
__device__ float g_h2[(size_t)(Tt + 1) * Bsz * Hsz];    // h2 sequence, slot 0 = zeros
__device__ float g_c1[Bsz * Hsz];
__device__ float g_c2[Bsz * Hsz];

// ---------------- init: zero recurrent state ----------------
__global__ void init_state_kernel() {
    int i = blockIdx.x * blockDim.x + threadIdx.x;
    if (i < Bsz * Hsz) {
        g_c1[i] = 0.f;
        g_c2[i] = 0.f;
        g_h1[i] = 0.f;   // slot 0
        g_h2[i] = 0.f;   // slot 0
    }
}

// ---------------- big input GEMM: Z[m, n] = sum_k A[m,k] * W[g,k,h] + bias[n] ----------------
// n in [0,2048): g = n>>9, h = n&511. 64-wide n-tiles never straddle a gate (512%64==0).
// XPERM: A rows are permuted x rows: m = t*B + b, x stored [B,T,I].
template <bool XPERM>
__global__ void __launch_bounds__(256)
gemm_bias_kernel(const float* __restrict__ A,
                 const float* __restrict__ W,     // [4, K, H]
                 const float* __restrict__ bias,  // [4*H] flat
                 float* __restrict__ Z,
                 int K) {
    __shared__ float As[16][65];
    __shared__ float Bs[16][65];

    const int m0 = blockIdx.y * 64;
    const int n0 = blockIdx.x * 64;
    const int gate = n0 >> 9;
    const int h0 = n0 & 511;
    const float* Bp = W + (size_t)gate * K * Hsz + h0;

    const int tid = threadIdx.x;
    const int tx = tid & 15, ty = tid >> 4;

    float acc[4][4] = {};

    for (int kk = 0; kk < K; kk += 16) {
        #pragma unroll
        for (int i = 0; i < 4; i++) {
            int idx = tid + i * 256;
            int m = idx >> 4, k = idx & 15;
            long arow;
            if (XPERM) {
                int gm = m0 + m;                         // gm = t*B + b
                arow = (long)((gm & (Bsz - 1)) * Tt + (gm >> 8)) * Isz;  // x[b,t,:]
            } else {
                arow = (long)(m0 + m) * K;
            }
            As[k][m] = A[arow + kk + k];
        }
        #pragma unroll
        for (int i = 0; i < 4; i++) {
            int idx = tid + i * 256;
            int k = idx >> 6, n = idx & 63;
            Bs[k][n] = Bp[(size_t)(kk + k) * Hsz + n];
        }
        __syncthreads();
        #pragma unroll
        for (int k = 0; k < 16; k++) {
            float a[4], b[4];
            #pragma unroll
            for (int i = 0; i < 4; i++) a[i] = As[k][ty + 16 * i];
            #pragma unroll
            for (int j = 0; j < 4; j++) b[j] = Bs[k][tx + 16 * j];
            #pragma unroll
            for (int i = 0; i < 4; i++)
                #pragma unroll
                for (int j = 0; j < 4; j++)
                    acc[i][j] += a[i] * b[j];
        }
        __syncthreads();
    }

    #pragma unroll
    for (int i = 0; i < 4; i++) {
        int m = m0 + ty + 16 * i;
        #pragma unroll
        for (int j = 0; j < 4; j++) {
            int n = n0 + tx + 16 * j;
            Z[(size_t)m * NG + n] = acc[i][j] + bias[n];
        }
    }
}

// ---------------- recurrent step: z = Zx[t] + h_prev@Wh, gates, cell update ----------------
// CTA tile: 64 batch rows x (4 gates x 16 h-cols). Grid: (32, 4).
__global__ void __launch_bounds__(256)
lstm_step_kernel(const float* __restrict__ Zx,    // [B, 4H] for this t
                 const float* __restrict__ hprev, // [B, H]
                 const float* __restrict__ Wh,    // [4, H, H]
                 float* __restrict__ c,           // [B, H]
                 float* __restrict__ hout) {      // [B, H]
    __shared__ float As[16][65];
    __shared__ float Bs[16][65];
    __shared__ float zs[64][65];

    const int m0 = blockIdx.y * 64;   // batch block
    const int h0 = blockIdx.x * 16;   // h block
    const int tid = threadIdx.x;
    const int tx = tid & 15, ty = tid >> 4;

    float acc[4][4] = {};

    for (int kk = 0; kk < Hsz; kk += 16) {
        #pragma unroll
        for (int i = 0; i < 4; i++) {
            int idx = tid + i * 256;
            int m = idx >> 4, k = idx & 15;
            As[k][m] = hprev[(size_t)(m0 + m) * Hsz + kk + k];
        }
        #pragma unroll
        for (int i = 0; i < 4; i++) {
            int idx = tid + i * 256;
            int k = idx >> 6, j = idx & 63;
            int g = j >> 4, hh = j & 15;
            Bs[k][j] = Wh[((size_t)g * Hsz + kk + k) * Hsz + h0 + hh];
        }
        __syncthreads();
        #pragma unroll
        for (int k = 0; k < 16; k++) {
            float a[4], b[4];
            #pragma unroll
            for (int i = 0; i < 4; i++) a[i] = As[k][ty + 16 * i];
            #pragma unroll
            for (int j = 0; j < 4; j++) b[j] = Bs[k][tx + 16 * j];
            #pragma unroll
            for (int i = 0; i < 4; i++)
                #pragma unroll
                for (int j = 0; j < 4; j++)
                    acc[i][j] += a[i] * b[j];
        }
        __syncthreads();
    }

    // stage z (recurrent part + precomputed input part) into smem
    #pragma unroll
    for (int i = 0; i < 4; i++) {
        int m = ty + 16 * i;
        #pragma unroll
        for (int j = 0; j < 4; j++) {
            int n = tx + 16 * j;             // 0..63: g = n>>4, hh = n&15
            int g = n >> 4, hh = n & 15;
            zs[m][n] = acc[i][j] + Zx[(size_t)(m0 + m) * NG + g * Hsz + h0 + hh];
        }
    }
    __syncthreads();

    // gate math: 64 rows x 16 h = 1024 cells, 4 per thread
    #pragma unroll
    for (int i = 0; i < 4; i++) {
        int cell = tid + i * 256;
        int r = cell >> 4;
        int hh = cell & 15;
        float zg = zs[r][hh];
        float zi = zs[r][16 + hh];
        float zf = zs[r][32 + hh];
        float zo = zs[r][48 + hh];
        float gg = tanhf(zg);
        float ii = 1.f / (1.f + expf(-zi));
        float ff = 1.f / (1.f + expf(-zf));
        float oo = 1.f / (1.f + expf(-zo));
        size_t cidx = (size_t)(m0 + r) * Hsz + h0 + hh;
        float cn = gg * ii + c[cidx] * ff;
        c[cidx] = cn;
        hout[cidx] = tanhf(cn) * oo;
    }
}

// ---------------- final projection: out[b,c] = h2[b,:]@Wph[:,c] + bp[c] ----------------
__global__ void proj_kernel(const float* __restrict__ h2,
                            const float* __restrict__ Wph,  // [H, C]
                            const float* __restrict__ bp,   // [C]
                            float* __restrict__ out) {
    int idx = blockIdx.x * blockDim.x + threadIdx.x;
    if (idx >= Bsz * Csz) return;
    int b = idx / Csz, cc = idx % Csz;
    float s = bp[cc];
    for (int k = 0; k < Hsz; k++)
        s += h2[(size_t)b * Hsz + k] * Wph[(size_t)k * Csz + cc];
    out[idx] = s;
}

// ---------------- launch ----------------
extern "C" void kernel_launch(void* const* d_in, const int* in_sizes, int n_in,
                              void* d_out, int out_size) {
    const float* x   = (const float*)d_in[0];
    const float* Wx1 = (const float*)d_in[1];
    const float* Wh1 = (const float*)d_in[2];
    const float* b1  = (const float*)d_in[3];
    const float* Wx2 = (const float*)d_in[4];
    const float* Wh2 = (const float*)d_in[5];
    const float* b2  = (const float*)d_in[6];
    const float* Wph = (const float*)d_in[7];
    const float* bp  = (const float*)d_in[8];
    float* out = (float*)d_out;

    float *Zx1, *Zx2, *h1, *h2, *c1, *c2;
    cudaGetSymbolAddress((void**)&Zx1, g_Zx1);
    cudaGetSymbolAddress((void**)&Zx2, g_Zx2);
    cudaGetSymbolAddress((void**)&h1,  g_h1);
    cudaGetSymbolAddress((void**)&h2,  g_h2);
    cudaGetSymbolAddress((void**)&c1,  g_c1);
    cudaGetSymbolAddress((void**)&c2,  g_c2);

    // zero recurrent state (deterministic per call)
    init_state_kernel<<<(Bsz * Hsz + 255) / 256, 256>>>();

    // Phase 1: Zx1 = x @ Wx1 + b1   (M = T*B = 65536, K = I = 128)
    {
        dim3 grid(NG / 64, (Tt * Bsz) / 64);
        gemm_bias_kernel<true><<<grid, 256>>>(x, Wx1, b1, Zx1, Isz);
    }

    // Phase 2: layer-1 recurrence
    {
        dim3 grid(Hsz / 16, Bsz / 64);
        for (int t = 0; t < Tt; t++) {
            lstm_step_kernel<<<grid, 256>>>(
                Zx1 + (size_t)t * Bsz * NG,
                h1 + (size_t)t * Bsz * Hsz,
                Wh1, c1,
                h1 + (size_t)(t + 1) * Bsz * Hsz);
        }
    }

    // Phase 3: Zx2 = h1_seq @ Wx2 + b2   (M = 65536, K = H = 512)
    {
        dim3 grid(NG / 64, (Tt * Bsz) / 64);
        gemm_bias_kernel<false><<<grid, 256>>>(h1 + (size_t)Bsz * Hsz, Wx2, b2, Zx2, Hsz);
    }

    // Phase 4: layer-2 recurrence
    {
        dim3 grid(Hsz / 16, Bsz / 64);
        for (int t = 0; t < Tt; t++) {
            lstm_step_kernel<<<grid, 256>>>(
                Zx2 + (size_t)t * Bsz * NG,
                h2 + (size_t)t * Bsz * Hsz,
                Wh2, c2,
                h2 + (size_t)(t + 1) * Bsz * Hsz);
        }
    }

    // Phase 5: projection from final h2
    proj_kernel<<<(Bsz * Csz + 255) / 256, 256>>>(
        h2 + (size_t)Tt * Bsz * Hsz, Wph, bp, out);
}

// round 2
// speedup vs baseline: 2.1555x; 2.1555x over previous
#include <cuda_runtime.h>
#include <math.h>
#include <stdint.h>

#define Bsz 256
#define Tt  256
#define Isz 128
#define Hsz 512
#define Csz 10
#define NG  2048   // 4*H

#define PA 36      // A smem pitch (floats), ≡4 mod 32 -> conflict-free frag loads
#define PB 72      // B smem pitch (floats), ≡8 mod 32 -> conflict-free frag loads
#define PZ 68      // z staging pitch

// ---------------- scratch (static device globals; no runtime alloc) ----------------
__device__ float g_Zx1[(size_t)Tt * Bsz * NG];
__device__ float g_Zx2[(size_t)Tt * Bsz * NG];
__device__ float g_h1[(size_t)(Tt + 1) * Bsz * Hsz];
__device__ float g_h2[(size_t)(Tt + 1) * Bsz * Hsz];
__device__ float g_c1[Bsz * Hsz];
__device__ float g_c2[Bsz * Hsz];

// ---------------- helpers ----------------
__device__ __forceinline__ uint32_t f2tf(float f) {
    uint32_t u;
    asm("cvt.rna.tf32.f32 %0, %1;" : "=r"(u) : "f"(f));
    return u;
}

// D += A*B, m16n8k8 tf32
__device__ __forceinline__ void mma8(float* c, const uint32_t* a, const uint32_t* b) {
    asm volatile(
        "mma.sync.aligned.m16n8k8.row.col.f32.tf32.tf32.f32 "
        "{%0,%1,%2,%3},{%4,%5,%6,%7},{%8,%9},{%0,%1,%2,%3};"
        : "+f"(c[0]), "+f"(c[1]), "+f"(c[2]), "+f"(c[3])
        : "r"(a[0]), "r"(a[1]), "r"(a[2]), "r"(a[3]), "r"(b[0]), "r"(b[1]));
}

// ---------------- init ----------------
__global__ void init_state_kernel() {
    int i = blockIdx.x * blockDim.x + threadIdx.x;
    if (i < Bsz * Hsz) {
        g_c1[i] = 0.f;
        g_c2[i] = 0.f;
        g_h1[i] = 0.f;
        g_h2[i] = 0.f;
    }
}

// ---------------- recurrent step (tensor-core): z = Zx[t] + hprev@Wh; gates; cell ----------------
// CTA tile: 64 batch x (4 gates x 16 h-cols). 128 threads = 4 warps (2x2, warp tile 32x32).
// Grid: (Hsz/16=32, Bsz/64=4) = 128 CTAs.
__global__ void __launch_bounds__(128)
lstm_step_mma(const float* __restrict__ Zx,     // [B, 4H] for this t
              const float* __restrict__ hprev,  // [B, H]
              const float* __restrict__ Wh,     // [4, H, H]
              float* __restrict__ c,            // [B, H]
              float* __restrict__ hout) {       // [B, H]
    __shared__ uint32_t As[64 * PA];   // m-major: As[m*PA + k]
    __shared__ uint32_t Bs[32 * PB];   // k-major: Bs[k*PB + j], j = g*16+hh
    __shared__ float    zs[64 * PZ];

    const int m0 = blockIdx.y * 64;
    const int h0 = blockIdx.x * 16;
    const int tid = threadIdx.x, lane = tid & 31, wid = tid >> 5;
    const int gid = lane >> 2, tig = lane & 3;
    const int wm0 = (wid & 1) * 32, wn0 = (wid >> 1) * 32;

    float4 ra[4], rb[4];
    #pragma unroll
    for (int i = 0; i < 4; i++) {
        int idx = tid + i * 128;
        ra[i] = *(const float4*)(hprev + (size_t)(m0 + (idx >> 3)) * Hsz + (idx & 7) * 4);
        int k = idx >> 4, nq = idx & 15, j = nq * 4, g = j >> 4, hh = j & 15;
        rb[i] = *(const float4*)(Wh + (size_t)g * Hsz * Hsz + (size_t)k * Hsz + h0 + hh);
    }

    float acc[8][4] = {};   // tile t = mt*4 + nt

    #pragma unroll 1
    for (int ch = 0; ch < 16; ch++) {
        __syncthreads();
        #pragma unroll
        for (int i = 0; i < 4; i++) {
            int idx = tid + i * 128;
            {
                int row = idx >> 3, kq = idx & 7;
                uint4 u = {f2tf(ra[i].x), f2tf(ra[i].y), f2tf(ra[i].z), f2tf(ra[i].w)};
                *(uint4*)&As[row * PA + kq * 4] = u;
            }
            {
                int k = idx >> 4, nq = idx & 15;
                uint4 u = {f2tf(rb[i].x), f2tf(rb[i].y), f2tf(rb[i].z), f2tf(rb[i].w)};
                *(uint4*)&Bs[k * PB + nq * 4] = u;
            }
        }
        __syncthreads();
        if (ch < 15) {
            int kk = (ch + 1) * 32;
            #pragma unroll
            for (int i = 0; i < 4; i++) {
                int idx = tid + i * 128;
                ra[i] = *(const float4*)(hprev + (size_t)(m0 + (idx >> 3)) * Hsz + kk + (idx & 7) * 4);
                int k = idx >> 4, nq = idx & 15, j = nq * 4, g = j >> 4, hh = j & 15;
                rb[i] = *(const float4*)(Wh + (size_t)g * Hsz * Hsz + (size_t)(kk + k) * Hsz + h0 + hh);
            }
        }
        #pragma unroll
        for (int ks = 0; ks < 4; ks++) {
            uint32_t a[2][4], b[2];
            #pragma unroll
            for (int mt = 0; mt < 2; mt++) {
                int m = wm0 + mt * 16;
                a[mt][0] = As[(m + gid) * PA + ks * 8 + tig];
                a[mt][1] = As[(m + 8 + gid) * PA + ks * 8 + tig];
                a[mt][2] = As[(m + gid) * PA + ks * 8 + tig + 4];
                a[mt][3] = As[(m + 8 + gid) * PA + ks * 8 + tig + 4];
            }
            #pragma unroll
            for (int nt = 0; nt < 4; nt++) {
                b[0] = Bs[(ks * 8 + tig) * PB + wn0 + nt * 8 + gid];
                b[1] = Bs[(ks * 8 + tig + 4) * PB + wn0 + nt * 8 + gid];
                mma8(acc[nt], a[0], b);
                mma8(acc[4 + nt], a[1], b);
            }
        }
    }

    // stage z into smem
    #pragma unroll
    for (int t = 0; t < 8; t++) {
        int mt = t >> 2, nt = t & 3;
        int row = wm0 + mt * 16 + gid, col = wn0 + nt * 8 + tig * 2;
        *(float2*)&zs[row * PZ + col]       = make_float2(acc[t][0], acc[t][1]);
        *(float2*)&zs[(row + 8) * PZ + col] = make_float2(acc[t][2], acc[t][3]);
    }
    __syncthreads();

    // gate math: 64 rows x 16 h = 1024 cells, 8 per thread
    #pragma unroll
    for (int i = 0; i < 8; i++) {
        int cell = tid + i * 128;
        int r = cell >> 4, hh = cell & 15;
        const float* zrow = &zs[r * PZ];
        const float* zxr = Zx + (size_t)(m0 + r) * NG + h0 + hh;
        float zg = zrow[hh]      + zxr[0];
        float zi = zrow[16 + hh] + zxr[512];
        float zf = zrow[32 + hh] + zxr[1024];
        float zo = zrow[48 + hh] + zxr[1536];
        float gg = tanhf(zg);
        float ii = 1.f / (1.f + __expf(-zi));
        float ff = 1.f / (1.f + __expf(-zf));
        float oo = 1.f / (1.f + __expf(-zo));
        size_t ci = (size_t)(m0 + r) * Hsz + h0 + hh;
        float cn = gg * ii + c[ci] * ff;
        c[ci] = cn;
        hout[ci] = tanhf(cn) * oo;
    }
}

// ---------------- big input GEMM (tensor-core): Z = A @ W[g] + bias ----------------
// CTA tile 128x64, 256 threads = 8 warps (4x2, warp tile 32x32).
// Grid: (NG/64=32, M/128=512).
template <bool XPERM>
__global__ void __launch_bounds__(256)
gemm_mma(const float* __restrict__ A,
         const float* __restrict__ W,     // [4, K, H]
         const float* __restrict__ bias,  // [4*H]
         float* __restrict__ Z,
         int K) {
    __shared__ uint32_t As[128 * PA];
    __shared__ uint32_t Bs[32 * PB];

    const int m0 = blockIdx.y * 128, n0 = blockIdx.x * 64;
    const int gate = n0 >> 9, h0 = n0 & 511;
    const float* Bg = W + (size_t)gate * K * Hsz + h0;
    const int tid = threadIdx.x, lane = tid & 31, wid = tid >> 5;
    const int gid = lane >> 2, tig = lane & 3;
    const int wm0 = (wid & 3) * 32, wn0 = (wid >> 2) * 32;

    float4 ra[4], rb[2];
    #pragma unroll
    for (int i = 0; i < 4; i++) {
        int idx = tid + i * 256;
        int row = idx >> 3, kq = idx & 7;
        size_t ar;
        if (XPERM) { int gm = m0 + row; ar = (size_t)((gm & 255) * Tt + (gm >> 8)) * Isz; }
        else       { ar = (size_t)(m0 + row) * K; }
        ra[i] = *(const float4*)(A + ar + kq * 4);
    }
    #pragma unroll
    for (int i = 0; i < 2; i++) {
        int idx = tid + i * 256;
        rb[i] = *(const float4*)(Bg + (size_t)(idx >> 4) * Hsz + (idx & 15) * 4);
    }

    float acc[8][4] = {};
    const int NC = K / 32;

    #pragma unroll 1
    for (int ch = 0; ch < NC; ch++) {
        __syncthreads();
        #pragma unroll
        for (int i = 0; i < 4; i++) {
            int idx = tid + i * 256;
            int row = idx >> 3, kq = idx & 7;
            uint4 u = {f2tf(ra[i].x), f2tf(ra[i].y), f2tf(ra[i].z), f2tf(ra[i].w)};
            *(uint4*)&As[row * PA + kq * 4] = u;
        }
        #pragma unroll
        for (int i = 0; i < 2; i++) {
            int idx = tid + i * 256;
            int k = idx >> 4, nq = idx & 15;
            uint4 u = {f2tf(rb[i].x), f2tf(rb[i].y), f2tf(rb[i].z), f2tf(rb[i].w)};
            *(uint4*)&Bs[k * PB + nq * 4] = u;
        }
        __syncthreads();
        if (ch + 1 < NC) {
            int kk = (ch + 1) * 32;
            #pragma unroll
            for (int i = 0; i < 4; i++) {
                int idx = tid + i * 256;
                int row = idx >> 3, kq = idx & 7;
                size_t ar;
                if (XPERM) { int gm = m0 + row; ar = (size_t)((gm & 255) * Tt + (gm >> 8)) * Isz; }
                else       { ar = (size_t)(m0 + row) * K; }
                ra[i] = *(const float4*)(A + ar + kk + kq * 4);
            }
            #pragma unroll
            for (int i = 0; i < 2; i++) {
                int idx = tid + i * 256;
                rb[i] = *(const float4*)(Bg + (size_t)(kk + (idx >> 4)) * Hsz + (idx & 15) * 4);
            }
        }
        #pragma unroll
        for (int ks = 0; ks < 4; ks++) {
            uint32_t a[2][4], b[2];
            #pragma unroll
            for (int mt = 0; mt < 2; mt++) {
                int m = wm0 + mt * 16;
                a[mt][0] = As[(m + gid) * PA + ks * 8 + tig];
                a[mt][1] = As[(m + 8 + gid) * PA + ks * 8 + tig];
                a[mt][2] = As[(m + gid) * PA + ks * 8 + tig + 4];
                a[mt][3] = As[(m + 8 + gid) * PA + ks * 8 + tig + 4];
            }
            #pragma unroll
            for (int nt = 0; nt < 4; nt++) {
                b[0] = Bs[(ks * 8 + tig) * PB + wn0 + nt * 8 + gid];
                b[1] = Bs[(ks * 8 + tig + 4) * PB + wn0 + nt * 8 + gid];
                mma8(acc[nt], a[0], b);
                mma8(acc[4 + nt], a[1], b);
            }
        }
    }

    #pragma unroll
    for (int t = 0; t < 8; t++) {
        int mt = t >> 2, nt = t & 3;
        int row = m0 + wm0 + mt * 16 + gid;
        int col = n0 + wn0 + nt * 8 + tig * 2;
        float b0 = bias[col], b1 = bias[col + 1];
        *(float2*)&Z[(size_t)row * NG + col]       = make_float2(acc[t][0] + b0, acc[t][1] + b1);
        *(float2*)&Z[(size_t)(row + 8) * NG + col] = make_float2(acc[t][2] + b0, acc[t][3] + b1);
    }
}

// ---------------- final projection ----------------
__global__ void proj_kernel(const float* __restrict__ h2,
                            const float* __restrict__ Wph,  // [H, C]
                            const float* __restrict__ bp,   // [C]
                            float* __restrict__ out) {
    int idx = blockIdx.x * blockDim.x + threadIdx.x;
    if (idx >= Bsz * Csz) return;
    int b = idx / Csz, cc = idx % Csz;
    float s = bp[cc];
    for (int k = 0; k < Hsz; k++)
        s += h2[(size_t)b * Hsz + k] * Wph[(size_t)k * Csz + cc];
    out[idx] = s;
}

// ---------------- launch ----------------
extern "C" void kernel_launch(void* const* d_in, const int* in_sizes, int n_in,
                              void* d_out, int out_size) {
    const float* x   = (const float*)d_in[0];
    const float* Wx1 = (const float*)d_in[1];
    const float* Wh1 = (const float*)d_in[2];
    const float* b1  = (const float*)d_in[3];
    const float* Wx2 = (const float*)d_in[4];
    const float* Wh2 = (const float*)d_in[5];
    const float* b2  = (const float*)d_in[6];
    const float* Wph = (const float*)d_in[7];
    const float* bp  = (const float*)d_in[8];
    float* out = (float*)d_out;

    float *Zx1, *Zx2, *h1, *h2, *c1, *c2;
    cudaGetSymbolAddress((void**)&Zx1, g_Zx1);
    cudaGetSymbolAddress((void**)&Zx2, g_Zx2);
    cudaGetSymbolAddress((void**)&h1,  g_h1);
    cudaGetSymbolAddress((void**)&h2,  g_h2);
    cudaGetSymbolAddress((void**)&c1,  g_c1);
    cudaGetSymbolAddress((void**)&c2,  g_c2);

    init_state_kernel<<<(Bsz * Hsz + 255) / 256, 256>>>();

    // Phase 1: Zx1 = x @ Wx1 + b1   (M = 65536, K = 128)
    {
        dim3 grid(NG / 64, (Tt * Bsz) / 128);
        gemm_mma<true><<<grid, 256>>>(x, Wx1, b1, Zx1, Isz);
    }

    // Phase 2: layer-1 recurrence
    {
        dim3 grid(Hsz / 16, Bsz / 64);
        for (int t = 0; t < Tt; t++) {
            lstm_step_mma<<<grid, 128>>>(
                Zx1 + (size_t)t * Bsz * NG,
                h1 + (size_t)t * Bsz * Hsz,
                Wh1, c1,
                h1 + (size_t)(t + 1) * Bsz * Hsz);
        }
    }

    // Phase 3: Zx2 = h1_seq @ Wx2 + b2   (M = 65536, K = 512)
    {
        dim3 grid(NG / 64, (Tt * Bsz) / 128);
        gemm_mma<false><<<grid, 256>>>(h1 + (size_t)Bsz * Hsz, Wx2, b2, Zx2, Hsz);
    }

    // Phase 4: layer-2 recurrence
    {
        dim3 grid(Hsz / 16, Bsz / 64);
        for (int t = 0; t < Tt; t++) {
            lstm_step_mma<<<grid, 128>>>(
                Zx2 + (size_t)t * Bsz * NG,
                h2 + (size_t)t * Bsz * Hsz,
                Wh2, c2,
                h2 + (size_t)(t + 1) * Bsz * Hsz);
        }
    }

    // Phase 5: projection
    proj_kernel<<<(Bsz * Csz + 255) / 256, 256>>>(
        h2 + (size_t)Tt * Bsz * Hsz, Wph, bp, out);
}

// round 3
// speedup vs baseline: 3.6340x; 1.6859x over previous
#include <cuda_runtime.h>
#include <math.h>
#include <stdint.h>

#define Bsz 256
#define Tt  256
#define Isz 128
#define Hsz 512
#define Csz 10
#define NG  2048   // 4*H

// persistent-kernel smem pitches (in 4-byte words)
#define PW  72     // Wh: k-major, bank-conflict-free for B-frags
#define PAs 68     // A chunk: m-major
#define PZ  68     // z staging
// gemm pitches
#define GPA 36
#define GPB 136

// ---------------- scratch ----------------
__device__ float g_Zx1[(size_t)Tt * Bsz * NG];
__device__ float g_Zx2[(size_t)Tt * Bsz * NG];
__device__ float g_h1[(size_t)(Tt + 1) * Bsz * Hsz];
__device__ float g_h2[(size_t)(Tt + 1) * Bsz * Hsz];
__device__ unsigned g_bar[2];

// ---------------- helpers ----------------
__device__ __forceinline__ uint32_t f2tf(float f) {
    uint32_t u;
    asm("cvt.rna.tf32.f32 %0, %1;" : "=r"(u) : "f"(f));
    return u;
}
__device__ __forceinline__ void mma8(float* c, const uint32_t* a, const uint32_t* b) {
    asm volatile(
        "mma.sync.aligned.m16n8k8.row.col.f32.tf32.tf32.f32 "
        "{%0,%1,%2,%3},{%4,%5,%6,%7},{%8,%9},{%0,%1,%2,%3};"
        : "+f"(c[0]), "+f"(c[1]), "+f"(c[2]), "+f"(c[3])
        : "r"(a[0]), "r"(a[1]), "r"(a[2]), "r"(a[3]), "r"(b[0]), "r"(b[1]));
}
__device__ __forceinline__ float sigf(float x) { return __fdividef(1.f, 1.f + __expf(-x)); }
__device__ __forceinline__ float tanha(float x) { return __fmaf_rn(2.f, sigf(2.f * x), -1.f); }

__device__ __forceinline__ size_t a_row_off(int gm, int K, bool xperm) {
    // xperm: A row gm = t*B + b maps to x[b][t][:]
    return xperm ? (size_t)((gm & (Bsz - 1)) * Tt + (gm >> 8)) * Isz : (size_t)gm * K;
}

// ---------------- init: zero h slot-0 + barrier counters ----------------
__global__ void init_kernel() {
    int i = blockIdx.x * blockDim.x + threadIdx.x;
    if (i < Bsz * Hsz) {
        g_h1[i] = 0.f;
        g_h2[i] = 0.f;
    }
    if (i < 2) g_bar[i] = 0u;
}

// ---------------- persistent recurrent layer ----------------
// Grid (32, 4) = 128 CTAs, 256 threads. CTA owns batch block (64) x h block (16) x 4 gates.
// Wh slice (512 x 64) resident in SMEM as tf32; c resident in SMEM.
__global__ void __launch_bounds__(256, 1)
lstm_layer(const float* __restrict__ Zx,    // [T, B, 4H]
           const float* __restrict__ Wh,    // [4, H, H]
           float* __restrict__ hseq,        // [(T+1), B, H], slot 0 zeroed
           unsigned* __restrict__ bar) {
    extern __shared__ uint32_t sm[];
    uint32_t* Ws = sm;                          // 512*PW
    uint32_t* As = sm + 512 * PW;               // 2 * 64*PAs
    float* zs = (float*)(As + 2 * 64 * PAs);    // 64*PZ
    float* cs = zs + 64 * PZ;                   // 64*16

    const int h0 = blockIdx.x * 16;
    const int m0 = blockIdx.y * 64;
    const int tid = threadIdx.x, lane = tid & 31, wid = tid >> 5;
    const int gid = lane >> 2, tig = lane & 3;
    const int wm0 = (wid & 1) * 32, wn0 = (wid >> 1) * 16;

    // load Wh slice -> SMEM (tf32), cols j = g*16 + hh
    #pragma unroll 4
    for (int i = 0; i < 32; i++) {
        int f4 = tid + i * 256;                  // 8192 float4 total
        int k = f4 >> 4, rem = f4 & 15, g = rem >> 2, q = rem & 3;
        float4 v = *(const float4*)(Wh + ((size_t)g * Hsz + k) * Hsz + h0 + q * 4);
        uint32_t* d = &Ws[k * PW + g * 16 + q * 4];
        d[0] = f2tf(v.x); d[1] = f2tf(v.y); d[2] = f2tf(v.z); d[3] = f2tf(v.w);
    }
    *(float4*)&cs[tid * 4] = make_float4(0.f, 0.f, 0.f, 0.f);
    __syncthreads();

    const int rr = tid >> 2;            // row 0..63 for gate math
    const int hq = (tid & 3) * 4;       // h offset 0/4/8/12
    const unsigned ncta = gridDim.x * gridDim.y;

    for (int t = 0; t < Tt; t++) {
        const float* hp = hseq + (size_t)t * Bsz * Hsz + (size_t)m0 * Hsz;

        // prefetch Zx for this thread's 4 cells (independent of barrier; DRAM latency hidden by mma)
        const float* zxp = Zx + (size_t)t * Bsz * NG + (size_t)(m0 + rr) * NG + h0 + hq;
        float zxa[16];
        *(float4*)&zxa[0]  = *(const float4*)(zxp);
        *(float4*)&zxa[4]  = *(const float4*)(zxp + 512);
        *(float4*)&zxa[8]  = *(const float4*)(zxp + 1024);
        *(float4*)&zxa[12] = *(const float4*)(zxp + 1536);

        float acc[4][4] = {};
        float4 ra[4];

        // prologue: chunk 0 -> buf 0
        #pragma unroll
        for (int i = 0; i < 4; i++) {
            int f4 = tid + i * 256; int row = f4 >> 4, q = f4 & 15;
            ra[i] = __ldcg((const float4*)(hp + (size_t)row * Hsz + q * 4));
        }
        #pragma unroll
        for (int i = 0; i < 4; i++) {
            int f4 = tid + i * 256; int row = f4 >> 4, q = f4 & 15;
            uint32_t* d = &As[row * PAs + q * 4];
            d[0] = f2tf(ra[i].x); d[1] = f2tf(ra[i].y); d[2] = f2tf(ra[i].z); d[3] = f2tf(ra[i].w);
        }
        __syncthreads();

        #pragma unroll 1
        for (int ch = 0; ch < 8; ch++) {
            if (ch < 7) {
                int k0 = (ch + 1) * 64;
                #pragma unroll
                for (int i = 0; i < 4; i++) {
                    int f4 = tid + i * 256; int row = f4 >> 4, q = f4 & 15;
                    ra[i] = __ldcg((const float4*)(hp + (size_t)row * Hsz + k0 + q * 4));
                }
            }
            const uint32_t* ab = As + (ch & 1) * 64 * PAs;
            const uint32_t* wb = Ws + ch * 64 * PW;
            #pragma unroll
            for (int ks = 0; ks < 8; ks++) {
                uint32_t a[2][4], b[2][2];
                #pragma unroll
                for (int mt = 0; mt < 2; mt++) {
                    int m = wm0 + mt * 16;
                    a[mt][0] = ab[(m + gid) * PAs + ks * 8 + tig];
                    a[mt][1] = ab[(m + 8 + gid) * PAs + ks * 8 + tig];
                    a[mt][2] = ab[(m + gid) * PAs + ks * 8 + tig + 4];
                    a[mt][3] = ab[(m + 8 + gid) * PAs + ks * 8 + tig + 4];
                }
                #pragma unroll
                for (int nt = 0; nt < 2; nt++) {
                    b[nt][0] = wb[(ks * 8 + tig) * PW + wn0 + nt * 8 + gid];
                    b[nt][1] = wb[(ks * 8 + tig + 4) * PW + wn0 + nt * 8 + gid];
                }
                mma8(acc[0], a[0], b[0]); mma8(acc[1], a[0], b[1]);
                mma8(acc[2], a[1], b[0]); mma8(acc[3], a[1], b[1]);
            }
            if (ch < 7) {
                uint32_t* d2 = As + ((ch + 1) & 1) * 64 * PAs;
                #pragma unroll
                for (int i = 0; i < 4; i++) {
                    int f4 = tid + i * 256; int row = f4 >> 4, q = f4 & 15;
                    uint32_t* d = &d2[row * PAs + q * 4];
                    d[0] = f2tf(ra[i].x); d[1] = f2tf(ra[i].y); d[2] = f2tf(ra[i].z); d[3] = f2tf(ra[i].w);
                }
            }
            __syncthreads();
        }

        // stage z (recurrent part)
        #pragma unroll
        for (int u = 0; u < 4; u++) {
            int mt = u >> 1, nt = u & 1;
            int row = wm0 + mt * 16 + gid, col = wn0 + nt * 8 + tig * 2;
            *(float2*)&zs[row * PZ + col]       = make_float2(acc[u][0], acc[u][1]);
            *(float2*)&zs[(row + 8) * PZ + col] = make_float2(acc[u][2], acc[u][3]);
        }
        __syncthreads();

        // gate math: 4 cells per thread (row rr, h cols hq..hq+3)
        {
            const float* zrow = &zs[rr * PZ];
            float4 co = *(float4*)&cs[rr * 16 + hq];
            float* cop = (float*)&co;
            float cv[4], hv[4];
            #pragma unroll
            for (int j = 0; j < 4; j++) {
                float zg = zrow[hq + j]      + zxa[j];
                float zi = zrow[16 + hq + j] + zxa[4 + j];
                float zf = zrow[32 + hq + j] + zxa[8 + j];
                float zo = zrow[48 + hq + j] + zxa[12 + j];
                float gg = tanha(zg);
                float ii = sigf(zi);
                float ff = sigf(zf);
                float oo = sigf(zo);
                float cn = __fmaf_rn(gg, ii, cop[j] * ff);
                cv[j] = cn;
                hv[j] = tanha(cn) * oo;
            }
            *(float4*)&cs[rr * 16 + hq] = *(float4*)cv;
            *(float4*)(hseq + (size_t)(t + 1) * Bsz * Hsz + (size_t)(m0 + rr) * Hsz + h0 + hq)
                = *(float4*)hv;
        }

        // grid barrier (skip after last step)
        if (t < Tt - 1) {
            __threadfence();
            __syncthreads();
            if (tid == 0) {
                atomicAdd(bar, 1u);
                unsigned tgt = ncta * (unsigned)(t + 1);
                while (*(volatile unsigned*)bar < tgt) { }
            }
            __syncthreads();
        }
    }
}

// ---------------- big input GEMM: 128x128 tile, double-buffered ----------------
template <bool XPERM>
__global__ void __launch_bounds__(256)
gemm_mma2(const float* __restrict__ A,
          const float* __restrict__ W,     // [4, K, H]
          const float* __restrict__ bias,  // [4*H]
          float* __restrict__ Z,
          int K) {
    extern __shared__ uint32_t sm[];
    uint32_t* As = sm;                       // 2 x 128*GPA
    uint32_t* Bs = sm + 2 * 128 * GPA;       // 2 x 32*GPB

    const int m0 = blockIdx.y * 128, n0 = blockIdx.x * 128;
    const int gate = n0 >> 9, h0 = n0 & 511;
    const float* Bg = W + (size_t)gate * K * Hsz + h0;
    const int tid = threadIdx.x, lane = tid & 31, wid = tid >> 5;
    const int gid = lane >> 2, tig = lane & 3;
    const int wm0 = (wid & 1) * 64, wn0 = (wid >> 1) * 32;

    float4 ra[4], rb[4];
    // prologue: load chunk 0
    #pragma unroll
    for (int i = 0; i < 4; i++) {
        int f4 = tid + i * 256; int row = f4 >> 3, q = f4 & 7;
        ra[i] = *(const float4*)(A + a_row_off(m0 + row, K, XPERM) + q * 4);
    }
    #pragma unroll
    for (int i = 0; i < 4; i++) {
        int f4 = tid + i * 256; int k = f4 >> 5, q = f4 & 31;
        rb[i] = *(const float4*)(Bg + (size_t)k * Hsz + q * 4);
    }
    {
        #pragma unroll
        for (int i = 0; i < 4; i++) {
            int f4 = tid + i * 256; int row = f4 >> 3, q = f4 & 7;
            uint32_t* d = &As[row * GPA + q * 4];
            d[0] = f2tf(ra[i].x); d[1] = f2tf(ra[i].y); d[2] = f2tf(ra[i].z); d[3] = f2tf(ra[i].w);
        }
        #pragma unroll
        for (int i = 0; i < 4; i++) {
            int f4 = tid + i * 256; int k = f4 >> 5, q = f4 & 31;
            uint32_t* d = &Bs[k * GPB + q * 4];
            d[0] = f2tf(rb[i].x); d[1] = f2tf(rb[i].y); d[2] = f2tf(rb[i].z); d[3] = f2tf(rb[i].w);
        }
    }
    __syncthreads();

    float acc[16][4] = {};
    const int NC = K / 32;

    #pragma unroll 1
    for (int ch = 0; ch < NC; ch++) {
        if (ch + 1 < NC) {
            int kk = (ch + 1) * 32;
            #pragma unroll
            for (int i = 0; i < 4; i++) {
                int f4 = tid + i * 256; int row = f4 >> 3, q = f4 & 7;
                ra[i] = *(const float4*)(A + a_row_off(m0 + row, K, XPERM) + kk + q * 4);
            }
            #pragma unroll
            for (int i = 0; i < 4; i++) {
                int f4 = tid + i * 256; int k = f4 >> 5, q = f4 & 31;
                rb[i] = *(const float4*)(Bg + (size_t)(kk + k) * Hsz + q * 4);
            }
        }
        const uint32_t* ab = As + (ch & 1) * 128 * GPA;
        const uint32_t* bb = Bs + (ch & 1) * 32 * GPB;
        #pragma unroll
        for (int ks = 0; ks < 4; ks++) {
            uint32_t a[4][4], b[4][2];
            #pragma unroll
            for (int mt = 0; mt < 4; mt++) {
                int m = wm0 + mt * 16;
                a[mt][0] = ab[(m + gid) * GPA + ks * 8 + tig];
                a[mt][1] = ab[(m + 8 + gid) * GPA + ks * 8 + tig];
                a[mt][2] = ab[(m + gid) * GPA + ks * 8 + tig + 4];
                a[mt][3] = ab[(m + 8 + gid) * GPA + ks * 8 + tig + 4];
            }
            #pragma unroll
            for (int nt = 0; nt < 4; nt++) {
                b[nt][0] = bb[(ks * 8 + tig) * GPB + wn0 + nt * 8 + gid];
                b[nt][1] = bb[(ks * 8 + tig + 4) * GPB + wn0 + nt * 8 + gid];
            }
            #pragma unroll
            for (int mt = 0; mt < 4; mt++)
                #pragma unroll
                for (int nt = 0; nt < 4; nt++)
                    mma8(acc[mt * 4 + nt], a[mt], b[nt]);
        }
        if (ch + 1 < NC) {
            uint32_t* a2 = As + ((ch + 1) & 1) * 128 * GPA;
            uint32_t* b2 = Bs + ((ch + 1) & 1) * 32 * GPB;
            #pragma unroll
            for (int i = 0; i < 4; i++) {
                int f4 = tid + i * 256; int row = f4 >> 3, q = f4 & 7;
                uint32_t* d = &a2[row * GPA + q * 4];
                d[0] = f2tf(ra[i].x); d[1] = f2tf(ra[i].y); d[2] = f2tf(ra[i].z); d[3] = f2tf(ra[i].w);
            }
            #pragma unroll
            for (int i = 0; i < 4; i++) {
                int f4 = tid + i * 256; int k = f4 >> 5, q = f4 & 31;
                uint32_t* d = &b2[k * GPB + q * 4];
                d[0] = f2tf(rb[i].x); d[1] = f2tf(rb[i].y); d[2] = f2tf(rb[i].z); d[3] = f2tf(rb[i].w);
            }
        }
        __syncthreads();
    }

    #pragma unroll
    for (int u = 0; u < 16; u++) {
        int mt = u >> 2, nt = u & 3;
        int row = m0 + wm0 + mt * 16 + gid;
        int col = n0 + wn0 + nt * 8 + tig * 2;
        float b0 = bias[col], b1 = bias[col + 1];
        *(float2*)&Z[(size_t)row * NG + col]       = make_float2(acc[u][0] + b0, acc[u][1] + b1);
        *(float2*)&Z[(size_t)(row + 8) * NG + col] = make_float2(acc[u][2] + b0, acc[u][3] + b1);
    }
}

// ---------------- final projection ----------------
__global__ void proj_kernel(const float* __restrict__ h2,
                            const float* __restrict__ Wph,  // [H, C]
                            const float* __restrict__ bp,   // [C]
                            float* __restrict__ out) {
    int idx = blockIdx.x * blockDim.x + threadIdx.x;
    if (idx >= Bsz * Csz) return;
    int b = idx / Csz, cc = idx % Csz;
    float s = bp[cc];
    for (int k = 0; k < Hsz; k++)
        s += h2[(size_t)b * Hsz + k] * Wph[(size_t)k * Csz + cc];
    out[idx] = s;
}

// ---------------- launch ----------------
#define PSM ((512 * PW + 2 * 64 * PAs + 64 * PZ + 64 * 16) * 4)
#define GSM ((2 * 128 * GPA + 2 * 32 * GPB) * 4)

extern "C" void kernel_launch(void* const* d_in, const int* in_sizes, int n_in,
                              void* d_out, int out_size) {
    const float* x   = (const float*)d_in[0];
    const float* Wx1 = (const float*)d_in[1];
    const float* Wh1 = (const float*)d_in[2];
    const float* b1  = (const float*)d_in[3];
    const float* Wx2 = (const float*)d_in[4];
    const float* Wh2 = (const float*)d_in[5];
    const float* b2  = (const float*)d_in[6];
    const float* Wph = (const float*)d_in[7];
    const float* bp  = (const float*)d_in[8];
    float* out = (float*)d_out;

    float *Zx1, *Zx2, *h1, *h2;
    unsigned* bar;
    cudaGetSymbolAddress((void**)&Zx1, g_Zx1);
    cudaGetSymbolAddress((void**)&Zx2, g_Zx2);
    cudaGetSymbolAddress((void**)&h1,  g_h1);
    cudaGetSymbolAddress((void**)&h2,  g_h2);
    cudaGetSymbolAddress((void**)&bar, g_bar);

    cudaFuncSetAttribute(lstm_layer, cudaFuncAttributeMaxDynamicSharedMemorySize, PSM);
    cudaFuncSetAttribute(gemm_mma2<true>,  cudaFuncAttributeMaxDynamicSharedMemorySize, GSM);
    cudaFuncSetAttribute(gemm_mma2<false>, cudaFuncAttributeMaxDynamicSharedMemorySize, GSM);

    init_kernel<<<(Bsz * Hsz + 255) / 256, 256>>>();

    // Phase 1: Zx1 = x @ Wx1 + b1   (M = 65536, K = 128)
    gemm_mma2<true><<<dim3(NG / 128, (Tt * Bsz) / 128), 256, GSM>>>(x, Wx1, b1, Zx1, Isz);

    // Phase 2: layer-1 recurrence (persistent, 256 steps)
    lstm_layer<<<dim3(Hsz / 16, Bsz / 64), 256, PSM>>>(Zx1, Wh1, h1, bar + 0);

    // Phase 3: Zx2 = h1_seq @ Wx2 + b2   (M = 65536, K = 512)
    gemm_mma2<false><<<dim3(NG / 128, (Tt * Bsz) / 128), 256, GSM>>>(h1 + (size_t)Bsz * Hsz, Wx2, b2, Zx2, Hsz);

    // Phase 4: layer-2 recurrence
    lstm_layer<<<dim3(Hsz / 16, Bsz / 64), 256, PSM>>>(Zx2, Wh2, h2, bar + 1);

    // Phase 5: projection
    proj_kernel<<<(Bsz * Csz + 255) / 256, 256>>>(
        h2 + (size_t)Tt * Bsz * Hsz, Wph, bp, out);
}

// round 4
// speedup vs baseline: 5.8469x; 1.6089x over previous
#include <cuda_runtime.h>
#include <cuda_fp16.h>
#include <math.h>
#include <stdint.h>

#define Bsz 256
#define Tt  256
#define Isz 128
#define Hsz 512
#define Csz 10
#define NG  2048   // 4*H

// step-kernel smem pitches (halves)
#define PAH 520    // A tile, m-major; word pitch 260 -> bank-conflict-free frags
#define PWH 520    // Wh tile, n-major
#define PZ  68     // z staging pitch (floats)
// gemm pitches (words)
#define GPA 36
#define GPB 136

// ---------------- scratch ----------------
__device__ float  g_Zx1[(size_t)Tt * Bsz * NG];
__device__ float  g_Zx2[(size_t)Tt * Bsz * NG];
__device__ __half g_h1[(size_t)(Tt + 1) * Bsz * Hsz];
__device__ __half g_h2[(size_t)(Tt + 1) * Bsz * Hsz];
__device__ unsigned g_bar[8];

// ---------------- helpers ----------------
__device__ __forceinline__ uint32_t f2tf(float f) {
    uint32_t u;
    asm("cvt.rna.tf32.f32 %0, %1;" : "=r"(u) : "f"(f));
    return u;
}
__device__ __forceinline__ void mma8(float* c, const uint32_t* a, const uint32_t* b) {
    asm volatile(
        "mma.sync.aligned.m16n8k8.row.col.f32.tf32.tf32.f32 "
        "{%0,%1,%2,%3},{%4,%5,%6,%7},{%8,%9},{%0,%1,%2,%3};"
        : "+f"(c[0]), "+f"(c[1]), "+f"(c[2]), "+f"(c[3])
        : "r"(a[0]), "r"(a[1]), "r"(a[2]), "r"(a[3]), "r"(b[0]), "r"(b[1]));
}
__device__ __forceinline__ void mma16(float* c, const uint32_t* a, const uint32_t* b) {
    asm volatile(
        "mma.sync.aligned.m16n8k16.row.col.f32.f16.f16.f32 "
        "{%0,%1,%2,%3},{%4,%5,%6,%7},{%8,%9},{%0,%1,%2,%3};"
        : "+f"(c[0]), "+f"(c[1]), "+f"(c[2]), "+f"(c[3])
        : "r"(a[0]), "r"(a[1]), "r"(a[2]), "r"(a[3]), "r"(b[0]), "r"(b[1]));
}
__device__ __forceinline__ float sigf(float x) { return __fdividef(1.f, 1.f + __expf(-x)); }
__device__ __forceinline__ float tanha(float x) { return __fmaf_rn(2.f, sigf(2.f * x), -1.f); }

__device__ __forceinline__ size_t a_row_off(int gm, int K, bool xperm) {
    return xperm ? (size_t)((gm & (Bsz - 1)) * Tt + (gm >> 8)) * Isz : (size_t)gm * K;
}

// ---------------- init ----------------
__global__ void init_kernel() {
    int i = blockIdx.x * blockDim.x + threadIdx.x;
    if (i < Bsz * Hsz) {
        g_h1[i] = __float2half(0.f);
        g_h2[i] = __float2half(0.f);
    }
    if (i < 8) g_bar[i] = 0u;
}

// ---------------- persistent recurrent layer (fp16 mma, split-K warps) ----------------
// Grid (32, 4) = 128 CTAs, 256 threads. CTA: batch block 64 x (4 gates x 16 h).
// Warp layout: wm0 = (wid&1)*32, wn0 = ((wid>>1)&1)*32, kh = wid>>2 (k-half).
__global__ void __launch_bounds__(256, 1)
lstm_layer(const float* __restrict__ Zx,    // [T, B, 4H] fp32
           const float* __restrict__ Wh,    // [4, H, H] fp32
           __half* __restrict__ hseq,       // [(T+1), B, H] fp16, slot 0 zeroed
           unsigned* __restrict__ bar) {    // 4 counters (one per batch group)
    extern __shared__ __align__(16) unsigned char smraw[];
    __half* Ws = (__half*)smraw;                 // 64 n x PWH
    __half* As = Ws + 64 * PWH;                  // 64 m x PAH
    float* zs0 = (float*)(As + 64 * PAH);        // 64 x PZ
    float* zs1 = zs0 + 64 * PZ;                  // 64 x PZ
    float* cs  = zs1 + 64 * PZ;                  // 64 x 16

    const int h0 = blockIdx.x * 16;
    const int m0 = blockIdx.y * 64;
    const int tid = threadIdx.x, lane = tid & 31, wid = tid >> 5;
    const int gid = lane >> 2, tig = lane & 3;
    const int wm0 = (wid & 1) * 32, wn0 = ((wid >> 1) & 1) * 32;
    const int kh  = wid >> 2;                    // 0: k 0..255, 1: k 256..511
    uint32_t* Aw = (uint32_t*)As;
    uint32_t* Ww = (uint32_t*)Ws;

    // ---- one-time: Wh slice -> SMEM, transposed to n-major fp16 ----
    #pragma unroll 4
    for (int i = 0; i < 32; i++) {
        int f4 = tid + i * 256;                  // 8192 float4 reads
        int k = f4 >> 4, rem = f4 & 15, g = rem >> 2, q = rem & 3;
        float4 v = *(const float4*)(Wh + ((size_t)g * Hsz + k) * Hsz + h0 + q * 4);
        int nb = g * 16 + q * 4;
        Ws[(nb + 0) * PWH + k] = __float2half_rn(v.x);
        Ws[(nb + 1) * PWH + k] = __float2half_rn(v.y);
        Ws[(nb + 2) * PWH + k] = __float2half_rn(v.z);
        Ws[(nb + 3) * PWH + k] = __float2half_rn(v.w);
    }
    *(float4*)&cs[tid * 4] = make_float4(0.f, 0.f, 0.f, 0.f);
    __syncthreads();

    const int rr = tid >> 2;            // gate-phase row 0..63
    const int hq = (tid & 3) * 4;       // gate-phase h offset
    const unsigned grp = blockIdx.y;

    for (int t = 0; t < Tt; t++) {
        // prefetch Zx (fp32) for this thread's 4 cells
        const float* zxp = Zx + (size_t)t * Bsz * NG + (size_t)(m0 + rr) * NG + h0 + hq;
        float zxa[16];
        *(float4*)&zxa[0]  = *(const float4*)(zxp);
        *(float4*)&zxa[4]  = *(const float4*)(zxp + 512);
        *(float4*)&zxa[8]  = *(const float4*)(zxp + 1024);
        *(float4*)&zxa[12] = *(const float4*)(zxp + 1536);

        // load full h tile (64 x 512 fp16 = 64KB) into As
        const __half* hp = hseq + (size_t)t * Bsz * Hsz + (size_t)m0 * Hsz;
        #pragma unroll
        for (int i = 0; i < 16; i++) {
            int f4 = tid + i * 256;
            int row = f4 >> 6, u = f4 & 63;
            uint4 v = *(const uint4*)(hp + (size_t)row * Hsz + u * 8);
            *(uint4*)(Aw + row * (PAH / 2) + u * 4) = v;
        }
        __syncthreads();

        float acc[8][4] = {};
        #pragma unroll
        for (int ks = 0; ks < 16; ks++) {
            int kwd = (kh * 16 + ks) * 8;        // word offset of k16 block
            uint32_t a[2][4], b[4][2];
            #pragma unroll
            for (int mt = 0; mt < 2; mt++) {
                int m = wm0 + mt * 16;
                a[mt][0] = Aw[(m + gid) * 260 + kwd + tig];
                a[mt][1] = Aw[(m + 8 + gid) * 260 + kwd + tig];
                a[mt][2] = Aw[(m + gid) * 260 + kwd + tig + 4];
                a[mt][3] = Aw[(m + 8 + gid) * 260 + kwd + tig + 4];
            }
            #pragma unroll
            for (int nt = 0; nt < 4; nt++) {
                int n = wn0 + nt * 8;
                b[nt][0] = Ww[(n + gid) * 260 + kwd + tig];
                b[nt][1] = Ww[(n + gid) * 260 + kwd + tig + 4];
            }
            #pragma unroll
            for (int mt = 0; mt < 2; mt++)
                #pragma unroll
                for (int nt = 0; nt < 4; nt++)
                    mma16(acc[mt * 4 + nt], a[mt], b[nt]);
        }

        // stage partial z per k-half
        float* zsb = kh ? zs1 : zs0;
        #pragma unroll
        for (int u = 0; u < 8; u++) {
            int mt = u >> 2, nt = u & 3;
            int row = wm0 + mt * 16 + gid, col = wn0 + nt * 8 + tig * 2;
            *(float2*)&zsb[row * PZ + col]       = make_float2(acc[u][0], acc[u][1]);
            *(float2*)&zsb[(row + 8) * PZ + col] = make_float2(acc[u][2], acc[u][3]);
        }
        __syncthreads();

        // gate math: 4 cells per thread
        {
            const float* z0 = &zs0[rr * PZ];
            const float* z1 = &zs1[rr * PZ];
            float4 co = *(float4*)&cs[rr * 16 + hq];
            float* cop = (float*)&co;
            float cv[4];
            __half hv[4];
            #pragma unroll
            for (int j = 0; j < 4; j++) {
                float zg = z0[hq + j]      + z1[hq + j]      + zxa[j];
                float zi = z0[16 + hq + j] + z1[16 + hq + j] + zxa[4 + j];
                float zf = z0[32 + hq + j] + z1[32 + hq + j] + zxa[8 + j];
                float zo = z0[48 + hq + j] + z1[48 + hq + j] + zxa[12 + j];
                float gg = tanha(zg);
                float ii = sigf(zi);
                float ff = sigf(zf);
                float oo = sigf(zo);
                float cn = __fmaf_rn(gg, ii, cop[j] * ff);
                cv[j] = cn;
                hv[j] = __float2half_rn(tanha(cn) * oo);
            }
            *(float4*)&cs[rr * 16 + hq] = *(float4*)cv;
            *(uint2*)(hseq + (size_t)(t + 1) * Bsz * Hsz + (size_t)(m0 + rr) * Hsz + h0 + hq)
                = *(uint2*)hv;
        }

        // group barrier: only the 32 CTAs sharing this batch block
        if (t < Tt - 1) {
            __threadfence();
            __syncthreads();
            if (tid == 0) {
                atomicAdd(&bar[grp], 1u);
                unsigned tgt = 32u * (unsigned)(t + 1);
                while (*(volatile unsigned*)&bar[grp] < tgt) { }
            }
            __syncthreads();
        }
    }
}

// ---------------- big input GEMM: tf32, 128x128 tile, double-buffered ----------------
template <bool XPERM, bool AHALF>
__global__ void __launch_bounds__(256)
gemm_mma2(const void* __restrict__ Av,
          const float* __restrict__ W,     // [4, K, H]
          const float* __restrict__ bias,  // [4*H]
          float* __restrict__ Z,
          int K) {
    extern __shared__ uint32_t sm[];
    uint32_t* As = sm;                       // 2 x 128*GPA
    uint32_t* Bs = sm + 2 * 128 * GPA;       // 2 x 32*GPB
    const float* Af = (const float*)Av;
    const __half* Ah = (const __half*)Av;

    const int m0 = blockIdx.y * 128, n0 = blockIdx.x * 128;
    const int gate = n0 >> 9, h0 = n0 & 511;
    const float* Bg = W + (size_t)gate * K * Hsz + h0;
    const int tid = threadIdx.x, lane = tid & 31, wid = tid >> 5;
    const int gid = lane >> 2, tig = lane & 3;
    const int wm0 = (wid & 1) * 64, wn0 = (wid >> 1) * 32;

    float4 ra[4], rb[4];
    auto loadA = [&](int i, int kk) {
        int f4 = tid + i * 256; int row = f4 >> 3, q = f4 & 7;
        size_t off = a_row_off(m0 + row, K, XPERM) + kk + q * 4;
        if (AHALF) {
            uint2 u = *(const uint2*)(Ah + off);
            __half2* hp = (__half2*)&u;
            float2 lo = __half22float2(hp[0]), hi = __half22float2(hp[1]);
            ra[i] = make_float4(lo.x, lo.y, hi.x, hi.y);
        } else {
            ra[i] = *(const float4*)(Af + off);
        }
    };

    #pragma unroll
    for (int i = 0; i < 4; i++) loadA(i, 0);
    #pragma unroll
    for (int i = 0; i < 4; i++) {
        int f4 = tid + i * 256; int k = f4 >> 5, q = f4 & 31;
        rb[i] = *(const float4*)(Bg + (size_t)k * Hsz + q * 4);
    }
    {
        #pragma unroll
        for (int i = 0; i < 4; i++) {
            int f4 = tid + i * 256; int row = f4 >> 3, q = f4 & 7;
            uint32_t* d = &As[row * GPA + q * 4];
            d[0] = f2tf(ra[i].x); d[1] = f2tf(ra[i].y); d[2] = f2tf(ra[i].z); d[3] = f2tf(ra[i].w);
        }
        #pragma unroll
        for (int i = 0; i < 4; i++) {
            int f4 = tid + i * 256; int k = f4 >> 5, q = f4 & 31;
            uint32_t* d = &Bs[k * GPB + q * 4];
            d[0] = f2tf(rb[i].x); d[1] = f2tf(rb[i].y); d[2] = f2tf(rb[i].z); d[3] = f2tf(rb[i].w);
        }
    }
    __syncthreads();

    float acc[16][4] = {};
    const int NC = K / 32;

    #pragma unroll 1
    for (int ch = 0; ch < NC; ch++) {
        if (ch + 1 < NC) {
            int kk = (ch + 1) * 32;
            #pragma unroll
            for (int i = 0; i < 4; i++) loadA(i, kk);
            #pragma unroll
            for (int i = 0; i < 4; i++) {
                int f4 = tid + i * 256; int k = f4 >> 5, q = f4 & 31;
                rb[i] = *(const float4*)(Bg + (size_t)(kk + k) * Hsz + q * 4);
            }
        }
        const uint32_t* ab = As + (ch & 1) * 128 * GPA;
        const uint32_t* bb = Bs + (ch & 1) * 32 * GPB;
        #pragma unroll
        for (int ks = 0; ks < 4; ks++) {
            uint32_t a[4][4], b[4][2];
            #pragma unroll
            for (int mt = 0; mt < 4; mt++) {
                int m = wm0 + mt * 16;
                a[mt][0] = ab[(m + gid) * GPA + ks * 8 + tig];
                a[mt][1] = ab[(m + 8 + gid) * GPA + ks * 8 + tig];
                a[mt][2] = ab[(m + gid) * GPA + ks * 8 + tig + 4];
                a[mt][3] = ab[(m + 8 + gid) * GPA + ks * 8 + tig + 4];
            }
            #pragma unroll
            for (int nt = 0; nt < 4; nt++) {
                b[nt][0] = bb[(ks * 8 + tig) * GPB + wn0 + nt * 8 + gid];
                b[nt][1] = bb[(ks * 8 + tig + 4) * GPB + wn0 + nt * 8 + gid];
            }
            #pragma unroll
            for (int mt = 0; mt < 4; mt++)
                #pragma unroll
                for (int nt = 0; nt < 4; nt++)
                    mma8(acc[mt * 4 + nt], a[mt], b[nt]);
        }
        if (ch + 1 < NC) {
            uint32_t* a2 = As + ((ch + 1) & 1) * 128 * GPA;
            uint32_t* b2 = Bs + ((ch + 1) & 1) * 32 * GPB;
            #pragma unroll
            for (int i = 0; i < 4; i++) {
                int f4 = tid + i * 256; int row = f4 >> 3, q = f4 & 7;
                uint32_t* d = &a2[row * GPA + q * 4];
                d[0] = f2tf(ra[i].x); d[1] = f2tf(ra[i].y); d[2] = f2tf(ra[i].z); d[3] = f2tf(ra[i].w);
            }
            #pragma unroll
            for (int i = 0; i < 4; i++) {
                int f4 = tid + i * 256; int k = f4 >> 5, q = f4 & 31;
                uint32_t* d = &b2[k * GPB + q * 4];
                d[0] = f2tf(rb[i].x); d[1] = f2tf(rb[i].y); d[2] = f2tf(rb[i].z); d[3] = f2tf(rb[i].w);
            }
        }
        __syncthreads();
    }

    #pragma unroll
    for (int u = 0; u < 16; u++) {
        int mt = u >> 2, nt = u & 3;
        int row = m0 + wm0 + mt * 16 + gid;
        int col = n0 + wn0 + nt * 8 + tig * 2;
        float b0 = bias[col], b1 = bias[col + 1];
        *(float2*)&Z[(size_t)row * NG + col]       = make_float2(acc[u][0] + b0, acc[u][1] + b1);
        *(float2*)&Z[(size_t)(row + 8) * NG + col] = make_float2(acc[u][2] + b0, acc[u][3] + b1);
    }
}

// ---------------- final projection ----------------
__global__ void proj_kernel(const __half* __restrict__ h2,
                            const float* __restrict__ Wph,  // [H, C]
                            const float* __restrict__ bp,   // [C]
                            float* __restrict__ out) {
    int idx = blockIdx.x * blockDim.x + threadIdx.x;
    if (idx >= Bsz * Csz) return;
    int b = idx / Csz, cc = idx % Csz;
    float s = bp[cc];
    for (int k = 0; k < Hsz; k++)
        s += __half2float(h2[(size_t)b * Hsz + k]) * Wph[(size_t)k * Csz + cc];
    out[idx] = s;
}

// ---------------- launch ----------------
#define PSM ((64 * PWH + 64 * PAH) * 2 + (2 * 64 * PZ + 64 * 16) * 4)
#define GSM ((2 * 128 * GPA + 2 * 32 * GPB) * 4)

extern "C" void kernel_launch(void* const* d_in, const int* in_sizes, int n_in,
                              void* d_out, int out_size) {
    const float* x   = (const float*)d_in[0];
    const float* Wx1 = (const float*)d_in[1];
    const float* Wh1 = (const float*)d_in[2];
    const float* b1  = (const float*)d_in[3];
    const float* Wx2 = (const float*)d_in[4];
    const float* Wh2 = (const float*)d_in[5];
    const float* b2  = (const float*)d_in[6];
    const float* Wph = (const float*)d_in[7];
    const float* bp  = (const float*)d_in[8];
    float* out = (float*)d_out;

    float *Zx1, *Zx2;
    __half *h1, *h2;
    unsigned* bar;
    cudaGetSymbolAddress((void**)&Zx1, g_Zx1);
    cudaGetSymbolAddress((void**)&Zx2, g_Zx2);
    cudaGetSymbolAddress((void**)&h1,  g_h1);
    cudaGetSymbolAddress((void**)&h2,  g_h2);
    cudaGetSymbolAddress((void**)&bar, g_bar);

    cudaFuncSetAttribute(lstm_layer, cudaFuncAttributeMaxDynamicSharedMemorySize, PSM);
    cudaFuncSetAttribute(gemm_mma2<true, false>,  cudaFuncAttributeMaxDynamicSharedMemorySize, GSM);
    cudaFuncSetAttribute(gemm_mma2<false, true>,  cudaFuncAttributeMaxDynamicSharedMemorySize, GSM);

    init_kernel<<<(Bsz * Hsz + 255) / 256, 256>>>();

    // Phase 1: Zx1 = x @ Wx1 + b1   (M = 65536, K = 128, A fp32 permuted)
    gemm_mma2<true, false><<<dim3(NG / 128, (Tt * Bsz) / 128), 256, GSM>>>(x, Wx1, b1, Zx1, Isz);

    // Phase 2: layer-1 recurrence (persistent)
    lstm_layer<<<dim3(Hsz / 16, Bsz / 64), 256, PSM>>>(Zx1, Wh1, h1, bar + 0);

    // Phase 3: Zx2 = h1_seq @ Wx2 + b2   (M = 65536, K = 512, A fp16)
    gemm_mma2<false, true><<<dim3(NG / 128, (Tt * Bsz) / 128), 256, GSM>>>(h1 + (size_t)Bsz * Hsz, Wx2, b2, Zx2, Hsz);

    // Phase 4: layer-2 recurrence
    lstm_layer<<<dim3(Hsz / 16, Bsz / 64), 256, PSM>>>(Zx2, Wh2, h2, bar + 4);

    // Phase 5: projection
    proj_kernel<<<(Bsz * Csz + 255) / 256, 256>>>(
        h2 + (size_t)Tt * Bsz * Hsz, Wph, bp, out);
}

// round 7
// speedup vs baseline: 7.1955x; 1.2306x over previous
#include <cuda_runtime.h>
#include <cuda_fp16.h>
#include <math.h>
#include <stdint.h>

#define Bsz 256
#define Tt  256
#define Isz 128
#define Hsz 512
#define Csz 10
#define NG  2048   // 4*H

// step-kernel smem pitches (halves)
#define PAH 520    // A tile, m-major; word pitch 260 -> bank-conflict-free frags
#define PWH 520    // Wh tile, n-major
#define PZ  68     // z staging pitch (floats)
// gemm pitch (u32 words per 128-row): 20 ≡ 4 mod 8 -> conflict-free frag LDS
#define GP  20

// ---------------- scratch ----------------
__device__ float  g_Zx1[(size_t)Tt * Bsz * NG];
__device__ float  g_Zx2[(size_t)Tt * Bsz * NG];
__device__ __half g_h1[(size_t)(Tt + 1) * Bsz * Hsz];
__device__ __half g_h2[(size_t)(Tt + 1) * Bsz * Hsz];
__device__ __half g_W1T[(size_t)4 * Hsz * Isz];   // [g][h][k] fp16
__device__ __half g_W2T[(size_t)4 * Hsz * Hsz];   // [g][h][k] fp16
__device__ unsigned g_bar[8];

// ---------------- helpers ----------------
__device__ __forceinline__ void mma16(float* c, const uint32_t* a, const uint32_t* b) {
    asm volatile(
        "mma.sync.aligned.m16n8k16.row.col.f32.f16.f16.f32 "
        "{%0,%1,%2,%3},{%4,%5,%6,%7},{%8,%9},{%0,%1,%2,%3};"
        : "+f"(c[0]), "+f"(c[1]), "+f"(c[2]), "+f"(c[3])
        : "r"(a[0]), "r"(a[1]), "r"(a[2]), "r"(a[3]), "r"(b[0]), "r"(b[1]));
}
__device__ __forceinline__ float tanha(float x) {
    float y;
    asm("tanh.approx.f32 %0, %1;" : "=f"(y) : "f"(x));
    return y;
}
__device__ __forceinline__ float sigf(float x) {
    return __fmaf_rn(0.5f, tanha(0.5f * x), 0.5f);
}
__device__ __forceinline__ size_t a_row_off(int gm, int K, bool xperm) {
    return xperm ? (size_t)((gm & (Bsz - 1)) * Tt + (gm >> 8)) * Isz : (size_t)gm * K;
}
__device__ __forceinline__ void bar_arrive(unsigned* p) {
    asm volatile("red.release.gpu.global.add.u32 [%0], %1;" :: "l"(p), "r"(1u) : "memory");
}
__device__ __forceinline__ void bar_spin(unsigned* p, unsigned tgt) {
    unsigned v;
    do {
        asm volatile("ld.acquire.gpu.global.u32 %0, [%1];" : "=r"(v) : "l"(p) : "memory");
    } while (v < tgt);
}

// ---------------- init: zero h slot-0 + barrier counters ----------------
__global__ void init_kernel() {
    int i = blockIdx.x * blockDim.x + threadIdx.x;
    if (i < Bsz * Hsz) {
        g_h1[i] = __float2half(0.f);
        g_h2[i] = __float2half(0.f);
    }
    if (i < 8) g_bar[i] = 0u;
}

// ---------------- weight prep: W[g][k][h] fp32 -> WT[g][h][k] fp16 ----------------
__global__ void prep_w(const float* __restrict__ W, __half* __restrict__ WT, int K) {
    int idx = blockIdx.x * blockDim.x + threadIdx.x;   // over (g, h, k/2)
    int kp = idx % (K / 2);
    int rest = idx / (K / 2);
    int h = rest % Hsz, g = rest / Hsz;
    if (g >= 4) return;
    int k = kp * 2;
    float a = W[((size_t)g * K + k) * Hsz + h];
    float b = W[((size_t)g * K + k + 1) * Hsz + h];
    *(__half2*)(WT + ((size_t)g * Hsz + h) * K + k) = __floats2half2_rn(a, b);
}

// ---------------- persistent recurrent layer (fp16 mma, split-K warps) ----------------
// Grid (32, 4) = 128 CTAs, 256 threads. CTA: batch block 64 x (4 gates x 16 h).
__global__ void __launch_bounds__(256, 1)
lstm_layer(const float* __restrict__ Zx,    // [T, B, 4H] fp32
           const float* __restrict__ Wh,    // [4, H, H] fp32
           __half* __restrict__ hseq,       // [(T+1), B, H] fp16, slot 0 zeroed
           unsigned* __restrict__ bar) {    // 4 counters (one per batch group)
    extern __shared__ __align__(16) unsigned char smraw[];
    __half* Ws = (__half*)smraw;                 // 64 n x PWH
    __half* As = Ws + 64 * PWH;                  // 64 m x PAH
    float* zs0 = (float*)(As + 64 * PAH);        // 64 x PZ
    float* zs1 = zs0 + 64 * PZ;                  // 64 x PZ
    float* cs  = zs1 + 64 * PZ;                  // 64 x 16

    const int h0 = blockIdx.x * 16;
    const int m0 = blockIdx.y * 64;
    const int tid = threadIdx.x, lane = tid & 31, wid = tid >> 5;
    const int gid = lane >> 2, tig = lane & 3;
    const int wm0 = (wid & 1) * 32, wn0 = ((wid >> 1) & 1) * 32;
    const int kh  = wid >> 2;                    // 0: k 0..255, 1: k 256..511
    uint32_t* Aw = (uint32_t*)As;
    uint32_t* Ww = (uint32_t*)Ws;

    // ---- one-time: Wh slice -> SMEM, transposed to n-major fp16 ----
    #pragma unroll 4
    for (int i = 0; i < 32; i++) {
        int f4 = tid + i * 256;                  // 8192 float4 reads
        int k = f4 >> 4, rem = f4 & 15, g = rem >> 2, q = rem & 3;
        float4 v = *(const float4*)(Wh + ((size_t)g * Hsz + k) * Hsz + h0 + q * 4);
        int nb = g * 16 + q * 4;
        Ws[(nb + 0) * PWH + k] = __float2half_rn(v.x);
        Ws[(nb + 1) * PWH + k] = __float2half_rn(v.y);
        Ws[(nb + 2) * PWH + k] = __float2half_rn(v.z);
        Ws[(nb + 3) * PWH + k] = __float2half_rn(v.w);
    }
    *(float4*)&cs[tid * 4] = make_float4(0.f, 0.f, 0.f, 0.f);
    __syncthreads();

    const int rr = tid >> 2;            // gate-phase row 0..63
    const int hq = (tid & 3) * 4;       // gate-phase h offset
    const unsigned grp = blockIdx.y;

    for (int t = 0; t < Tt; t++) {
        // prefetch Zx (fp32) for this thread's 4 cells
        const float* zxp = Zx + (size_t)t * Bsz * NG + (size_t)(m0 + rr) * NG + h0 + hq;
        float zxa[16];
        *(float4*)&zxa[0]  = *(const float4*)(zxp);
        *(float4*)&zxa[4]  = *(const float4*)(zxp + 512);
        *(float4*)&zxa[8]  = *(const float4*)(zxp + 1024);
        *(float4*)&zxa[12] = *(const float4*)(zxp + 1536);

        // load full h tile (64 x 512 fp16 = 64KB) into As
        const __half* hp = hseq + (size_t)t * Bsz * Hsz + (size_t)m0 * Hsz;
        #pragma unroll
        for (int i = 0; i < 16; i++) {
            int f4 = tid + i * 256;
            int row = f4 >> 6, u = f4 & 63;
            uint4 v = *(const uint4*)(hp + (size_t)row * Hsz + u * 8);
            *(uint4*)(Aw + row * (PAH / 2) + u * 4) = v;
        }
        __syncthreads();

        float acc[8][4] = {};
        #pragma unroll
        for (int ks = 0; ks < 16; ks++) {
            int kwd = (kh * 16 + ks) * 8;        // word offset of k16 block
            uint32_t a[2][4], b[4][2];
            #pragma unroll
            for (int mt = 0; mt < 2; mt++) {
                int m = wm0 + mt * 16;
                a[mt][0] = Aw[(m + gid) * 260 + kwd + tig];
                a[mt][1] = Aw[(m + 8 + gid) * 260 + kwd + tig];
                a[mt][2] = Aw[(m + gid) * 260 + kwd + tig + 4];
                a[mt][3] = Aw[(m + 8 + gid) * 260 + kwd + tig + 4];
            }
            #pragma unroll
            for (int nt = 0; nt < 4; nt++) {
                int n = wn0 + nt * 8;
                b[nt][0] = Ww[(n + gid) * 260 + kwd + tig];
                b[nt][1] = Ww[(n + gid) * 260 + kwd + tig + 4];
            }
            #pragma unroll
            for (int mt = 0; mt < 2; mt++)
                #pragma unroll
                for (int nt = 0; nt < 4; nt++)
                    mma16(acc[mt * 4 + nt], a[mt], b[nt]);
        }

        // stage partial z per k-half
        float* zsb = kh ? zs1 : zs0;
        #pragma unroll
        for (int u = 0; u < 8; u++) {
            int mt = u >> 2, nt = u & 3;
            int row = wm0 + mt * 16 + gid, col = wn0 + nt * 8 + tig * 2;
            *(float2*)&zsb[row * PZ + col]       = make_float2(acc[u][0], acc[u][1]);
            *(float2*)&zsb[(row + 8) * PZ + col] = make_float2(acc[u][2], acc[u][3]);
        }
        __syncthreads();

        // gate math: 4 cells per thread (HW tanh approx)
        {
            const float* z0 = &zs0[rr * PZ];
            const float* z1 = &zs1[rr * PZ];
            float4 co = *(float4*)&cs[rr * 16 + hq];
            float* cop = (float*)&co;
            float cv[4];
            __half hv[4];
            #pragma unroll
            for (int j = 0; j < 4; j++) {
                float zg = z0[hq + j]      + z1[hq + j]      + zxa[j];
                float zi = z0[16 + hq + j] + z1[16 + hq + j] + zxa[4 + j];
                float zf = z0[32 + hq + j] + z1[32 + hq + j] + zxa[8 + j];
                float zo = z0[48 + hq + j] + z1[48 + hq + j] + zxa[12 + j];
                float gg = tanha(zg);
                float ii = sigf(zi);
                float ff = sigf(zf);
                float oo = sigf(zo);
                float cn = __fmaf_rn(gg, ii, cop[j] * ff);
                cv[j] = cn;
                hv[j] = __float2half_rn(tanha(cn) * oo);
            }
            *(float4*)&cs[rr * 16 + hq] = *(float4*)cv;
            *(uint2*)(hseq + (size_t)(t + 1) * Bsz * Hsz + (size_t)(m0 + rr) * Hsz + h0 + hq)
                = *(uint2*)hv;
        }

        // group barrier: only the 32 CTAs sharing this batch block
        if (t < Tt - 1) {
            __syncthreads();
            if (tid == 0) {
                bar_arrive(&bar[grp]);
                bar_spin(&bar[grp], 32u * (unsigned)(t + 1));
            }
            __syncthreads();
        }
    }
}

// ---------------- big input GEMM: fp16 mma, 128x128 tile, double-buffered ----------------
// B from pre-transposed WT [g][h][k] fp16. A fp32 (XPERM) or fp16.
template <bool XPERM, bool AHALF>
__global__ void __launch_bounds__(256)
gemm_h(const void* __restrict__ Av,
       const __half* __restrict__ WT,    // [4, H, K] fp16
       const float* __restrict__ bias,   // [4*H]
       float* __restrict__ Z,
       int K) {
    extern __shared__ uint32_t smg[];
    uint32_t* As = smg;                      // 2 x 128*GP
    uint32_t* Bs = smg + 2 * 128 * GP;       // 2 x 128*GP
    const float* Af = (const float*)Av;
    const __half* Ah = (const __half*)Av;

    const int m0 = blockIdx.y * 128, n0 = blockIdx.x * 128;
    const int gate = n0 >> 9, h0 = n0 & 511;
    const __half* Bg = WT + ((size_t)gate * Hsz + h0) * K;
    const int tid = threadIdx.x, lane = tid & 31, wid = tid >> 5;
    const int gid = lane >> 2, tig = lane & 3;
    const int wm0 = (wid & 1) * 64, wn0 = (wid >> 1) * 32;

    uint2 ra[4], rb[4];
    auto loadA = [&](int i, int kk) {
        int f4 = tid + i * 256; int row = f4 >> 3, q = f4 & 7;
        size_t off = a_row_off(m0 + row, K, XPERM) + kk + q * 4;
        if (AHALF) {
            ra[i] = *(const uint2*)(Ah + off);
        } else {
            float4 v = *(const float4*)(Af + off);
            __half2 lo = __floats2half2_rn(v.x, v.y);
            __half2 hi = __floats2half2_rn(v.z, v.w);
            ra[i].x = *(uint32_t*)&lo;
            ra[i].y = *(uint32_t*)&hi;
        }
    };
    auto loadB = [&](int i, int kk) {
        int f4 = tid + i * 256; int n = f4 >> 3, q = f4 & 7;
        rb[i] = *(const uint2*)(Bg + (size_t)n * K + kk + q * 4);
    };
    auto storeAB = [&](int buf) {
        uint32_t* ad = As + buf * 128 * GP;
        uint32_t* bd = Bs + buf * 128 * GP;
        #pragma unroll
        for (int i = 0; i < 4; i++) {
            int f4 = tid + i * 256; int row = f4 >> 3, q = f4 & 7;
            *(uint2*)&ad[row * GP + q * 2] = ra[i];
        }
        #pragma unroll
        for (int i = 0; i < 4; i++) {
            int f4 = tid + i * 256; int n = f4 >> 3, q = f4 & 7;
            *(uint2*)&bd[n * GP + q * 2] = rb[i];
        }
    };

    #pragma unroll
    for (int i = 0; i < 4; i++) loadA(i, 0);
    #pragma unroll
    for (int i = 0; i < 4; i++) loadB(i, 0);
    storeAB(0);
    __syncthreads();

    float acc[16][4] = {};
    const int NC = K / 32;

    #pragma unroll 1
    for (int ch = 0; ch < NC; ch++) {
        if (ch + 1 < NC) {
            int kk = (ch + 1) * 32;
            #pragma unroll
            for (int i = 0; i < 4; i++) loadA(i, kk);
            #pragma unroll
            for (int i = 0; i < 4; i++) loadB(i, kk);
        }
        const uint32_t* ab = As + (ch & 1) * 128 * GP;
        const uint32_t* bb = Bs + (ch & 1) * 128 * GP;
        #pragma unroll
        for (int s = 0; s < 2; s++) {
            uint32_t a[4][4], b[4][2];
            #pragma unroll
            for (int mt = 0; mt < 4; mt++) {
                int mm = wm0 + mt * 16;
                a[mt][0] = ab[(mm + gid) * GP + s * 8 + tig];
                a[mt][1] = ab[(mm + 8 + gid) * GP + s * 8 + tig];
                a[mt][2] = ab[(mm + gid) * GP + s * 8 + tig + 4];
                a[mt][3] = ab[(mm + 8 + gid) * GP + s * 8 + tig + 4];
            }
            #pragma unroll
            for (int nt = 0; nt < 4; nt++) {
                int nn = wn0 + nt * 8;
                b[nt][0] = bb[(nn + gid) * GP + s * 8 + tig];
                b[nt][1] = bb[(nn + gid) * GP + s * 8 + tig + 4];
            }
            #pragma unroll
            for (int mt = 0; mt < 4; mt++)
                #pragma unroll
                for (int nt = 0; nt < 4; nt++)
                    mma16(acc[mt * 4 + nt], a[mt], b[nt]);
        }
        if (ch + 1 < NC) storeAB((ch + 1) & 1);
        __syncthreads();
    }

    #pragma unroll
    for (int u = 0; u < 16; u++) {
        int mt = u >> 2, nt = u & 3;
        int row = m0 + wm0 + mt * 16 + gid;
        int col = n0 + wn0 + nt * 8 + tig * 2;
        float b0 = bias[col], b1 = bias[col + 1];
        *(float2*)&Z[(size_t)row * NG + col]       = make_float2(acc[u][0] + b0, acc[u][1] + b1);
        *(float2*)&Z[(size_t)(row + 8) * NG + col] = make_float2(acc[u][2] + b0, acc[u][3] + b1);
    }
}

// ---------------- final projection ----------------
__global__ void proj_kernel(const __half* __restrict__ h2,
                            const float* __restrict__ Wph,  // [H, C]
                            const float* __restrict__ bp,   // [C]
                            float* __restrict__ out) {
    int idx = blockIdx.x * blockDim.x + threadIdx.x;
    if (idx >= Bsz * Csz) return;
    int b = idx / Csz, cc = idx % Csz;
    float s = bp[cc];
    for (int k = 0; k < Hsz; k++)
        s += __half2float(h2[(size_t)b * Hsz + k]) * Wph[(size_t)k * Csz + cc];
    out[idx] = s;
}

// ---------------- launch ----------------
#define PSM ((64 * PWH + 64 * PAH) * 2 + (2 * 64 * PZ + 64 * 16) * 4)
#define GSM ((2 * 128 * GP + 2 * 128 * GP) * 4)

extern "C" void kernel_launch(void* const* d_in, const int* in_sizes, int n_in,
                              void* d_out, int out_size) {
    const float* x   = (const float*)d_in[0];
    const float* Wx1 = (const float*)d_in[1];
    const float* Wh1 = (const float*)d_in[2];
    const float* b1  = (const float*)d_in[3];
    const float* Wx2 = (const float*)d_in[4];
    const float* Wh2 = (const float*)d_in[5];
    const float* b2  = (const float*)d_in[6];
    const float* Wph = (const float*)d_in[7];
    const float* bp  = (const float*)d_in[8];
    float* out = (float*)d_out;

    float *Zx1, *Zx2;
    __half *h1, *h2, *W1T, *W2T;
    unsigned* bar;
    cudaGetSymbolAddress((void**)&Zx1, g_Zx1);
    cudaGetSymbolAddress((void**)&Zx2, g_Zx2);
    cudaGetSymbolAddress((void**)&h1,  g_h1);
    cudaGetSymbolAddress((void**)&h2,  g_h2);
    cudaGetSymbolAddress((void**)&W1T, g_W1T);
    cudaGetSymbolAddress((void**)&W2T, g_W2T);
    cudaGetSymbolAddress((void**)&bar, g_bar);

    cudaFuncSetAttribute(lstm_layer, cudaFuncAttributeMaxDynamicSharedMemorySize, PSM);
    cudaFuncSetAttribute(gemm_h<true, false>, cudaFuncAttributeMaxDynamicSharedMemorySize, GSM);
    cudaFuncSetAttribute(gemm_h<false, true>, cudaFuncAttributeMaxDynamicSharedMemorySize, GSM);

    init_kernel<<<(Bsz * Hsz + 255) / 256, 256>>>();

    // Prep: transpose Wx1/Wx2 to [g][h][k] fp16
    prep_w<<<(4 * Hsz * (Isz / 2) + 255) / 256, 256>>>(Wx1, W1T, Isz);
    prep_w<<<(4 * Hsz * (Hsz / 2) + 255) / 256, 256>>>(Wx2, W2T, Hsz);

    // Phase 1: Zx1 = x @ Wx1 + b1   (M = 65536, K = 128, A fp32 permuted)
    gemm_h<true, false><<<dim3(NG / 128, (Tt * Bsz) / 128), 256, GSM>>>(x, W1T, b1, Zx1, Isz);

    // Phase 2: layer-1 recurrence (persistent)
    lstm_layer<<<dim3(Hsz / 16, Bsz / 64), 256, PSM>>>(Zx1, Wh1, h1, bar + 0);

    // Phase 3: Zx2 = h1_seq @ Wx2 + b2   (M = 65536, K = 512, A fp16)
    gemm_h<false, true><<<dim3(NG / 128, (Tt * Bsz) / 128), 256, GSM>>>(h1 + (size_t)Bsz * Hsz, W2T, b2, Zx2, Hsz);

    // Phase 4: layer-2 recurrence
    lstm_layer<<<dim3(Hsz / 16, Bsz / 64), 256, PSM>>>(Zx2, Wh2, h2, bar + 4);

    // Phase 5: projection
    proj_kernel<<<(Bsz * Csz + 255) / 256, 256>>>(
        h2 + (size_t)Tt * Bsz * Hsz, Wph, bp, out);
}

// round 8
// speedup vs baseline: 7.3270x; 1.0183x over previous
#include <cuda_runtime.h>
#include <cuda_fp16.h>
#include <math.h>
#include <stdint.h>

#define Bsz 256
#define Tt  256
#define Isz 128
#define Hsz 512
#define Csz 10
#define NG  2048   // 4*H

// step-kernel smem pitches (halves)
#define PAH 520    // A tile, m-major; word pitch 260 -> conflict-free frags
#define PWH 520    // Wh tile, n-major
#define PZ  68     // z staging pitch (floats)

// ---------------- scratch ----------------
__device__ __half g_Zx1[(size_t)Tt * Bsz * NG];
__device__ __half g_Zx2[(size_t)Tt * Bsz * NG];
__device__ __half g_h1[(size_t)(Tt + 1) * Bsz * Hsz];
__device__ __half g_h2[(size_t)(Tt + 1) * Bsz * Hsz];
__device__ __half g_xT[(size_t)Tt * Bsz * Isz];   // x as [t][b][k] fp16
__device__ __half g_W1T[(size_t)4 * Hsz * Isz];   // [g][h][k] fp16
__device__ __half g_W2T[(size_t)4 * Hsz * Hsz];   // [g][h][k] fp16
__device__ unsigned g_bar[8];

// ---------------- helpers ----------------
__device__ __forceinline__ void mma16(float* c, const uint32_t* a, const uint32_t* b) {
    asm volatile(
        "mma.sync.aligned.m16n8k16.row.col.f32.f16.f16.f32 "
        "{%0,%1,%2,%3},{%4,%5,%6,%7},{%8,%9},{%0,%1,%2,%3};"
        : "+f"(c[0]), "+f"(c[1]), "+f"(c[2]), "+f"(c[3])
        : "r"(a[0]), "r"(a[1]), "r"(a[2]), "r"(a[3]), "r"(b[0]), "r"(b[1]));
}
__device__ __forceinline__ float tanha(float x) {
    float y;
    asm("tanh.approx.f32 %0, %1;" : "=f"(y) : "f"(x));
    return y;
}
__device__ __forceinline__ float sigf(float x) {
    return __fmaf_rn(0.5f, tanha(0.5f * x), 0.5f);
}
__device__ __forceinline__ uint32_t smem_u32(const void* p) {
    uint32_t a;
    asm("{ .reg .u64 t; cvta.to.shared.u64 t, %1; cvt.u32.u64 %0, t; }" : "=r"(a) : "l"(p));
    return a;
}
__device__ __forceinline__ void cp16(uint32_t dst, const void* src) {
    asm volatile("cp.async.ca.shared.global [%0], [%1], 16;" :: "r"(dst), "l"(src));
}
#define CP_COMMIT() asm volatile("cp.async.commit_group;" ::: "memory")
#define CP_WAIT(n)  asm volatile("cp.async.wait_group %0;" :: "n"(n) : "memory")

__device__ __forceinline__ void bar_arrive(unsigned* p) {
    asm volatile("red.release.gpu.global.add.u32 [%0], %1;" :: "l"(p), "r"(1u) : "memory");
}
__device__ __forceinline__ void bar_spin(unsigned* p, unsigned tgt) {
    unsigned v;
    do {
        asm volatile("ld.acquire.gpu.global.u32 %0, [%1];" : "=r"(v) : "l"(p) : "memory");
    } while (v < tgt);
}

// ---------------- init: zero h slot-0 + barrier counters ----------------
__global__ void init_kernel() {
    int i = blockIdx.x * blockDim.x + threadIdx.x;
    if (i < Bsz * Hsz) {
        g_h1[i] = __float2half(0.f);
        g_h2[i] = __float2half(0.f);
    }
    if (i < 8) g_bar[i] = 0u;
}

// ---------------- prep: x [b][t][k] fp32 -> xT [t][b][k] fp16 ----------------
__global__ void prep_x(const float* __restrict__ x, __half* __restrict__ xT) {
    int idx = blockIdx.x * blockDim.x + threadIdx.x;   // T*B*16 threads, 8 halves each
    if (idx >= Tt * Bsz * 16) return;
    int q = idx & 15;
    int b = (idx >> 4) & (Bsz - 1);
    int t = idx >> 12;
    const float* src = x + ((size_t)b * Tt + t) * Isz + q * 8;
    float4 v0 = *(const float4*)src;
    float4 v1 = *(const float4*)(src + 4);
    __half2 h0 = __floats2half2_rn(v0.x, v0.y);
    __half2 h1 = __floats2half2_rn(v0.z, v0.w);
    __half2 h2 = __floats2half2_rn(v1.x, v1.y);
    __half2 h3 = __floats2half2_rn(v1.z, v1.w);
    uint4 u;
    u.x = *(uint32_t*)&h0; u.y = *(uint32_t*)&h1;
    u.z = *(uint32_t*)&h2; u.w = *(uint32_t*)&h3;
    *(uint4*)(xT + ((size_t)t * Bsz + b) * Isz + q * 8) = u;
}

// ---------------- prep: W[g][k][h] fp32 -> WT[g][h][k] fp16 ----------------
__global__ void prep_w(const float* __restrict__ W, __half* __restrict__ WT, int K) {
    int idx = blockIdx.x * blockDim.x + threadIdx.x;   // over (g, h, k/2)
    int kp = idx % (K / 2);
    int rest = idx / (K / 2);
    int h = rest % Hsz, g = rest / Hsz;
    if (g >= 4) return;
    int k = kp * 2;
    float a = W[((size_t)g * K + k) * Hsz + h];
    float b = W[((size_t)g * K + k + 1) * Hsz + h];
    *(__half2*)(WT + ((size_t)g * Hsz + h) * K + k) = __floats2half2_rn(a, b);
}

// ---------------- big GEMM: fp16 in/out, cp.async, 128x128 tile, K-chunk 64 ----------------
// A fp16 [M][K] rows contiguous; B = WT [g][h][K]; Z fp16 [M][2048].
__global__ void __launch_bounds__(256)
gemm_h2(const __half* __restrict__ A,
        const __half* __restrict__ WT,
        const float* __restrict__ bias,
        __half* __restrict__ Z,
        int K) {
    extern __shared__ __align__(16) unsigned char smg[];
    const uint32_t sb = smem_u32(smg);
    uint32_t* sw = (uint32_t*)smg;

    const int m0 = blockIdx.y * 128, n0 = blockIdx.x * 128;
    const int gate = n0 >> 9, h0 = n0 & 511;
    const __half* Bg = WT + ((size_t)gate * Hsz + h0) * K;
    const int tid = threadIdx.x, lane = tid & 31, wid = tid >> 5;
    const int gid = lane >> 2, tig = lane & 3;
    const int wm0 = (wid & 1) * 64, wn0 = (wid >> 1) * 32;

    auto stage = [&](int buf, int kk) {
        uint32_t base = sb + buf * 36864;
        #pragma unroll
        for (int i = 0; i < 4; i++) {
            int idx = tid + i * 256; int r = idx >> 3, q = idx & 7;
            cp16(base + r * 144 + q * 16, A + (size_t)(m0 + r) * K + kk + q * 8);
        }
        #pragma unroll
        for (int i = 0; i < 4; i++) {
            int idx = tid + i * 256; int r = idx >> 3, q = idx & 7;
            cp16(base + 18432 + r * 144 + q * 16, Bg + (size_t)r * K + kk + q * 8);
        }
        CP_COMMIT();
    };

    stage(0, 0);
    float acc[16][4] = {};
    const int NC = K / 64;

    #pragma unroll 1
    for (int ch = 0; ch < NC; ch++) {
        if (ch + 1 < NC) {
            stage((ch + 1) & 1, (ch + 1) * 64);
            CP_WAIT(1);
        } else {
            CP_WAIT(0);
        }
        __syncthreads();
        const uint32_t* ab = sw + (ch & 1) * 9216;
        const uint32_t* bb = ab + 4608;
        #pragma unroll
        for (int s = 0; s < 4; s++) {
            uint32_t a[4][4], b[4][2];
            #pragma unroll
            for (int mt = 0; mt < 4; mt++) {
                int mm = wm0 + mt * 16;
                a[mt][0] = ab[(mm + gid) * 36 + s * 8 + tig];
                a[mt][1] = ab[(mm + 8 + gid) * 36 + s * 8 + tig];
                a[mt][2] = ab[(mm + gid) * 36 + s * 8 + tig + 4];
                a[mt][3] = ab[(mm + 8 + gid) * 36 + s * 8 + tig + 4];
            }
            #pragma unroll
            for (int nt = 0; nt < 4; nt++) {
                int nn = wn0 + nt * 8;
                b[nt][0] = bb[(nn + gid) * 36 + s * 8 + tig];
                b[nt][1] = bb[(nn + gid) * 36 + s * 8 + tig + 4];
            }
            #pragma unroll
            for (int mt = 0; mt < 4; mt++)
                #pragma unroll
                for (int nt = 0; nt < 4; nt++)
                    mma16(acc[mt * 4 + nt], a[mt], b[nt]);
        }
        __syncthreads();
    }

    #pragma unroll
    for (int u = 0; u < 16; u++) {
        int mt = u >> 2, nt = u & 3;
        int row = m0 + wm0 + mt * 16 + gid;
        int col = n0 + wn0 + nt * 8 + tig * 2;
        float b0 = bias[col], b1 = bias[col + 1];
        *(__half2*)&Z[(size_t)row * NG + col] =
            __floats2half2_rn(acc[u][0] + b0, acc[u][1] + b1);
        *(__half2*)&Z[(size_t)(row + 8) * NG + col] =
            __floats2half2_rn(acc[u][2] + b0, acc[u][3] + b1);
    }
}

// ---------------- persistent recurrent layer (fp16 mma, split-K warps) ----------------
// Grid (32, 4) = 128 CTAs, 256 threads. CTA: batch block 64 x (4 gates x 16 h).
__global__ void __launch_bounds__(256, 1)
lstm_layer(const __half* __restrict__ Zx,   // [T, B, 4H] fp16
           const float* __restrict__ Wh,    // [4, H, H] fp32
           __half* __restrict__ hseq,       // [(T+1), B, H] fp16, slot 0 zeroed
           unsigned* __restrict__ bar) {
    extern __shared__ __align__(16) unsigned char smraw[];
    __half* Ws = (__half*)smraw;                 // 64 n x PWH
    __half* As = Ws + 64 * PWH;                  // 64 m x PAH
    float* zs0 = (float*)(As + 64 * PAH);        // 64 x PZ
    float* zs1 = zs0 + 64 * PZ;                  // 64 x PZ
    float* cs  = zs1 + 64 * PZ;                  // 64 x 16

    const int h0 = blockIdx.x * 16;
    const int m0 = blockIdx.y * 64;
    const int tid = threadIdx.x, lane = tid & 31, wid = tid >> 5;
    const int gid = lane >> 2, tig = lane & 3;
    const int wm0 = (wid & 1) * 32, wn0 = ((wid >> 1) & 1) * 32;
    const int kh  = wid >> 2;
    uint32_t* Aw = (uint32_t*)As;
    uint32_t* Ww = (uint32_t*)Ws;

    // ---- one-time: Wh slice -> SMEM, transposed to n-major fp16 ----
    #pragma unroll 4
    for (int i = 0; i < 32; i++) {
        int f4 = tid + i * 256;
        int k = f4 >> 4, rem = f4 & 15, g = rem >> 2, q = rem & 3;
        float4 v = *(const float4*)(Wh + ((size_t)g * Hsz + k) * Hsz + h0 + q * 4);
        int nb = g * 16 + q * 4;
        Ws[(nb + 0) * PWH + k] = __float2half_rn(v.x);
        Ws[(nb + 1) * PWH + k] = __float2half_rn(v.y);
        Ws[(nb + 2) * PWH + k] = __float2half_rn(v.z);
        Ws[(nb + 3) * PWH + k] = __float2half_rn(v.w);
    }
    *(float4*)&cs[tid * 4] = make_float4(0.f, 0.f, 0.f, 0.f);
    __syncthreads();

    const int rr = tid >> 2;            // gate-phase row 0..63
    const int hq = (tid & 3) * 4;       // gate-phase h offset
    const unsigned grp = blockIdx.y;

    // prefetch Zx[0] (4 halves per gate per thread)
    uint2 zxu[4];
    {
        const __half* zxp = Zx + (size_t)(m0 + rr) * NG + h0 + hq;
        #pragma unroll
        for (int g = 0; g < 4; g++) zxu[g] = __ldcs((const uint2*)(zxp + g * Hsz));
    }

    for (int t = 0; t < Tt; t++) {
        // load full h tile (64 x 512 fp16 = 64KB) into As
        const __half* hp = hseq + (size_t)t * Bsz * Hsz + (size_t)m0 * Hsz;
        #pragma unroll
        for (int i = 0; i < 16; i++) {
            int f4 = tid + i * 256;
            int row = f4 >> 6, u = f4 & 63;
            uint4 v = *(const uint4*)(hp + (size_t)row * Hsz + u * 8);
            *(uint4*)(Aw + row * (PAH / 2) + u * 4) = v;
        }
        __syncthreads();

        float acc[8][4] = {};
        #pragma unroll
        for (int ks = 0; ks < 16; ks++) {
            int kwd = (kh * 16 + ks) * 8;
            uint32_t a[2][4], b[4][2];
            #pragma unroll
            for (int mt = 0; mt < 2; mt++) {
                int m = wm0 + mt * 16;
                a[mt][0] = Aw[(m + gid) * 260 + kwd + tig];
                a[mt][1] = Aw[(m + 8 + gid) * 260 + kwd + tig];
                a[mt][2] = Aw[(m + gid) * 260 + kwd + tig + 4];
                a[mt][3] = Aw[(m + 8 + gid) * 260 + kwd + tig + 4];
            }
            #pragma unroll
            for (int nt = 0; nt < 4; nt++) {
                int n = wn0 + nt * 8;
                b[nt][0] = Ww[(n + gid) * 260 + kwd + tig];
                b[nt][1] = Ww[(n + gid) * 260 + kwd + tig + 4];
            }
            #pragma unroll
            for (int mt = 0; mt < 2; mt++)
                #pragma unroll
                for (int nt = 0; nt < 4; nt++)
                    mma16(acc[mt * 4 + nt], a[mt], b[nt]);
        }

        // stage partial z per k-half
        float* zsb = kh ? zs1 : zs0;
        #pragma unroll
        for (int u = 0; u < 8; u++) {
            int mt = u >> 2, nt = u & 3;
            int row = wm0 + mt * 16 + gid, col = wn0 + nt * 8 + tig * 2;
            *(float2*)&zsb[row * PZ + col]       = make_float2(acc[u][0], acc[u][1]);
            *(float2*)&zsb[(row + 8) * PZ + col] = make_float2(acc[u][2], acc[u][3]);
        }
        __syncthreads();

        // gate math: 4 cells per thread
        {
            const float* z0 = &zs0[rr * PZ];
            const float* z1 = &zs1[rr * PZ];
            float zxa[4][4];
            #pragma unroll
            for (int g = 0; g < 4; g++) {
                __half2* zh = (__half2*)&zxu[g];
                float2 lo = __half22float2(zh[0]);
                float2 hi = __half22float2(zh[1]);
                zxa[g][0] = lo.x; zxa[g][1] = lo.y; zxa[g][2] = hi.x; zxa[g][3] = hi.y;
            }
            float4 co = *(float4*)&cs[rr * 16 + hq];
            float* cop = (float*)&co;
            float cv[4];
            __half hv[4];
            #pragma unroll
            for (int j = 0; j < 4; j++) {
                float zg = z0[hq + j]      + z1[hq + j]      + zxa[0][j];
                float zi = z0[16 + hq + j] + z1[16 + hq + j] + zxa[1][j];
                float zf = z0[32 + hq + j] + z1[32 + hq + j] + zxa[2][j];
                float zo = z0[48 + hq + j] + z1[48 + hq + j] + zxa[3][j];
                float gg = tanha(zg);
                float ii = sigf(zi);
                float ff = sigf(zf);
                float oo = sigf(zo);
                float cn = __fmaf_rn(gg, ii, cop[j] * ff);
                cv[j] = cn;
                hv[j] = __float2half_rn(tanha(cn) * oo);
            }
            *(float4*)&cs[rr * 16 + hq] = *(float4*)cv;
            *(uint2*)(hseq + (size_t)(t + 1) * Bsz * Hsz + (size_t)(m0 + rr) * Hsz + h0 + hq)
                = *(uint2*)hv;
        }

        if (t < Tt - 1) {
            // prefetch Zx[t+1] BEFORE the barrier: DRAM latency overlaps the spin
            const __half* zxp = Zx + (size_t)(t + 1) * Bsz * NG + (size_t)(m0 + rr) * NG + h0 + hq;
            #pragma unroll
            for (int g = 0; g < 4; g++) zxu[g] = __ldcs((const uint2*)(zxp + g * Hsz));

            __syncthreads();
            if (tid == 0) {
                bar_arrive(&bar[grp]);
                bar_spin(&bar[grp], 32u * (unsigned)(t + 1));
            }
            __syncthreads();
        }
    }
}

// ---------------- final projection ----------------
__global__ void proj_kernel(const __half* __restrict__ h2,
                            const float* __restrict__ Wph,  // [H, C]
                            const float* __restrict__ bp,   // [C]
                            float* __restrict__ out) {
    int idx = blockIdx.x * blockDim.x + threadIdx.x;
    if (idx >= Bsz * Csz) return;
    int b = idx / Csz, cc = idx % Csz;
    float s = bp[cc];
    for (int k = 0; k < Hsz; k++)
        s += __half2float(h2[(size_t)b * Hsz + k]) * Wph[(size_t)k * Csz + cc];
    out[idx] = s;
}

// ---------------- launch ----------------
#define PSM ((64 * PWH + 64 * PAH) * 2 + (2 * 64 * PZ + 64 * 16) * 4)
#define GSM (2 * 36864)

extern "C" void kernel_launch(void* const* d_in, const int* in_sizes, int n_in,
                              void* d_out, int out_size) {
    const float* x   = (const float*)d_in[0];
    const float* Wx1 = (const float*)d_in[1];
    const float* Wh1 = (const float*)d_in[2];
    const float* b1  = (const float*)d_in[3];
    const float* Wx2 = (const float*)d_in[4];
    const float* Wh2 = (const float*)d_in[5];
    const float* b2  = (const float*)d_in[6];
    const float* Wph = (const float*)d_in[7];
    const float* bp  = (const float*)d_in[8];
    float* out = (float*)d_out;

    __half *Zx1, *Zx2, *h1, *h2, *xT, *W1T, *W2T;
    unsigned* bar;
    cudaGetSymbolAddress((void**)&Zx1, g_Zx1);
    cudaGetSymbolAddress((void**)&Zx2, g_Zx2);
    cudaGetSymbolAddress((void**)&h1,  g_h1);
    cudaGetSymbolAddress((void**)&h2,  g_h2);
    cudaGetSymbolAddress((void**)&xT,  g_xT);
    cudaGetSymbolAddress((void**)&W1T, g_W1T);
    cudaGetSymbolAddress((void**)&W2T, g_W2T);
    cudaGetSymbolAddress((void**)&bar, g_bar);

    cudaFuncSetAttribute(lstm_layer, cudaFuncAttributeMaxDynamicSharedMemorySize, PSM);
    cudaFuncSetAttribute(gemm_h2, cudaFuncAttributeMaxDynamicSharedMemorySize, GSM);

    init_kernel<<<(Bsz * Hsz + 255) / 256, 256>>>();

    // Prep: x -> [t][b][k] fp16; Wx1/Wx2 -> [g][h][k] fp16
    prep_x<<<(Tt * Bsz * 16 + 255) / 256, 256>>>(x, xT);
    prep_w<<<(4 * Hsz * (Isz / 2) + 255) / 256, 256>>>(Wx1, W1T, Isz);
    prep_w<<<(4 * Hsz * (Hsz / 2) + 255) / 256, 256>>>(Wx2, W2T, Hsz);

    // Phase 1: Zx1 = x @ Wx1 + b1   (M = 65536, K = 128)
    gemm_h2<<<dim3(NG / 128, (Tt * Bsz) / 128), 256, GSM>>>(xT, W1T, b1, Zx1, Isz);

    // Phase 2: layer-1 recurrence (persistent)
    lstm_layer<<<dim3(Hsz / 16, Bsz / 64), 256, PSM>>>(Zx1, Wh1, h1, bar + 0);

    // Phase 3: Zx2 = h1_seq @ Wx2 + b2   (M = 65536, K = 512)
    gemm_h2<<<dim3(NG / 128, (Tt * Bsz) / 128), 256, GSM>>>(h1 + (size_t)Bsz * Hsz, W2T, b2, Zx2, Hsz);

    // Phase 4: layer-2 recurrence
    lstm_layer<<<dim3(Hsz / 16, Bsz / 64), 256, PSM>>>(Zx2, Wh2, h2, bar + 4);

    // Phase 5: projection
    proj_kernel<<<(Bsz * Csz + 255) / 256, 256>>>(
        h2 + (size_t)Tt * Bsz * Hsz, Wph, bp, out);
}

// round 9
// speedup vs baseline: 7.9629x; 1.0868x over previous
#include <cuda_runtime.h>
#include <cuda_fp16.h>
#include <math.h>
#include <stdint.h>

#define Bsz 256
#define Tt  256
#define Isz 128
#define Hsz 512
#define Csz 10
#define NG  2048   // 4*H

// step-kernel smem: Ws [64 n][520 halves], As [64 m][520 halves], pitch 1040B (≡16 mod 128)
#define PAH 520
#define PWH 520
#define PZ  68
#define OFF_AS (64 * PWH * 2)                       // 66560
#define OFF_Z0 (OFF_AS + 64 * PAH * 2)              // 133120
#define OFF_Z1 (OFF_Z0 + 64 * PZ * 4)
#define OFF_CS (OFF_Z1 + 64 * PZ * 4)
#define PSM    (OFF_CS + 64 * 16 * 4)

// gemm: 3 buffers, each A(128x144B) + B(128x144B)
#define GBUF 36864
#define GSM  (3 * GBUF)

// ---------------- scratch ----------------
__device__ __half g_Zx1[(size_t)Tt * Bsz * NG];
__device__ __half g_Zx2[(size_t)Tt * Bsz * NG];
__device__ __half g_h1[(size_t)(Tt + 1) * Bsz * Hsz];
__device__ __half g_h2[(size_t)(Tt + 1) * Bsz * Hsz];
__device__ __half g_xT[(size_t)Tt * Bsz * Isz];   // x as [t][b][k] fp16
__device__ __half g_W1T[(size_t)4 * Hsz * Isz];   // [g][h][k] fp16
__device__ __half g_W2T[(size_t)4 * Hsz * Hsz];   // [g][h][k] fp16
__device__ unsigned g_bar[8];

// ---------------- helpers ----------------
__device__ __forceinline__ void mma16(float* c, const uint32_t* a, const uint32_t* b) {
    asm volatile(
        "mma.sync.aligned.m16n8k16.row.col.f32.f16.f16.f32 "
        "{%0,%1,%2,%3},{%4,%5,%6,%7},{%8,%9},{%0,%1,%2,%3};"
        : "+f"(c[0]), "+f"(c[1]), "+f"(c[2]), "+f"(c[3])
        : "r"(a[0]), "r"(a[1]), "r"(a[2]), "r"(a[3]), "r"(b[0]), "r"(b[1]));
}
__device__ __forceinline__ void ldsm4(uint32_t* r, uint32_t addr) {
    asm volatile("ldmatrix.sync.aligned.m8n8.x4.shared.b16 {%0,%1,%2,%3}, [%4];"
        : "=r"(r[0]), "=r"(r[1]), "=r"(r[2]), "=r"(r[3]) : "r"(addr));
}
__device__ __forceinline__ void ldsm2(uint32_t* r, uint32_t addr) {
    asm volatile("ldmatrix.sync.aligned.m8n8.x2.shared.b16 {%0,%1}, [%2];"
        : "=r"(r[0]), "=r"(r[1]) : "r"(addr));
}
__device__ __forceinline__ float tanha(float x) {
    float y;
    asm("tanh.approx.f32 %0, %1;" : "=f"(y) : "f"(x));
    return y;
}
__device__ __forceinline__ float sigf(float x) {
    return __fmaf_rn(0.5f, tanha(0.5f * x), 0.5f);
}
__device__ __forceinline__ uint32_t smem_u32(const void* p) {
    uint32_t a;
    asm("{ .reg .u64 t; cvta.to.shared.u64 t, %1; cvt.u32.u64 %0, t; }" : "=r"(a) : "l"(p));
    return a;
}
__device__ __forceinline__ void cp16(uint32_t dst, const void* src) {
    asm volatile("cp.async.ca.shared.global [%0], [%1], 16;" :: "r"(dst), "l"(src));
}
#define CP_COMMIT() asm volatile("cp.async.commit_group;" ::: "memory")
#define CP_WAIT(n)  asm volatile("cp.async.wait_group %0;" :: "n"(n) : "memory")

__device__ __forceinline__ void bar_arrive(unsigned* p) {
    asm volatile("red.release.gpu.global.add.u32 [%0], %1;" :: "l"(p), "r"(1u) : "memory");
}
__device__ __forceinline__ void bar_spin(unsigned* p, unsigned tgt) {
    unsigned v;
    do {
        asm volatile("ld.acquire.gpu.global.u32 %0, [%1];" : "=r"(v) : "l"(p) : "memory");
    } while (v < tgt);
}

// ---------------- init ----------------
__global__ void init_kernel() {
    int i = blockIdx.x * blockDim.x + threadIdx.x;
    if (i < Bsz * Hsz) {
        g_h1[i] = __float2half(0.f);
        g_h2[i] = __float2half(0.f);
    }
    if (i < 8) g_bar[i] = 0u;
}

// ---------------- prep: x [b][t][k] fp32 -> xT [t][b][k] fp16 ----------------
__global__ void prep_x(const float* __restrict__ x, __half* __restrict__ xT) {
    int idx = blockIdx.x * blockDim.x + threadIdx.x;
    if (idx >= Tt * Bsz * 16) return;
    int q = idx & 15;
    int b = (idx >> 4) & (Bsz - 1);
    int t = idx >> 12;
    const float* src = x + ((size_t)b * Tt + t) * Isz + q * 8;
    float4 v0 = *(const float4*)src;
    float4 v1 = *(const float4*)(src + 4);
    __half2 h0 = __floats2half2_rn(v0.x, v0.y);
    __half2 h1 = __floats2half2_rn(v0.z, v0.w);
    __half2 h2 = __floats2half2_rn(v1.x, v1.y);
    __half2 h3 = __floats2half2_rn(v1.z, v1.w);
    uint4 u;
    u.x = *(uint32_t*)&h0; u.y = *(uint32_t*)&h1;
    u.z = *(uint32_t*)&h2; u.w = *(uint32_t*)&h3;
    *(uint4*)(xT + ((size_t)t * Bsz + b) * Isz + q * 8) = u;
}

// ---------------- prep: W[g][k][h] fp32 -> WT[g][h][k] fp16 ----------------
__global__ void prep_w(const float* __restrict__ W, __half* __restrict__ WT, int K) {
    int idx = blockIdx.x * blockDim.x + threadIdx.x;
    int kp = idx % (K / 2);
    int rest = idx / (K / 2);
    int h = rest % Hsz, g = rest / Hsz;
    if (g >= 4) return;
    int k = kp * 2;
    float a = W[((size_t)g * K + k) * Hsz + h];
    float b = W[((size_t)g * K + k + 1) * Hsz + h];
    *(__half2*)(WT + ((size_t)g * Hsz + h) * K + k) = __floats2half2_rn(a, b);
}

// ---------------- big GEMM: fp16 in/out, cp.async 3-stage, 128x128 tile, K-chunk 64 ----------------
__global__ void __launch_bounds__(256)
gemm_h2(const __half* __restrict__ A,
        const __half* __restrict__ WT,
        const float* __restrict__ bias,
        __half* __restrict__ Z,
        int K) {
    extern __shared__ __align__(16) unsigned char smg[];
    const uint32_t sb = smem_u32(smg);

    const int m0 = blockIdx.y * 128, n0 = blockIdx.x * 128;
    const int gate = n0 >> 9, h0 = n0 & 511;
    const __half* Bg = WT + ((size_t)gate * Hsz + h0) * K;
    const int tid = threadIdx.x, lane = tid & 31, wid = tid >> 5;
    const int gid = lane >> 2, tig = lane & 3;
    const int wm0 = (wid & 1) * 64, wn0 = (wid >> 1) * 32;
    const int l7 = lane & 7, l8 = (lane >> 3) & 1, l16 = lane >> 4;

    // ldmatrix lane-relative offsets (within a buffer)
    uint32_t araw[4], braw[4];
    #pragma unroll
    for (int mt = 0; mt < 4; mt++)
        araw[mt] = (uint32_t)((wm0 + mt * 16 + l7 + l8 * 8) * 144 + l16 * 16);
    #pragma unroll
    for (int nt = 0; nt < 4; nt++)
        braw[nt] = (uint32_t)(18432 + (wn0 + nt * 8 + l7) * 144 + l8 * 16);

    auto stage = [&](int buf, int kk) {
        uint32_t base = sb + buf * GBUF;
        #pragma unroll
        for (int i = 0; i < 4; i++) {
            int idx = tid + i * 256; int r = idx >> 3, q = idx & 7;
            cp16(base + r * 144 + q * 16, A + (size_t)(m0 + r) * K + kk + q * 8);
        }
        #pragma unroll
        for (int i = 0; i < 4; i++) {
            int idx = tid + i * 256; int r = idx >> 3, q = idx & 7;
            cp16(base + 18432 + r * 144 + q * 16, Bg + (size_t)r * K + kk + q * 8);
        }
        CP_COMMIT();
    };

    const int NC = K / 64;
    stage(0, 0);
    if (NC > 1) stage(1, 64);
    float acc[16][4] = {};

    #pragma unroll 1
    for (int ch = 0; ch < NC; ch++) {
        if (ch + 2 < NC) {
            stage((ch + 2) % 3, (ch + 2) * 64);
            CP_WAIT(2);
        } else if (ch + 1 < NC) {
            CP_WAIT(1);
        } else {
            CP_WAIT(0);
        }
        __syncthreads();
        uint32_t bufb = sb + (ch % 3) * GBUF;
        #pragma unroll
        for (int s = 0; s < 4; s++) {
            uint32_t a[4][4], b[4][2];
            #pragma unroll
            for (int mt = 0; mt < 4; mt++) ldsm4(a[mt], bufb + araw[mt] + s * 32);
            #pragma unroll
            for (int nt = 0; nt < 4; nt++) ldsm2(b[nt], bufb + braw[nt] + s * 32);
            #pragma unroll
            for (int mt = 0; mt < 4; mt++)
                #pragma unroll
                for (int nt = 0; nt < 4; nt++)
                    mma16(acc[mt * 4 + nt], a[mt], b[nt]);
        }
        __syncthreads();
    }

    #pragma unroll
    for (int u = 0; u < 16; u++) {
        int mt = u >> 2, nt = u & 3;
        int row = m0 + wm0 + mt * 16 + gid;
        int col = n0 + wn0 + nt * 8 + tig * 2;
        float b0 = bias[col], b1 = bias[col + 1];
        *(__half2*)&Z[(size_t)row * NG + col] =
            __floats2half2_rn(acc[u][0] + b0, acc[u][1] + b1);
        *(__half2*)&Z[(size_t)(row + 8) * NG + col] =
            __floats2half2_rn(acc[u][2] + b0, acc[u][3] + b1);
    }
}

// ---------------- persistent recurrent layer (fp16 mma, ldmatrix, cp.async staging) ----------------
// Grid (32, 4) = 128 CTAs, 256 threads. CTA: batch block 64 x (4 gates x 16 h).
__global__ void __launch_bounds__(256, 1)
lstm_layer(const __half* __restrict__ Zx,   // [T, B, 4H] fp16
           const float* __restrict__ Wh,    // [4, H, H] fp32
           __half* __restrict__ hseq,       // [(T+1), B, H] fp16, slot 0 zeroed
           unsigned* __restrict__ bar) {
    extern __shared__ __align__(16) unsigned char smraw[];
    const uint32_t sb = smem_u32(smraw);
    __half* Ws = (__half*)smraw;
    float* zs0 = (float*)(smraw + OFF_Z0);
    float* zs1 = (float*)(smraw + OFF_Z1);
    float* cs  = (float*)(smraw + OFF_CS);

    const int h0 = blockIdx.x * 16;
    const int m0 = blockIdx.y * 64;
    const int tid = threadIdx.x, lane = tid & 31, wid = tid >> 5;
    const int gid = lane >> 2, tig = lane & 3;
    const int wm0 = (wid & 1) * 32, wn0 = ((wid >> 1) & 1) * 32;
    const int kh  = wid >> 2;
    const int l7 = lane & 7, l8 = (lane >> 3) & 1, l16 = lane >> 4;

    // ---- one-time: Wh slice -> SMEM, transposed to n-major fp16 ----
    #pragma unroll 4
    for (int i = 0; i < 32; i++) {
        int f4 = tid + i * 256;
        int k = f4 >> 4, rem = f4 & 15, g = rem >> 2, q = rem & 3;
        float4 v = *(const float4*)(Wh + ((size_t)g * Hsz + k) * Hsz + h0 + q * 4);
        int nb = g * 16 + q * 4;
        Ws[(nb + 0) * PWH + k] = __float2half_rn(v.x);
        Ws[(nb + 1) * PWH + k] = __float2half_rn(v.y);
        Ws[(nb + 2) * PWH + k] = __float2half_rn(v.z);
        Ws[(nb + 3) * PWH + k] = __float2half_rn(v.w);
    }
    *(float4*)&cs[tid * 4] = make_float4(0.f, 0.f, 0.f, 0.f);
    __syncthreads();

    // t-invariant ldmatrix addresses (bytes)
    uint32_t abase[2], bbase[4];
    #pragma unroll
    for (int mt = 0; mt < 2; mt++)
        abase[mt] = sb + OFF_AS + (wm0 + mt * 16 + l7 + l8 * 8) * 1040 + l16 * 16 + kh * 512;
    #pragma unroll
    for (int nt = 0; nt < 4; nt++)
        bbase[nt] = sb + (wn0 + nt * 8 + l7) * 1040 + l8 * 16 + kh * 512;

    const int rr = tid >> 2;            // gate-phase row 0..63
    const int hq = (tid & 3) * 4;       // gate-phase h offset
    const unsigned grp = blockIdx.y;

    // prefetch Zx[0]
    uint2 zxu[4];
    {
        const __half* zxp = Zx + (size_t)(m0 + rr) * NG + h0 + hq;
        #pragma unroll
        for (int g = 0; g < 4; g++) zxu[g] = __ldcs((const uint2*)(zxp + g * Hsz));
    }

    for (int t = 0; t < Tt; t++) {
        // stage h tile (64 x 512 fp16 = 64KB) via cp.async
        const __half* hp = hseq + (size_t)t * Bsz * Hsz + (size_t)m0 * Hsz;
        #pragma unroll
        for (int i = 0; i < 16; i++) {
            int f4 = tid + i * 256;
            int row = f4 >> 6, u = f4 & 63;
            cp16(sb + OFF_AS + row * 1040 + u * 16, hp + (size_t)row * Hsz + u * 8);
        }
        CP_COMMIT();
        CP_WAIT(0);
        __syncthreads();

        float acc[8][4] = {};
        #pragma unroll
        for (int ks = 0; ks < 16; ks++) {
            uint32_t a[2][4], b[4][2];
            ldsm4(a[0], abase[0] + ks * 32);
            ldsm4(a[1], abase[1] + ks * 32);
            #pragma unroll
            for (int nt = 0; nt < 4; nt++) ldsm2(b[nt], bbase[nt] + ks * 32);
            #pragma unroll
            for (int mt = 0; mt < 2; mt++)
                #pragma unroll
                for (int nt = 0; nt < 4; nt++)
                    mma16(acc[mt * 4 + nt], a[mt], b[nt]);
        }

        // stage partial z per k-half
        float* zsb = kh ? zs1 : zs0;
        #pragma unroll
        for (int u = 0; u < 8; u++) {
            int mt = u >> 2, nt = u & 3;
            int row = wm0 + mt * 16 + gid, col = wn0 + nt * 8 + tig * 2;
            *(float2*)&zsb[row * PZ + col]       = make_float2(acc[u][0], acc[u][1]);
            *(float2*)&zsb[(row + 8) * PZ + col] = make_float2(acc[u][2], acc[u][3]);
        }
        __syncthreads();

        // gate math: 4 cells per thread
        {
            const float* z0 = &zs0[rr * PZ];
            const float* z1 = &zs1[rr * PZ];
            float zxa[4][4];
            #pragma unroll
            for (int g = 0; g < 4; g++) {
                __half2* zh = (__half2*)&zxu[g];
                float2 lo = __half22float2(zh[0]);
                float2 hi = __half22float2(zh[1]);
                zxa[g][0] = lo.x; zxa[g][1] = lo.y; zxa[g][2] = hi.x; zxa[g][3] = hi.y;
            }
            float4 co = *(float4*)&cs[rr * 16 + hq];
            float* cop = (float*)&co;
            float cv[4];
            __half hv[4];
            #pragma unroll
            for (int j = 0; j < 4; j++) {
                float zg = z0[hq + j]      + z1[hq + j]      + zxa[0][j];
                float zi = z0[16 + hq + j] + z1[16 + hq + j] + zxa[1][j];
                float zf = z0[32 + hq + j] + z1[32 + hq + j] + zxa[2][j];
                float zo = z0[48 + hq + j] + z1[48 + hq + j] + zxa[3][j];
                float gg = tanha(zg);
                float ii = sigf(zi);
                float ff = sigf(zf);
                float oo = sigf(zo);
                float cn = __fmaf_rn(gg, ii, cop[j] * ff);
                cv[j] = cn;
                hv[j] = __float2half_rn(tanha(cn) * oo);
            }
            *(float4*)&cs[rr * 16 + hq] = *(float4*)cv;
            *(uint2*)(hseq + (size_t)(t + 1) * Bsz * Hsz + (size_t)(m0 + rr) * Hsz + h0 + hq)
                = *(uint2*)hv;
        }

        if (t < Tt - 1) {
            // prefetch Zx[t+1] BEFORE the barrier: DRAM latency overlaps the spin
            const __half* zxp = Zx + (size_t)(t + 1) * Bsz * NG + (size_t)(m0 + rr) * NG + h0 + hq;
            #pragma unroll
            for (int g = 0; g < 4; g++) zxu[g] = __ldcs((const uint2*)(zxp + g * Hsz));

            __syncthreads();
            if (tid == 0) {
                bar_arrive(&bar[grp]);
                bar_spin(&bar[grp], 32u * (unsigned)(t + 1));
            }
            __syncthreads();
        }
    }
}

// ---------------- final projection ----------------
__global__ void proj_kernel(const __half* __restrict__ h2,
                            const float* __restrict__ Wph,
                            const float* __restrict__ bp,
                            float* __restrict__ out) {
    int idx = blockIdx.x * blockDim.x + threadIdx.x;
    if (idx >= Bsz * Csz) return;
    int b = idx / Csz, cc = idx % Csz;
    float s = bp[cc];
    for (int k = 0; k < Hsz; k++)
        s += __half2float(h2[(size_t)b * Hsz + k]) * Wph[(size_t)k * Csz + cc];
    out[idx] = s;
}

// ---------------- launch ----------------
extern "C" void kernel_launch(void* const* d_in, const int* in_sizes, int n_in,
                              void* d_out, int out_size) {
    const float* x   = (const float*)d_in[0];
    const float* Wx1 = (const float*)d_in[1];
    const float* Wh1 = (const float*)d_in[2];
    const float* b1  = (const float*)d_in[3];
    const float* Wx2 = (const float*)d_in[4];
    const float* Wh2 = (const float*)d_in[5];
    const float* b2  = (const float*)d_in[6];
    const float* Wph = (const float*)d_in[7];
    const float* bp  = (const float*)d_in[8];
    float* out = (float*)d_out;

    __half *Zx1, *Zx2, *h1, *h2, *xT, *W1T, *W2T;
    unsigned* bar;
    cudaGetSymbolAddress((void**)&Zx1, g_Zx1);
    cudaGetSymbolAddress((void**)&Zx2, g_Zx2);
    cudaGetSymbolAddress((void**)&h1,  g_h1);
    cudaGetSymbolAddress((void**)&h2,  g_h2);
    cudaGetSymbolAddress((void**)&xT,  g_xT);
    cudaGetSymbolAddress((void**)&W1T, g_W1T);
    cudaGetSymbolAddress((void**)&W2T, g_W2T);
    cudaGetSymbolAddress((void**)&bar, g_bar);

    cudaFuncSetAttribute(lstm_layer, cudaFuncAttributeMaxDynamicSharedMemorySize, PSM);
    cudaFuncSetAttribute(gemm_h2, cudaFuncAttributeMaxDynamicSharedMemorySize, GSM);

    init_kernel<<<(Bsz * Hsz + 255) / 256, 256>>>();

    prep_x<<<(Tt * Bsz * 16 + 255) / 256, 256>>>(x, xT);
    prep_w<<<(4 * Hsz * (Isz / 2) + 255) / 256, 256>>>(Wx1, W1T, Isz);
    prep_w<<<(4 * Hsz * (Hsz / 2) + 255) / 256, 256>>>(Wx2, W2T, Hsz);

    // Phase 1: Zx1 = x @ Wx1 + b1
    gemm_h2<<<dim3(NG / 128, (Tt * Bsz) / 128), 256, GSM>>>(xT, W1T, b1, Zx1, Isz);

    // Phase 2: layer-1 recurrence
    lstm_layer<<<dim3(Hsz / 16, Bsz / 64), 256, PSM>>>(Zx1, Wh1, h1, bar + 0);

    // Phase 3: Zx2 = h1_seq @ Wx2 + b2
    gemm_h2<<<dim3(NG / 128, (Tt * Bsz) / 128), 256, GSM>>>(h1 + (size_t)Bsz * Hsz, W2T, b2, Zx2, Hsz);

    // Phase 4: layer-2 recurrence
    lstm_layer<<<dim3(Hsz / 16, Bsz / 64), 256, PSM>>>(Zx2, Wh2, h2, bar + 4);

    // Phase 5: projection
    proj_kernel<<<(Bsz * Csz + 255) / 256, 256>>>(
        h2 + (size_t)Tt * Bsz * Hsz, Wph, bp, out);
}

// round 11
// speedup vs baseline: 8.3029x; 1.0427x over previous
#include <cuda_runtime.h>
#include <cuda_fp16.h>
#include <math.h>
#include <stdint.h>

#define Bsz 256
#define Tt  256
#define Isz 128
#define Hsz 512
#define Csz 10
#define NG  2048   // 4*H

// step-kernel smem (bytes); pitch 1040B (== 16 mod 128 -> conflict-free ldsm)
#define PAH    520
#define PWH    520
#define PZ     68    // z0 pitch (floats)
#define PZ1    68    // z1 pitch (halves)
#define OFF_AS 66560                 // after Ws (64*1040)
#define OFF_Z0 (OFF_AS + 66560)      // 133120
#define OFF_Z1 (OFF_Z0 + 64 * PZ * 4)        // 150528
#define OFF_WX (OFF_Z1 + 64 * PZ1 * 2)       // 159232
#define PSM_P  (OFF_WX + 66560)      // 225792 (with Wx slice)
#define PSM_NP OFF_WX                // 159232 (layer 2)

// gemm: 3 buffers, each A(128x144B) + B(128x144B)
#define GBUF 36864
#define GSM  (3 * GBUF)

// ---------------- scratch ----------------
__device__ __half g_Zx1[(size_t)Tt * Bsz * NG];
__device__ __half g_Zx2[(size_t)Tt * Bsz * NG];
__device__ __half g_h1[(size_t)(Tt + 1) * Bsz * Hsz];
__device__ __half g_h2[(size_t)(Tt + 1) * Bsz * Hsz];
__device__ __half g_xT[(size_t)Tt * Bsz * Isz];
__device__ __half g_W1T[(size_t)4 * Hsz * Isz];
__device__ __half g_W2T[(size_t)4 * Hsz * Hsz];
__device__ unsigned g_bar[8];

// ---------------- helpers ----------------
__device__ __forceinline__ void mma16(float* c, const uint32_t* a, const uint32_t* b) {
    asm volatile(
        "mma.sync.aligned.m16n8k16.row.col.f32.f16.f16.f32 "
        "{%0,%1,%2,%3},{%4,%5,%6,%7},{%8,%9},{%0,%1,%2,%3};"
        : "+f"(c[0]), "+f"(c[1]), "+f"(c[2]), "+f"(c[3])
        : "r"(a[0]), "r"(a[1]), "r"(a[2]), "r"(a[3]), "r"(b[0]), "r"(b[1]));
}
__device__ __forceinline__ void ldsm4(uint32_t* r, uint32_t addr) {
    asm volatile("ldmatrix.sync.aligned.m8n8.x4.shared.b16 {%0,%1,%2,%3}, [%4];"
        : "=r"(r[0]), "=r"(r[1]), "=r"(r[2]), "=r"(r[3]) : "r"(addr));
}
__device__ __forceinline__ void ldsm2(uint32_t* r, uint32_t addr) {
    asm volatile("ldmatrix.sync.aligned.m8n8.x2.shared.b16 {%0,%1}, [%2];"
        : "=r"(r[0]), "=r"(r[1]) : "r"(addr));
}
__device__ __forceinline__ float tanha(float x) {
    float y;
    asm("tanh.approx.f32 %0, %1;" : "=f"(y) : "f"(x));
    return y;
}
__device__ __forceinline__ float sigf(float x) {
    return __fmaf_rn(0.5f, tanha(0.5f * x), 0.5f);
}
__device__ __forceinline__ uint32_t smem_u32(const void* p) {
    uint32_t a;
    asm("{ .reg .u64 t; cvta.to.shared.u64 t, %1; cvt.u32.u64 %0, t; }" : "=r"(a) : "l"(p));
    return a;
}
__device__ __forceinline__ void cp16(uint32_t dst, const void* src) {
    asm volatile("cp.async.ca.shared.global [%0], [%1], 16;" :: "r"(dst), "l"(src));
}
#define CP_COMMIT() asm volatile("cp.async.commit_group;" ::: "memory")
#define CP_WAIT(n)  asm volatile("cp.async.wait_group %0;" :: "n"(n) : "memory")

__device__ __forceinline__ void bar_arrive(unsigned* p) {
    asm volatile("red.release.gpu.global.add.u32 [%0], %1;" :: "l"(p), "r"(1u) : "memory");
}
__device__ __forceinline__ void bar_spin(unsigned* p, unsigned tgt) {
    unsigned v;
    do {
        asm volatile("ld.acquire.gpu.global.u32 %0, [%1];" : "=r"(v) : "l"(p) : "memory");
    } while (v < tgt);
}

// ---------------- init ----------------
__global__ void init_kernel() {
    int i = blockIdx.x * blockDim.x + threadIdx.x;
    if (i < Bsz * Hsz) {
        g_h1[i] = __float2half(0.f);
        g_h2[i] = __float2half(0.f);
    }
    if (i < 8) g_bar[i] = 0u;
}

// ---------------- prep: x [b][t][k] fp32 -> xT [t][b][k] fp16 ----------------
__global__ void prep_x(const float* __restrict__ x, __half* __restrict__ xT) {
    int idx = blockIdx.x * blockDim.x + threadIdx.x;
    if (idx >= Tt * Bsz * 16) return;
    int q = idx & 15;
    int b = (idx >> 4) & (Bsz - 1);
    int t = idx >> 12;
    const float* src = x + ((size_t)b * Tt + t) * Isz + q * 8;
    float4 v0 = *(const float4*)src;
    float4 v1 = *(const float4*)(src + 4);
    __half2 h0 = __floats2half2_rn(v0.x, v0.y);
    __half2 h1 = __floats2half2_rn(v0.z, v0.w);
    __half2 h2 = __floats2half2_rn(v1.x, v1.y);
    __half2 h3 = __floats2half2_rn(v1.z, v1.w);
    uint4 u;
    u.x = *(uint32_t*)&h0; u.y = *(uint32_t*)&h1;
    u.z = *(uint32_t*)&h2; u.w = *(uint32_t*)&h3;
    *(uint4*)(xT + ((size_t)t * Bsz + b) * Isz + q * 8) = u;
}

// ---------------- prep: W[g][k][h] fp32 -> WT[g][h][k] fp16 ----------------
__global__ void prep_w(const float* __restrict__ W, __half* __restrict__ WT, int K) {
    int idx = blockIdx.x * blockDim.x + threadIdx.x;
    int kp = idx % (K / 2);
    int rest = idx / (K / 2);
    int h = rest % Hsz, g = rest / Hsz;
    if (g >= 4) return;
    int k = kp * 2;
    float a = W[((size_t)g * K + k) * Hsz + h];
    float b = W[((size_t)g * K + k + 1) * Hsz + h];
    *(__half2*)(WT + ((size_t)g * Hsz + h) * K + k) = __floats2half2_rn(a, b);
}

// ---------------- big GEMM: fp16 in/out, cp.async 3-stage, 128x128 tile ----------------
__global__ void __launch_bounds__(256)
gemm_h2(const __half* __restrict__ A,
        const __half* __restrict__ WT,
        const float* __restrict__ bias,
        __half* __restrict__ Z,
        int K) {
    extern __shared__ __align__(16) unsigned char smg[];
    const uint32_t sb = smem_u32(smg);

    const int m0 = blockIdx.y * 128, n0 = blockIdx.x * 128;
    const int gate = n0 >> 9, h0 = n0 & 511;
    const __half* Bg = WT + ((size_t)gate * Hsz + h0) * K;
    const int tid = threadIdx.x, lane = tid & 31, wid = tid >> 5;
    const int gid = lane >> 2, tig = lane & 3;
    const int wm0 = (wid & 1) * 64, wn0 = (wid >> 1) * 32;
    const int l7 = lane & 7, l8 = (lane >> 3) & 1, l16 = lane >> 4;

    uint32_t araw[4], braw[4];
    #pragma unroll
    for (int mt = 0; mt < 4; mt++)
        araw[mt] = (uint32_t)((wm0 + mt * 16 + l7 + l8 * 8) * 144 + l16 * 16);
    #pragma unroll
    for (int nt = 0; nt < 4; nt++)
        braw[nt] = (uint32_t)(18432 + (wn0 + nt * 8 + l7) * 144 + l8 * 16);

    auto stage = [&](int buf, int kk) {
        uint32_t base = sb + buf * GBUF;
        #pragma unroll
        for (int i = 0; i < 4; i++) {
            int idx = tid + i * 256; int r = idx >> 3, q = idx & 7;
            cp16(base + r * 144 + q * 16, A + (size_t)(m0 + r) * K + kk + q * 8);
        }
        #pragma unroll
        for (int i = 0; i < 4; i++) {
            int idx = tid + i * 256; int r = idx >> 3, q = idx & 7;
            cp16(base + 18432 + r * 144 + q * 16, Bg + (size_t)r * K + kk + q * 8);
        }
        CP_COMMIT();
    };

    const int NC = K / 64;
    stage(0, 0);
    if (NC > 1) stage(1, 64);
    float acc[16][4] = {};

    #pragma unroll 1
    for (int ch = 0; ch < NC; ch++) {
        if (ch + 2 < NC) {
            stage((ch + 2) % 3, (ch + 2) * 64);
            CP_WAIT(2);
        } else if (ch + 1 < NC) {
            CP_WAIT(1);
        } else {
            CP_WAIT(0);
        }
        __syncthreads();
        uint32_t bufb = sb + (ch % 3) * GBUF;
        #pragma unroll
        for (int s = 0; s < 4; s++) {
            uint32_t a[4][4], b[4][2];
            #pragma unroll
            for (int mt = 0; mt < 4; mt++) ldsm4(a[mt], bufb + araw[mt] + s * 32);
            #pragma unroll
            for (int nt = 0; nt < 4; nt++) ldsm2(b[nt], bufb + braw[nt] + s * 32);
            #pragma unroll
            for (int mt = 0; mt < 4; mt++)
                #pragma unroll
                for (int nt = 0; nt < 4; nt++)
                    mma16(acc[mt * 4 + nt], a[mt], b[nt]);
        }
        __syncthreads();
    }

    #pragma unroll
    for (int u = 0; u < 16; u++) {
        int mt = u >> 2, nt = u & 3;
        int row = m0 + wm0 + mt * 16 + gid;
        int col = n0 + wn0 + nt * 8 + tig * 2;
        float b0 = bias[col], b1 = bias[col + 1];
        *(__half2*)&Z[(size_t)row * NG + col] =
            __floats2half2_rn(acc[u][0] + b0, acc[u][1] + b1);
        *(__half2*)&Z[(size_t)(row + 8) * NG + col] =
            __floats2half2_rn(acc[u][2] + b0, acc[u][3] + b1);
    }
}

// ---------------- persistent recurrent layer ----------------
// Grid (32, 4) = 128 CTAs, 256 threads. CTA: batch block 64 x (4 gates x 16 h).
// PRODUCE: also computes Zx2 block t-1 (= A_tile @ Wx2_slice + b2) in the barrier window.
// Producer uses FULL-K per-warp tiling (wm=(wid&1)*32, wn=(wid>>1)*16): each output
// element owned by exactly one warp (the R9 bug was split-K partials clobbering).
template <bool PRODUCE>
__global__ void __launch_bounds__(256, 1)
lstm_layer(const __half* __restrict__ Zx,    // [T, B, 4H] fp16
           const float* __restrict__ Wh,     // [4, H, H] fp32
           __half* __restrict__ hseq,        // [(T+1), B, H] fp16, slot 0 zeroed
           unsigned* __restrict__ bar,
           const __half* __restrict__ WxT,   // [4, H, 512] fp16 (PRODUCE only)
           const float* __restrict__ bias2,  // [4*H] (PRODUCE only)
           __half* __restrict__ Zxout) {     // [T, B, 4H] fp16 (PRODUCE only)
    extern __shared__ __align__(16) unsigned char smraw[];
    const uint32_t sb = smem_u32(smraw);
    __half* Ws = (__half*)smraw;
    float*  zs0 = (float*)(smraw + OFF_Z0);
    __half* zs1 = (__half*)(smraw + OFF_Z1);

    const int h0 = blockIdx.x * 16;
    const int m0 = blockIdx.y * 64;
    const int tid = threadIdx.x, lane = tid & 31, wid = tid >> 5;
    const int gid = lane >> 2, tig = lane & 3;
    const int wm0 = (wid & 1) * 32, wn0 = ((wid >> 1) & 1) * 32;
    const int kh  = wid >> 2;
    const int l7 = lane & 7, l8 = (lane >> 3) & 1, l16 = lane >> 4;

    // ---- one-time: Wh slice -> SMEM, n-major fp16 ----
    #pragma unroll 4
    for (int i = 0; i < 32; i++) {
        int f4 = tid + i * 256;
        int k = f4 >> 4, rem = f4 & 15, g = rem >> 2, q = rem & 3;
        float4 v = *(const float4*)(Wh + ((size_t)g * Hsz + k) * Hsz + h0 + q * 4);
        int nb = g * 16 + q * 4;
        Ws[(nb + 0) * PWH + k] = __float2half_rn(v.x);
        Ws[(nb + 1) * PWH + k] = __float2half_rn(v.y);
        Ws[(nb + 2) * PWH + k] = __float2half_rn(v.z);
        Ws[(nb + 3) * PWH + k] = __float2half_rn(v.w);
    }
    // ---- one-time: Wx2 slice -> SMEM (PRODUCE) ----
    if (PRODUCE) {
        #pragma unroll
        for (int i = 0; i < 16; i++) {
            int idx = tid + i * 256;
            int n = idx >> 6, q = idx & 63;
            int g = n >> 4, hh = n & 15;
            cp16(sb + OFF_WX + n * 1040 + q * 16,
                 WxT + ((size_t)g * Hsz + h0 + hh) * 512 + q * 8);
        }
        CP_COMMIT();
        CP_WAIT(0);
    }
    __syncthreads();

    // t-invariant ldmatrix addresses (bytes) — recurrent split-K path
    uint32_t abase[2], bbase[4];
    #pragma unroll
    for (int mt = 0; mt < 2; mt++)
        abase[mt] = sb + OFF_AS + (wm0 + mt * 16 + l7 + l8 * 8) * 1040 + l16 * 16 + kh * 512;
    #pragma unroll
    for (int nt = 0; nt < 4; nt++)
        bbase[nt] = sb + (wn0 + nt * 8 + l7) * 1040 + l8 * 16 + kh * 512;

    // producer addresses — FULL-K tiling: wm0 (rows), wn0p = (wid>>1)*16 (cols)
    const int wn0p = (wid >> 1) * 16;
    uint32_t pabase[2], pxbase[2];
    int gc2[2];
    float2 bsv2[2];
    if (PRODUCE) {
        #pragma unroll
        for (int mt = 0; mt < 2; mt++)
            pabase[mt] = sb + OFF_AS + (wm0 + mt * 16 + l7 + l8 * 8) * 1040 + l16 * 16;
        #pragma unroll
        for (int nt = 0; nt < 2; nt++) {
            pxbase[nt] = sb + OFF_WX + (wn0p + nt * 8 + l7) * 1040 + l8 * 16;
            int n = wn0p + nt * 8 + tig * 2;     // 0..63
            int g = n >> 4, hh = n & 15;
            gc2[nt] = g * Hsz + h0 + hh;
            bsv2[nt] = make_float2(bias2[gc2[nt]], bias2[gc2[nt] + 1]);
        }
    }

    const int rr = tid >> 2;
    const int hq = (tid & 3) * 4;
    const unsigned grp = blockIdx.y;

    float cr[4] = {0.f, 0.f, 0.f, 0.f};

    // prefetch Zx[0]
    uint2 zxu[4];
    {
        const __half* zxp = Zx + (size_t)(m0 + rr) * NG + h0 + hq;
        #pragma unroll
        for (int g = 0; g < 4; g++) zxu[g] = __ldcs((const uint2*)(zxp + g * Hsz));
    }

    // full-K producer (A tile currently staged in As, all 512 k)
    auto produce = [&](int tdst) {
        float za[4][4] = {};
        #pragma unroll 8
        for (int ks = 0; ks < 32; ks++) {
            uint32_t a[2][4], b[2][2];
            ldsm4(a[0], pabase[0] + ks * 32);
            ldsm4(a[1], pabase[1] + ks * 32);
            ldsm2(b[0], pxbase[0] + ks * 32);
            ldsm2(b[1], pxbase[1] + ks * 32);
            mma16(za[0], a[0], b[0]); mma16(za[1], a[0], b[1]);
            mma16(za[2], a[1], b[0]); mma16(za[3], a[1], b[1]);
        }
        __half* zb = Zxout + ((size_t)tdst * Bsz + m0) * NG;
        #pragma unroll
        for (int u = 0; u < 4; u++) {
            int mt = u >> 1, nt = u & 1;
            int row = wm0 + mt * 16 + gid;
            *(__half2*)&zb[(size_t)row * NG + gc2[nt]] =
                __floats2half2_rn(za[u][0] + bsv2[nt].x, za[u][1] + bsv2[nt].y);
            *(__half2*)&zb[(size_t)(row + 8) * NG + gc2[nt]] =
                __floats2half2_rn(za[u][2] + bsv2[nt].x, za[u][3] + bsv2[nt].y);
        }
    };

    for (int t = 0; t < Tt; t++) {
        // stage h tile (64 x 512 fp16) via cp.async
        const __half* hp = hseq + (size_t)t * Bsz * Hsz + (size_t)m0 * Hsz;
        #pragma unroll
        for (int i = 0; i < 16; i++) {
            int f4 = tid + i * 256;
            int row = f4 >> 6, u = f4 & 63;
            cp16(sb + OFF_AS + row * 1040 + u * 16, hp + (size_t)row * Hsz + u * 8);
        }
        CP_COMMIT();
        CP_WAIT(0);
        __syncthreads();

        // recurrent mma (split-K over warps)
        float acc[8][4] = {};
        #pragma unroll
        for (int ks = 0; ks < 16; ks++) {
            uint32_t a[2][4], b[4][2];
            ldsm4(a[0], abase[0] + ks * 32);
            ldsm4(a[1], abase[1] + ks * 32);
            #pragma unroll
            for (int nt = 0; nt < 4; nt++) ldsm2(b[nt], bbase[nt] + ks * 32);
            #pragma unroll
            for (int mt = 0; mt < 2; mt++)
                #pragma unroll
                for (int nt = 0; nt < 4; nt++)
                    mma16(acc[mt * 4 + nt], a[mt], b[nt]);
        }

        // stage partial z per k-half: kh=0 -> fp32 z0, kh=1 -> fp16 z1
        #pragma unroll
        for (int u = 0; u < 8; u++) {
            int mt = u >> 2, nt = u & 3;
            int row = wm0 + mt * 16 + gid, col = wn0 + nt * 8 + tig * 2;
            if (kh == 0) {
                *(float2*)&zs0[row * PZ + col]       = make_float2(acc[u][0], acc[u][1]);
                *(float2*)&zs0[(row + 8) * PZ + col] = make_float2(acc[u][2], acc[u][3]);
            } else {
                *(__half2*)&zs1[row * PZ1 + col]       = __floats2half2_rn(acc[u][0], acc[u][1]);
                *(__half2*)&zs1[(row + 8) * PZ1 + col] = __floats2half2_rn(acc[u][2], acc[u][3]);
            }
        }
        __syncthreads();

        // gate math: 4 cells per thread
        {
            const float* z0 = &zs0[rr * PZ];
            const __half* z1 = &zs1[rr * PZ1];
            float zxa[4][4];
            #pragma unroll
            for (int g = 0; g < 4; g++) {
                __half2* zh = (__half2*)&zxu[g];
                float2 lo = __half22float2(zh[0]);
                float2 hi = __half22float2(zh[1]);
                zxa[g][0] = lo.x; zxa[g][1] = lo.y; zxa[g][2] = hi.x; zxa[g][3] = hi.y;
            }
            __half hv[4];
            #pragma unroll
            for (int j = 0; j < 4; j++) {
                float zg = z0[hq + j]      + __half2float(z1[hq + j])      + zxa[0][j];
                float zi = z0[16 + hq + j] + __half2float(z1[16 + hq + j]) + zxa[1][j];
                float zf = z0[32 + hq + j] + __half2float(z1[32 + hq + j]) + zxa[2][j];
                float zo = z0[48 + hq + j] + __half2float(z1[48 + hq + j]) + zxa[3][j];
                float gg = tanha(zg);
                float ii = sigf(zi);
                float ff = sigf(zf);
                float oo = sigf(zo);
                float cn = __fmaf_rn(gg, ii, cr[j] * ff);
                cr[j] = cn;
                hv[j] = __float2half_rn(tanha(cn) * oo);
            }
            *(uint2*)(hseq + (size_t)(t + 1) * Bsz * Hsz + (size_t)(m0 + rr) * Hsz + h0 + hq)
                = *(uint2*)hv;
        }

        if (PRODUCE || t < Tt - 1) {
            // prefetch Zx[t+1] (overlaps barrier)
            if (t < Tt - 1) {
                const __half* zxp = Zx + (size_t)(t + 1) * Bsz * NG + (size_t)(m0 + rr) * NG + h0 + hq;
                #pragma unroll
                for (int g = 0; g < 4; g++) zxu[g] = __ldcs((const uint2*)(zxp + g * Hsz));
            }
            __syncthreads();
            if (tid == 0) bar_arrive(&bar[grp]);

            // producer: Zx2 block t-1 from the staged A tile (fills the barrier window)
            if (PRODUCE && t >= 1) produce(t - 1);

            __syncthreads();
            if (tid == 0) bar_spin(&bar[grp], 32u * (unsigned)(t + 1));
            __syncthreads();
        }
    }

    // PRODUCE tail: Zx2 block Tt-1 from h slot Tt
    if (PRODUCE) {
        const __half* hp = hseq + (size_t)Tt * Bsz * Hsz + (size_t)m0 * Hsz;
        #pragma unroll
        for (int i = 0; i < 16; i++) {
            int f4 = tid + i * 256;
            int row = f4 >> 6, u = f4 & 63;
            cp16(sb + OFF_AS + row * 1040 + u * 16, hp + (size_t)row * Hsz + u * 8);
        }
        CP_COMMIT();
        CP_WAIT(0);
        __syncthreads();
        produce(Tt - 1);
    }
}

// ---------------- final projection ----------------
__global__ void proj_kernel(const __half* __restrict__ h2,
                            const float* __restrict__ Wph,
                            const float* __restrict__ bp,
                            float* __restrict__ out) {
    int idx = blockIdx.x * blockDim.x + threadIdx.x;
    if (idx >= Bsz * Csz) return;
    int b = idx / Csz, cc = idx % Csz;
    float s = bp[cc];
    for (int k = 0; k < Hsz; k++)
        s += __half2float(h2[(size_t)b * Hsz + k]) * Wph[(size_t)k * Csz + cc];
    out[idx] = s;
}

// ---------------- launch ----------------
extern "C" void kernel_launch(void* const* d_in, const int* in_sizes, int n_in,
                              void* d_out, int out_size) {
    const float* x   = (const float*)d_in[0];
    const float* Wx1 = (const float*)d_in[1];
    const float* Wh1 = (const float*)d_in[2];
    const float* b1  = (const float*)d_in[3];
    const float* Wx2 = (const float*)d_in[4];
    const float* Wh2 = (const float*)d_in[5];
    const float* b2  = (const float*)d_in[6];
    const float* Wph = (const float*)d_in[7];
    const float* bp  = (const float*)d_in[8];
    float* out = (float*)d_out;

    __half *Zx1, *Zx2, *h1, *h2, *xT, *W1T, *W2T;
    unsigned* bar;
    cudaGetSymbolAddress((void**)&Zx1, g_Zx1);
    cudaGetSymbolAddress((void**)&Zx2, g_Zx2);
    cudaGetSymbolAddress((void**)&h1,  g_h1);
    cudaGetSymbolAddress((void**)&h2,  g_h2);
    cudaGetSymbolAddress((void**)&xT,  g_xT);
    cudaGetSymbolAddress((void**)&W1T, g_W1T);
    cudaGetSymbolAddress((void**)&W2T, g_W2T);
    cudaGetSymbolAddress((void**)&bar, g_bar);

    cudaFuncSetAttribute(lstm_layer<true>,  cudaFuncAttributeMaxDynamicSharedMemorySize, PSM_P);
    cudaFuncSetAttribute(lstm_layer<false>, cudaFuncAttributeMaxDynamicSharedMemorySize, PSM_NP);
    cudaFuncSetAttribute(gemm_h2, cudaFuncAttributeMaxDynamicSharedMemorySize, GSM);

    init_kernel<<<(Bsz * Hsz + 255) / 256, 256>>>();

    prep_x<<<(Tt * Bsz * 16 + 255) / 256, 256>>>(x, xT);
    prep_w<<<(4 * Hsz * (Isz / 2) + 255) / 256, 256>>>(Wx1, W1T, Isz);
    prep_w<<<(4 * Hsz * (Hsz / 2) + 255) / 256, 256>>>(Wx2, W2T, Hsz);

    // Phase 1: Zx1 = x @ Wx1 + b1
    gemm_h2<<<dim3(NG / 128, (Tt * Bsz) / 128), 256, GSM>>>(xT, W1T, b1, Zx1, Isz);

    // Phase 2: layer-1 recurrence + Zx2 production in barrier windows
    lstm_layer<true><<<dim3(Hsz / 16, Bsz / 64), 256, PSM_P>>>(
        Zx1, Wh1, h1, bar + 0, W2T, b2, Zx2);

    // Phase 3: layer-2 recurrence
    lstm_layer<false><<<dim3(Hsz / 16, Bsz / 64), 256, PSM_NP>>>(
        Zx2, Wh2, h2, bar + 4, nullptr, nullptr, nullptr);

    // Phase 4: projection
    proj_kernel<<<(Bsz * Csz + 255) / 256, 256>>>(
        h2 + (size_t)Tt * Bsz * Hsz, Wph, bp, out);
}

// round 12
// speedup vs baseline: 8.4250x; 1.0147x over previous
#include <cuda_runtime.h>
#include <cuda_fp16.h>
#include <math.h>
#include <stdint.h>

#define Bsz 256
#define Tt  256
#define Isz 128
#define Hsz 512
#define Csz 10
#define NG  2048   // 4*H

// step-kernel smem (bytes); pitch 1040B (== 16 mod 128 -> conflict-free ldsm)
#define PAH    520
#define PWH    520
#define PZ     68    // z0 pitch (floats)
#define PZ1    68    // z1 pitch (halves)
#define OFF_AS 66560                 // after Ws (64*1040)
#define OFF_Z0 (OFF_AS + 66560)      // 133120
#define OFF_Z1 (OFF_Z0 + 64 * PZ * 4)        // 150528
#define OFF_WX (OFF_Z1 + 64 * PZ1 * 2)       // 159232
#define PSM_P  (OFF_WX + 66560)      // 225792 (with Wx slice)
#define PSM_NP OFF_WX                // 159232 (layer 2)

// gemm: 3 buffers, each A(128x144B) + B(128x144B)
#define GBUF 36864
#define GSM  (3 * GBUF)

// ---------------- scratch ----------------
__device__ __half g_Zx1[(size_t)Tt * Bsz * NG];
__device__ __half g_Zx2[(size_t)Tt * Bsz * NG];
__device__ __half g_h1[(size_t)(Tt + 1) * Bsz * Hsz];
__device__ __half g_h2[(size_t)(Tt + 1) * Bsz * Hsz];
__device__ __half g_xT[(size_t)Tt * Bsz * Isz];
__device__ __half g_W1T[(size_t)4 * Hsz * Isz];
__device__ __half g_W2T[(size_t)4 * Hsz * Hsz];
__device__ unsigned g_bar[8];

// ---------------- helpers ----------------
__device__ __forceinline__ void mma16(float* c, const uint32_t* a, const uint32_t* b) {
    asm volatile(
        "mma.sync.aligned.m16n8k16.row.col.f32.f16.f16.f32 "
        "{%0,%1,%2,%3},{%4,%5,%6,%7},{%8,%9},{%0,%1,%2,%3};"
        : "+f"(c[0]), "+f"(c[1]), "+f"(c[2]), "+f"(c[3])
        : "r"(a[0]), "r"(a[1]), "r"(a[2]), "r"(a[3]), "r"(b[0]), "r"(b[1]));
}
__device__ __forceinline__ void ldsm4(uint32_t* r, uint32_t addr) {
    asm volatile("ldmatrix.sync.aligned.m8n8.x4.shared.b16 {%0,%1,%2,%3}, [%4];"
        : "=r"(r[0]), "=r"(r[1]), "=r"(r[2]), "=r"(r[3]) : "r"(addr));
}
__device__ __forceinline__ void ldsm2(uint32_t* r, uint32_t addr) {
    asm volatile("ldmatrix.sync.aligned.m8n8.x2.shared.b16 {%0,%1}, [%2];"
        : "=r"(r[0]), "=r"(r[1]) : "r"(addr));
}
__device__ __forceinline__ float tanha(float x) {
    float y;
    asm("tanh.approx.f32 %0, %1;" : "=f"(y) : "f"(x));
    return y;
}
__device__ __forceinline__ float sigf(float x) {
    return __fmaf_rn(0.5f, tanha(0.5f * x), 0.5f);
}
__device__ __forceinline__ uint32_t smem_u32(const void* p) {
    uint32_t a;
    asm("{ .reg .u64 t; cvta.to.shared.u64 t, %1; cvt.u32.u64 %0, t; }" : "=r"(a) : "l"(p));
    return a;
}
__device__ __forceinline__ void cp16(uint32_t dst, const void* src) {
    asm volatile("cp.async.ca.shared.global [%0], [%1], 16;" :: "r"(dst), "l"(src));
}
#define CP_COMMIT() asm volatile("cp.async.commit_group;" ::: "memory")
#define CP_WAIT(n)  asm volatile("cp.async.wait_group %0;" :: "n"(n) : "memory")

__device__ __forceinline__ void bar_arrive(unsigned* p) {
    asm volatile("red.release.gpu.global.add.u32 [%0], %1;" :: "l"(p), "r"(1u) : "memory");
}
__device__ __forceinline__ void bar_spin(unsigned* p, unsigned tgt) {
    unsigned v;
    do {
        asm volatile("ld.acquire.gpu.global.u32 %0, [%1];" : "=r"(v) : "l"(p) : "memory");
    } while (v < tgt);
}

// ---------------- init ----------------
__global__ void init_kernel() {
    int i = blockIdx.x * blockDim.x + threadIdx.x;
    if (i < Bsz * Hsz) {
        g_h1[i] = __float2half(0.f);
        g_h2[i] = __float2half(0.f);
    }
    if (i < 8) g_bar[i] = 0u;
}

// ---------------- prep: x [b][t][k] fp32 -> xT [t][b][k] fp16 ----------------
__global__ void prep_x(const float* __restrict__ x, __half* __restrict__ xT) {
    int idx = blockIdx.x * blockDim.x + threadIdx.x;
    if (idx >= Tt * Bsz * 16) return;
    int q = idx & 15;
    int b = (idx >> 4) & (Bsz - 1);
    int t = idx >> 12;
    const float* src = x + ((size_t)b * Tt + t) * Isz + q * 8;
    float4 v0 = *(const float4*)src;
    float4 v1 = *(const float4*)(src + 4);
    __half2 h0 = __floats2half2_rn(v0.x, v0.y);
    __half2 h1 = __floats2half2_rn(v0.z, v0.w);
    __half2 h2 = __floats2half2_rn(v1.x, v1.y);
    __half2 h3 = __floats2half2_rn(v1.z, v1.w);
    uint4 u;
    u.x = *(uint32_t*)&h0; u.y = *(uint32_t*)&h1;
    u.z = *(uint32_t*)&h2; u.w = *(uint32_t*)&h3;
    *(uint4*)(xT + ((size_t)t * Bsz + b) * Isz + q * 8) = u;
}

// ---------------- prep: W[g][k][h] fp32 -> WT[g][h][k] fp16 ----------------
__global__ void prep_w(const float* __restrict__ W, __half* __restrict__ WT, int K) {
    int idx = blockIdx.x * blockDim.x + threadIdx.x;
    int kp = idx % (K / 2);
    int rest = idx / (K / 2);
    int h = rest % Hsz, g = rest / Hsz;
    if (g >= 4) return;
    int k = kp * 2;
    float a = W[((size_t)g * K + k) * Hsz + h];
    float b = W[((size_t)g * K + k + 1) * Hsz + h];
    *(__half2*)(WT + ((size_t)g * Hsz + h) * K + k) = __floats2half2_rn(a, b);
}

// ---------------- big GEMM: fp16 in/out, cp.async 3-stage, 128x128 tile ----------------
__global__ void __launch_bounds__(256)
gemm_h2(const __half* __restrict__ A,
        const __half* __restrict__ WT,
        const float* __restrict__ bias,
        __half* __restrict__ Z,
        int K) {
    extern __shared__ __align__(16) unsigned char smg[];
    const uint32_t sb = smem_u32(smg);

    const int m0 = blockIdx.y * 128, n0 = blockIdx.x * 128;
    const int gate = n0 >> 9, h0 = n0 & 511;
    const __half* Bg = WT + ((size_t)gate * Hsz + h0) * K;
    const int tid = threadIdx.x, lane = tid & 31, wid = tid >> 5;
    const int gid = lane >> 2, tig = lane & 3;
    const int wm0 = (wid & 1) * 64, wn0 = (wid >> 1) * 32;
    const int l7 = lane & 7, l8 = (lane >> 3) & 1, l16 = lane >> 4;

    uint32_t araw[4], braw[4];
    #pragma unroll
    for (int mt = 0; mt < 4; mt++)
        araw[mt] = (uint32_t)((wm0 + mt * 16 + l7 + l8 * 8) * 144 + l16 * 16);
    #pragma unroll
    for (int nt = 0; nt < 4; nt++)
        braw[nt] = (uint32_t)(18432 + (wn0 + nt * 8 + l7) * 144 + l8 * 16);

    auto stage = [&](int buf, int kk) {
        uint32_t base = sb + buf * GBUF;
        #pragma unroll
        for (int i = 0; i < 4; i++) {
            int idx = tid + i * 256; int r = idx >> 3, q = idx & 7;
            cp16(base + r * 144 + q * 16, A + (size_t)(m0 + r) * K + kk + q * 8);
        }
        #pragma unroll
        for (int i = 0; i < 4; i++) {
            int idx = tid + i * 256; int r = idx >> 3, q = idx & 7;
            cp16(base + 18432 + r * 144 + q * 16, Bg + (size_t)r * K + kk + q * 8);
        }
        CP_COMMIT();
    };

    const int NC = K / 64;
    stage(0, 0);
    if (NC > 1) stage(1, 64);
    float acc[16][4] = {};

    #pragma unroll 1
    for (int ch = 0; ch < NC; ch++) {
        if (ch + 2 < NC) {
            stage((ch + 2) % 3, (ch + 2) * 64);
            CP_WAIT(2);
        } else if (ch + 1 < NC) {
            CP_WAIT(1);
        } else {
            CP_WAIT(0);
        }
        __syncthreads();
        uint32_t bufb = sb + (ch % 3) * GBUF;
        #pragma unroll
        for (int s = 0; s < 4; s++) {
            uint32_t a[4][4], b[4][2];
            #pragma unroll
            for (int mt = 0; mt < 4; mt++) ldsm4(a[mt], bufb + araw[mt] + s * 32);
            #pragma unroll
            for (int nt = 0; nt < 4; nt++) ldsm2(b[nt], bufb + braw[nt] + s * 32);
            #pragma unroll
            for (int mt = 0; mt < 4; mt++)
                #pragma unroll
                for (int nt = 0; nt < 4; nt++)
                    mma16(acc[mt * 4 + nt], a[mt], b[nt]);
        }
        __syncthreads();
    }

    #pragma unroll
    for (int u = 0; u < 16; u++) {
        int mt = u >> 2, nt = u & 3;
        int row = m0 + wm0 + mt * 16 + gid;
        int col = n0 + wn0 + nt * 8 + tig * 2;
        float b0 = bias[col], b1 = bias[col + 1];
        *(__half2*)&Z[(size_t)row * NG + col] =
            __floats2half2_rn(acc[u][0] + b0, acc[u][1] + b1);
        *(__half2*)&Z[(size_t)(row + 8) * NG + col] =
            __floats2half2_rn(acc[u][2] + b0, acc[u][3] + b1);
    }
}

// ---------------- persistent recurrent layer ----------------
// Grid (32, 4) = 128 CTAs, 256 threads. CTA: batch block 64 x (4 gates x 16 h).
// Wh B-fragments are REGISTER-RESIDENT across all 256 steps (loaded once via ldsm;
// removes 64 ldsm2/warp/step and halves per-step SMEM crossbar traffic).
// PRODUCE: also computes Zx2 block t-1 (full-K warp tiling) in the barrier window.
template <bool PRODUCE>
__global__ void __launch_bounds__(256, 1)
lstm_layer(const __half* __restrict__ Zx,    // [T, B, 4H] fp16
           const float* __restrict__ Wh,     // [4, H, H] fp32
           __half* __restrict__ hseq,        // [(T+1), B, H] fp16, slot 0 zeroed
           unsigned* __restrict__ bar,
           const __half* __restrict__ WxT,   // [4, H, 512] fp16 (PRODUCE only)
           const float* __restrict__ bias2,  // [4*H] (PRODUCE only)
           __half* __restrict__ Zxout) {     // [T, B, 4H] fp16 (PRODUCE only)
    extern __shared__ __align__(16) unsigned char smraw[];
    const uint32_t sb = smem_u32(smraw);
    __half* Ws = (__half*)smraw;
    float*  zs0 = (float*)(smraw + OFF_Z0);
    __half* zs1 = (__half*)(smraw + OFF_Z1);

    const int h0 = blockIdx.x * 16;
    const int m0 = blockIdx.y * 64;
    const int tid = threadIdx.x, lane = tid & 31, wid = tid >> 5;
    const int gid = lane >> 2, tig = lane & 3;
    const int wm0 = (wid & 1) * 32, wn0 = ((wid >> 1) & 1) * 32;
    const int kh  = wid >> 2;
    const int l7 = lane & 7, l8 = (lane >> 3) & 1, l16 = lane >> 4;

    // ---- one-time: Wh slice -> SMEM, n-major fp16 ----
    #pragma unroll 4
    for (int i = 0; i < 32; i++) {
        int f4 = tid + i * 256;
        int k = f4 >> 4, rem = f4 & 15, g = rem >> 2, q = rem & 3;
        float4 v = *(const float4*)(Wh + ((size_t)g * Hsz + k) * Hsz + h0 + q * 4);
        int nb = g * 16 + q * 4;
        Ws[(nb + 0) * PWH + k] = __float2half_rn(v.x);
        Ws[(nb + 1) * PWH + k] = __float2half_rn(v.y);
        Ws[(nb + 2) * PWH + k] = __float2half_rn(v.z);
        Ws[(nb + 3) * PWH + k] = __float2half_rn(v.w);
    }
    // ---- one-time: Wx2 slice -> SMEM (PRODUCE) ----
    if (PRODUCE) {
        #pragma unroll
        for (int i = 0; i < 16; i++) {
            int idx = tid + i * 256;
            int n = idx >> 6, q = idx & 63;
            int g = n >> 4, hh = n & 15;
            cp16(sb + OFF_WX + n * 1040 + q * 16,
                 WxT + ((size_t)g * Hsz + h0 + hh) * 512 + q * 8);
        }
        CP_COMMIT();
        CP_WAIT(0);
    }
    __syncthreads();

    // ---- one-time: load Wh B-fragments into registers (split-K half of this warp) ----
    uint32_t breg[4][16][2];
    {
        #pragma unroll
        for (int nt = 0; nt < 4; nt++) {
            uint32_t base = sb + (wn0 + nt * 8 + l7) * 1040 + l8 * 16 + kh * 512;
            #pragma unroll
            for (int ks = 0; ks < 16; ks++)
                ldsm2(breg[nt][ks], base + ks * 32);
        }
    }

    // t-invariant ldmatrix A addresses (bytes)
    uint32_t abase[2];
    #pragma unroll
    for (int mt = 0; mt < 2; mt++)
        abase[mt] = sb + OFF_AS + (wm0 + mt * 16 + l7 + l8 * 8) * 1040 + l16 * 16 + kh * 512;

    // producer addresses — FULL-K tiling
    const int wn0p = (wid >> 1) * 16;
    uint32_t pabase[2], pxbase[2];
    int gc2[2];
    float2 bsv2[2];
    if (PRODUCE) {
        #pragma unroll
        for (int mt = 0; mt < 2; mt++)
            pabase[mt] = sb + OFF_AS + (wm0 + mt * 16 + l7 + l8 * 8) * 1040 + l16 * 16;
        #pragma unroll
        for (int nt = 0; nt < 2; nt++) {
            pxbase[nt] = sb + OFF_WX + (wn0p + nt * 8 + l7) * 1040 + l8 * 16;
            int n = wn0p + nt * 8 + tig * 2;
            int g = n >> 4, hh = n & 15;
            gc2[nt] = g * Hsz + h0 + hh;
            bsv2[nt] = make_float2(bias2[gc2[nt]], bias2[gc2[nt] + 1]);
        }
    }

    const int rr = tid >> 2;
    const int hq = (tid & 3) * 4;
    const unsigned grp = blockIdx.y;

    float cr[4] = {0.f, 0.f, 0.f, 0.f};

    // prefetch Zx[0]
    uint2 zxu[4];
    {
        const __half* zxp = Zx + (size_t)(m0 + rr) * NG + h0 + hq;
        #pragma unroll
        for (int g = 0; g < 4; g++) zxu[g] = __ldcs((const uint2*)(zxp + g * Hsz));
    }

    // full-K producer (A tile currently staged in As)
    auto produce = [&](int tdst) {
        float za[4][4] = {};
        #pragma unroll 8
        for (int ks = 0; ks < 32; ks++) {
            uint32_t a[2][4], b[2][2];
            ldsm4(a[0], pabase[0] + ks * 32);
            ldsm4(a[1], pabase[1] + ks * 32);
            ldsm2(b[0], pxbase[0] + ks * 32);
            ldsm2(b[1], pxbase[1] + ks * 32);
            mma16(za[0], a[0], b[0]); mma16(za[1], a[0], b[1]);
            mma16(za[2], a[1], b[0]); mma16(za[3], a[1], b[1]);
        }
        __half* zb = Zxout + ((size_t)tdst * Bsz + m0) * NG;
        #pragma unroll
        for (int u = 0; u < 4; u++) {
            int mt = u >> 1, nt = u & 1;
            int row = wm0 + mt * 16 + gid;
            *(__half2*)&zb[(size_t)row * NG + gc2[nt]] =
                __floats2half2_rn(za[u][0] + bsv2[nt].x, za[u][1] + bsv2[nt].y);
            *(__half2*)&zb[(size_t)(row + 8) * NG + gc2[nt]] =
                __floats2half2_rn(za[u][2] + bsv2[nt].x, za[u][3] + bsv2[nt].y);
        }
    };

    for (int t = 0; t < Tt; t++) {
        // stage h tile (64 x 512 fp16) via cp.async
        const __half* hp = hseq + (size_t)t * Bsz * Hsz + (size_t)m0 * Hsz;
        #pragma unroll
        for (int i = 0; i < 16; i++) {
            int f4 = tid + i * 256;
            int row = f4 >> 6, u = f4 & 63;
            cp16(sb + OFF_AS + row * 1040 + u * 16, hp + (size_t)row * Hsz + u * 8);
        }
        CP_COMMIT();
        CP_WAIT(0);
        __syncthreads();

        // recurrent mma (split-K over warps; B from registers)
        float acc[8][4] = {};
        #pragma unroll
        for (int ks = 0; ks < 16; ks++) {
            uint32_t a[2][4];
            ldsm4(a[0], abase[0] + ks * 32);
            ldsm4(a[1], abase[1] + ks * 32);
            #pragma unroll
            for (int mt = 0; mt < 2; mt++)
                #pragma unroll
                for (int nt = 0; nt < 4; nt++)
                    mma16(acc[mt * 4 + nt], a[mt], breg[nt][ks]);
        }

        // stage partial z per k-half: kh=0 -> fp32 z0, kh=1 -> fp16 z1
        #pragma unroll
        for (int u = 0; u < 8; u++) {
            int mt = u >> 2, nt = u & 3;
            int row = wm0 + mt * 16 + gid, col = wn0 + nt * 8 + tig * 2;
            if (kh == 0) {
                *(float2*)&zs0[row * PZ + col]       = make_float2(acc[u][0], acc[u][1]);
                *(float2*)&zs0[(row + 8) * PZ + col] = make_float2(acc[u][2], acc[u][3]);
            } else {
                *(__half2*)&zs1[row * PZ1 + col]       = __floats2half2_rn(acc[u][0], acc[u][1]);
                *(__half2*)&zs1[(row + 8) * PZ1 + col] = __floats2half2_rn(acc[u][2], acc[u][3]);
            }
        }
        __syncthreads();

        // gate math: 4 cells per thread
        {
            const float* z0 = &zs0[rr * PZ];
            const __half* z1 = &zs1[rr * PZ1];
            float zxa[4][4];
            #pragma unroll
            for (int g = 0; g < 4; g++) {
                __half2* zh = (__half2*)&zxu[g];
                float2 lo = __half22float2(zh[0]);
                float2 hi = __half22float2(zh[1]);
                zxa[g][0] = lo.x; zxa[g][1] = lo.y; zxa[g][2] = hi.x; zxa[g][3] = hi.y;
            }
            __half hv[4];
            #pragma unroll
            for (int j = 0; j < 4; j++) {
                float zg = z0[hq + j]      + __half2float(z1[hq + j])      + zxa[0][j];
                float zi = z0[16 + hq + j] + __half2float(z1[16 + hq + j]) + zxa[1][j];
                float zf = z0[32 + hq + j] + __half2float(z1[32 + hq + j]) + zxa[2][j];
                float zo = z0[48 + hq + j] + __half2float(z1[48 + hq + j]) + zxa[3][j];
                float gg = tanha(zg);
                float ii = sigf(zi);
                float ff = sigf(zf);
                float oo = sigf(zo);
                float cn = __fmaf_rn(gg, ii, cr[j] * ff);
                cr[j] = cn;
                hv[j] = __float2half_rn(tanha(cn) * oo);
            }
            *(uint2*)(hseq + (size_t)(t + 1) * Bsz * Hsz + (size_t)(m0 + rr) * Hsz + h0 + hq)
                = *(uint2*)hv;
        }

        if (PRODUCE || t < Tt - 1) {
            // prefetch Zx[t+1] (overlaps barrier)
            if (t < Tt - 1) {
                const __half* zxp = Zx + (size_t)(t + 1) * Bsz * NG + (size_t)(m0 + rr) * NG + h0 + hq;
                #pragma unroll
                for (int g = 0; g < 4; g++) zxu[g] = __ldcs((const uint2*)(zxp + g * Hsz));
            }
            __syncthreads();
            if (tid == 0) bar_arrive(&bar[grp]);

            // producer: Zx2 block t-1 (fills the barrier window)
            if (PRODUCE && t >= 1) produce(t - 1);

            __syncthreads();
            if (tid == 0) bar_spin(&bar[grp], 32u * (unsigned)(t + 1));
            __syncthreads();
        }
    }

    // PRODUCE tail: Zx2 block Tt-1 from h slot Tt
    if (PRODUCE) {
        const __half* hp = hseq + (size_t)Tt * Bsz * Hsz + (size_t)m0 * Hsz;
        #pragma unroll
        for (int i = 0; i < 16; i++) {
            int f4 = tid + i * 256;
            int row = f4 >> 6, u = f4 & 63;
            cp16(sb + OFF_AS + row * 1040 + u * 16, hp + (size_t)row * Hsz + u * 8);
        }
        CP_COMMIT();
        CP_WAIT(0);
        __syncthreads();
        produce(Tt - 1);
    }
}

// ---------------- final projection ----------------
__global__ void proj_kernel(const __half* __restrict__ h2,
                            const float* __restrict__ Wph,
                            const float* __restrict__ bp,
                            float* __restrict__ out) {
    int idx = blockIdx.x * blockDim.x + threadIdx.x;
    if (idx >= Bsz * Csz) return;
    int b = idx / Csz, cc = idx % Csz;
    float s = bp[cc];
    for (int k = 0; k < Hsz; k++)
        s += __half2float(h2[(size_t)b * Hsz + k]) * Wph[(size_t)k * Csz + cc];
    out[idx] = s;
}

// ---------------- launch ----------------
extern "C" void kernel_launch(void* const* d_in, const int* in_sizes, int n_in,
                              void* d_out, int out_size) {
    const float* x   = (const float*)d_in[0];
    const float* Wx1 = (const float*)d_in[1];
    const float* Wh1 = (const float*)d_in[2];
    const float* b1  = (const float*)d_in[3];
    const float* Wx2 = (const float*)d_in[4];
    const float* Wh2 = (const float*)d_in[5];
    const float* b2  = (const float*)d_in[6];
    const float* Wph = (const float*)d_in[7];
    const float* bp  = (const float*)d_in[8];
    float* out = (float*)d_out;

    __half *Zx1, *Zx2, *h1, *h2, *xT, *W1T, *W2T;
    unsigned* bar;
    cudaGetSymbolAddress((void**)&Zx1, g_Zx1);
    cudaGetSymbolAddress((void**)&Zx2, g_Zx2);
    cudaGetSymbolAddress((void**)&h1,  g_h1);
    cudaGetSymbolAddress((void**)&h2,  g_h2);
    cudaGetSymbolAddress((void**)&xT,  g_xT);
    cudaGetSymbolAddress((void**)&W1T, g_W1T);
    cudaGetSymbolAddress((void**)&W2T, g_W2T);
    cudaGetSymbolAddress((void**)&bar, g_bar);

    cudaFuncSetAttribute(lstm_layer<true>,  cudaFuncAttributeMaxDynamicSharedMemorySize, PSM_P);
    cudaFuncSetAttribute(lstm_layer<false>, cudaFuncAttributeMaxDynamicSharedMemorySize, PSM_NP);
    cudaFuncSetAttribute(gemm_h2, cudaFuncAttributeMaxDynamicSharedMemorySize, GSM);

    init_kernel<<<(Bsz * Hsz + 255) / 256, 256>>>();

    prep_x<<<(Tt * Bsz * 16 + 255) / 256, 256>>>(x, xT);
    prep_w<<<(4 * Hsz * (Isz / 2) + 255) / 256, 256>>>(Wx1, W1T, Isz);
    prep_w<<<(4 * Hsz * (Hsz / 2) + 255) / 256, 256>>>(Wx2, W2T, Hsz);

    // Phase 1: Zx1 = x @ Wx1 + b1
    gemm_h2<<<dim3(NG / 128, (Tt * Bsz) / 128), 256, GSM>>>(xT, W1T, b1, Zx1, Isz);

    // Phase 2: layer-1 recurrence + Zx2 production in barrier windows
    lstm_layer<true><<<dim3(Hsz / 16, Bsz / 64), 256, PSM_P>>>(
        Zx1, Wh1, h1, bar + 0, W2T, b2, Zx2);

    // Phase 3: layer-2 recurrence
    lstm_layer<false><<<dim3(Hsz / 16, Bsz / 64), 256, PSM_NP>>>(
        Zx2, Wh2, h2, bar + 4, nullptr, nullptr, nullptr);

    // Phase 4: projection
    proj_kernel<<<(Bsz * Csz + 255) / 256, 256>>>(
        h2 + (size_t)Tt * Bsz * Hsz, Wph, bp, out);
}

// round 13
// speedup vs baseline: 8.9002x; 1.0564x over previous
#include <cuda_runtime.h>
#include <cuda_fp16.h>
#include <math.h>
#include <stdint.h>

#define Bsz 256
#define Tt  256
#define Isz 128
#define Hsz 512
#define Csz 10
#define NG  2048   // 4*H

// fused-kernel smem (bytes); pitch 1040B (== 16 mod 128 -> conflict-free ldsm)
#define PZ     68    // z0 pitch (floats)
#define PZ1    68    // z1 pitch (halves)
#define OFF_AS 66560                          // A buffer (after Wh2s 64*1040)
#define OFF_Z0 (OFF_AS + 66560)               // 133120
#define OFF_Z1 (OFF_Z0 + 64 * PZ * 4)         // 150528
#define OFF_WX (OFF_Z1 + 64 * PZ1 * 2)        // 159232
#define PSM    (OFF_WX + 66560)               // 225792

// gemm: 3 buffers, each A(128x144B) + B(128x144B)
#define GBUF 36864
#define GSM  (3 * GBUF)

// ---------------- scratch ----------------
__device__ __half g_Zx1[(size_t)Tt * Bsz * NG];
__device__ __half g_Zx2[(size_t)Tt * Bsz * NG];
__device__ __half g_h1[(size_t)(Tt + 1) * Bsz * Hsz];
__device__ __half g_h2[(size_t)(Tt + 1) * Bsz * Hsz];
__device__ __half g_xT[(size_t)Tt * Bsz * Isz];
__device__ __half g_W1T[(size_t)4 * Hsz * Isz];
__device__ __half g_W2T[(size_t)4 * Hsz * Hsz];
__device__ unsigned g_bar[8];

// ---------------- helpers ----------------
__device__ __forceinline__ void mma16(float* c, const uint32_t* a, const uint32_t* b) {
    asm volatile(
        "mma.sync.aligned.m16n8k16.row.col.f32.f16.f16.f32 "
        "{%0,%1,%2,%3},{%4,%5,%6,%7},{%8,%9},{%0,%1,%2,%3};"
        : "+f"(c[0]), "+f"(c[1]), "+f"(c[2]), "+f"(c[3])
        : "r"(a[0]), "r"(a[1]), "r"(a[2]), "r"(a[3]), "r"(b[0]), "r"(b[1]));
}
__device__ __forceinline__ void ldsm4(uint32_t* r, uint32_t addr) {
    asm volatile("ldmatrix.sync.aligned.m8n8.x4.shared.b16 {%0,%1,%2,%3}, [%4];"
        : "=r"(r[0]), "=r"(r[1]), "=r"(r[2]), "=r"(r[3]) : "r"(addr));
}
__device__ __forceinline__ void ldsm2(uint32_t* r, uint32_t addr) {
    asm volatile("ldmatrix.sync.aligned.m8n8.x2.shared.b16 {%0,%1}, [%2];"
        : "=r"(r[0]), "=r"(r[1]) : "r"(addr));
}
__device__ __forceinline__ float tanha(float x) {
    float y;
    asm("tanh.approx.f32 %0, %1;" : "=f"(y) : "f"(x));
    return y;
}
__device__ __forceinline__ float sigf(float x) {
    return __fmaf_rn(0.5f, tanha(0.5f * x), 0.5f);
}
__device__ __forceinline__ uint32_t smem_u32(const void* p) {
    uint32_t a;
    asm("{ .reg .u64 t; cvta.to.shared.u64 t, %1; cvt.u32.u64 %0, t; }" : "=r"(a) : "l"(p));
    return a;
}
__device__ __forceinline__ void cp16(uint32_t dst, const void* src) {
    asm volatile("cp.async.ca.shared.global [%0], [%1], 16;" :: "r"(dst), "l"(src));
}
#define CP_COMMIT() asm volatile("cp.async.commit_group;" ::: "memory")
#define CP_WAIT(n)  asm volatile("cp.async.wait_group %0;" :: "n"(n) : "memory")

__device__ __forceinline__ void bar_arrive(unsigned* p) {
    asm volatile("red.release.gpu.global.add.u32 [%0], %1;" :: "l"(p), "r"(1u) : "memory");
}
__device__ __forceinline__ void bar_spin(unsigned* p, unsigned tgt) {
    unsigned v;
    do {
        asm volatile("ld.acquire.gpu.global.u32 %0, [%1];" : "=r"(v) : "l"(p) : "memory");
    } while (v < tgt);
}

// ---------------- init ----------------
__global__ void init_kernel() {
    int i = blockIdx.x * blockDim.x + threadIdx.x;
    if (i < Bsz * Hsz) {
        g_h1[i] = __float2half(0.f);
        g_h2[i] = __float2half(0.f);
    }
    if (i < 8) g_bar[i] = 0u;
}

// ---------------- prep: x [b][t][k] fp32 -> xT [t][b][k] fp16 ----------------
__global__ void prep_x(const float* __restrict__ x, __half* __restrict__ xT) {
    int idx = blockIdx.x * blockDim.x + threadIdx.x;
    if (idx >= Tt * Bsz * 16) return;
    int q = idx & 15;
    int b = (idx >> 4) & (Bsz - 1);
    int t = idx >> 12;
    const float* src = x + ((size_t)b * Tt + t) * Isz + q * 8;
    float4 v0 = *(const float4*)src;
    float4 v1 = *(const float4*)(src + 4);
    __half2 h0 = __floats2half2_rn(v0.x, v0.y);
    __half2 h1 = __floats2half2_rn(v0.z, v0.w);
    __half2 h2 = __floats2half2_rn(v1.x, v1.y);
    __half2 h3 = __floats2half2_rn(v1.z, v1.w);
    uint4 u;
    u.x = *(uint32_t*)&h0; u.y = *(uint32_t*)&h1;
    u.z = *(uint32_t*)&h2; u.w = *(uint32_t*)&h3;
    *(uint4*)(xT + ((size_t)t * Bsz + b) * Isz + q * 8) = u;
}

// ---------------- prep: W[g][k][h] fp32 -> WT[g][h][k] fp16 ----------------
__global__ void prep_w(const float* __restrict__ W, __half* __restrict__ WT, int K) {
    int idx = blockIdx.x * blockDim.x + threadIdx.x;
    int kp = idx % (K / 2);
    int rest = idx / (K / 2);
    int h = rest % Hsz, g = rest / Hsz;
    if (g >= 4) return;
    int k = kp * 2;
    float a = W[((size_t)g * K + k) * Hsz + h];
    float b = W[((size_t)g * K + k + 1) * Hsz + h];
    *(__half2*)(WT + ((size_t)g * Hsz + h) * K + k) = __floats2half2_rn(a, b);
}

// ---------------- big GEMM (phase 1): fp16 in/out, cp.async 3-stage, 128x128 tile ----------------
__global__ void __launch_bounds__(256)
gemm_h2(const __half* __restrict__ A,
        const __half* __restrict__ WT,
        const float* __restrict__ bias,
        __half* __restrict__ Z,
        int K) {
    extern __shared__ __align__(16) unsigned char smg[];
    const uint32_t sb = smem_u32(smg);

    const int m0 = blockIdx.y * 128, n0 = blockIdx.x * 128;
    const int gate = n0 >> 9, h0 = n0 & 511;
    const __half* Bg = WT + ((size_t)gate * Hsz + h0) * K;
    const int tid = threadIdx.x, lane = tid & 31, wid = tid >> 5;
    const int gid = lane >> 2, tig = lane & 3;
    const int wm0 = (wid & 1) * 64, wn0 = (wid >> 1) * 32;
    const int l7 = lane & 7, l8 = (lane >> 3) & 1, l16 = lane >> 4;

    uint32_t araw[4], braw[4];
    #pragma unroll
    for (int mt = 0; mt < 4; mt++)
        araw[mt] = (uint32_t)((wm0 + mt * 16 + l7 + l8 * 8) * 144 + l16 * 16);
    #pragma unroll
    for (int nt = 0; nt < 4; nt++)
        braw[nt] = (uint32_t)(18432 + (wn0 + nt * 8 + l7) * 144 + l8 * 16);

    auto stage = [&](int buf, int kk) {
        uint32_t base = sb + buf * GBUF;
        #pragma unroll
        for (int i = 0; i < 4; i++) {
            int idx = tid + i * 256; int r = idx >> 3, q = idx & 7;
            cp16(base + r * 144 + q * 16, A + (size_t)(m0 + r) * K + kk + q * 8);
        }
        #pragma unroll
        for (int i = 0; i < 4; i++) {
            int idx = tid + i * 256; int r = idx >> 3, q = idx & 7;
            cp16(base + 18432 + r * 144 + q * 16, Bg + (size_t)r * K + kk + q * 8);
        }
        CP_COMMIT();
    };

    const int NC = K / 64;
    stage(0, 0);
    if (NC > 1) stage(1, 64);
    float acc[16][4] = {};

    #pragma unroll 1
    for (int ch = 0; ch < NC; ch++) {
        if (ch + 2 < NC) {
            stage((ch + 2) % 3, (ch + 2) * 64);
            CP_WAIT(2);
        } else if (ch + 1 < NC) {
            CP_WAIT(1);
        } else {
            CP_WAIT(0);
        }
        __syncthreads();
        uint32_t bufb = sb + (ch % 3) * GBUF;
        #pragma unroll
        for (int s = 0; s < 4; s++) {
            uint32_t a[4][4], b[4][2];
            #pragma unroll
            for (int mt = 0; mt < 4; mt++) ldsm4(a[mt], bufb + araw[mt] + s * 32);
            #pragma unroll
            for (int nt = 0; nt < 4; nt++) ldsm2(b[nt], bufb + braw[nt] + s * 32);
            #pragma unroll
            for (int mt = 0; mt < 4; mt++)
                #pragma unroll
                for (int nt = 0; nt < 4; nt++)
                    mma16(acc[mt * 4 + nt], a[mt], b[nt]);
        }
        __syncthreads();
    }

    #pragma unroll
    for (int u = 0; u < 16; u++) {
        int mt = u >> 2, nt = u & 3;
        int row = m0 + wm0 + mt * 16 + gid;
        int col = n0 + wn0 + nt * 8 + tig * 2;
        float b0 = bias[col], b1 = bias[col + 1];
        *(__half2*)&Z[(size_t)row * NG + col] =
            __floats2half2_rn(acc[u][0] + b0, acc[u][1] + b1);
        *(__half2*)&Z[(size_t)(row + 8) * NG + col] =
            __floats2half2_rn(acc[u][2] + b0, acc[u][3] + b1);
    }
}

// ---------------- fused persistent 2-layer recurrence ----------------
// Grid (32, 4) = 128 CTAs, 256 threads, 1 barrier per epoch, 258 epochs.
// Epoch e: layer1 step e (e<=255), produce Zx2(e-1) (1<=e<=256), layer2 step e-2 (e>=2).
// Wh1 B-frags register-resident; Wh2 in SMEM; Wx2 in SMEM; A buffer time-shared.
__global__ void __launch_bounds__(256, 1)
lstm_fused(const __half* __restrict__ Zx1,   // [T, B, 4H] fp16
           const float* __restrict__ Wh1,    // [4, H, H] fp32
           const float* __restrict__ Wh2,    // [4, H, H] fp32
           __half* __restrict__ h1s,         // [(T+1), B, H], slot 0 zeroed
           __half* __restrict__ h2s,         // [(T+1), B, H], slot 0 zeroed
           unsigned* __restrict__ bar,
           const __half* __restrict__ W2T,   // [4, H, 512] fp16
           const float* __restrict__ bias2,  // [4*H]
           __half* __restrict__ Zx2) {       // [T, B, 4H] fp16
    extern __shared__ __align__(16) unsigned char smraw[];
    const uint32_t sb = smem_u32(smraw);
    __half* Wh2s = (__half*)smraw;                 // [64 n][520 halves]
    float*  zs0 = (float*)(smraw + OFF_Z0);
    __half* zs1 = (__half*)(smraw + OFF_Z1);

    const int h0 = blockIdx.x * 16;
    const int m0 = blockIdx.y * 64;
    const int tid = threadIdx.x, lane = tid & 31, wid = tid >> 5;
    const int gid = lane >> 2, tig = lane & 3;
    const int wm0 = (wid & 1) * 32, wn0 = ((wid >> 1) & 1) * 32;
    const int kh  = wid >> 2;
    const int l7 = lane & 7, l8 = (lane >> 3) & 1, l16 = lane >> 4;
    const unsigned grp = blockIdx.y;

    // ---- init 1: Wh1 slice -> A region (n-major fp16), then ldsm into registers ----
    #pragma unroll 4
    for (int i = 0; i < 32; i++) {
        int f4 = tid + i * 256;
        int k = f4 >> 4, rem = f4 & 15, g = rem >> 2, q = rem & 3;
        float4 v = *(const float4*)(Wh1 + ((size_t)g * Hsz + k) * Hsz + h0 + q * 4);
        int nb = g * 16 + q * 4;
        __half* dst = (__half*)(smraw + OFF_AS);
        dst[(nb + 0) * 520 + k] = __float2half_rn(v.x);
        dst[(nb + 1) * 520 + k] = __float2half_rn(v.y);
        dst[(nb + 2) * 520 + k] = __float2half_rn(v.z);
        dst[(nb + 3) * 520 + k] = __float2half_rn(v.w);
    }
    __syncthreads();
    uint32_t breg[4][16][2];
    #pragma unroll
    for (int nt = 0; nt < 4; nt++) {
        uint32_t base = sb + OFF_AS + (wn0 + nt * 8 + l7) * 1040 + l8 * 16 + kh * 512;
        #pragma unroll
        for (int ks = 0; ks < 16; ks++)
            ldsm2(breg[nt][ks], base + ks * 32);
    }
    __syncthreads();

    // ---- init 2: Wh2 slice -> Wh2s (n-major fp16); Wx2 slice -> OFF_WX (cp.async) ----
    #pragma unroll 4
    for (int i = 0; i < 32; i++) {
        int f4 = tid + i * 256;
        int k = f4 >> 4, rem = f4 & 15, g = rem >> 2, q = rem & 3;
        float4 v = *(const float4*)(Wh2 + ((size_t)g * Hsz + k) * Hsz + h0 + q * 4);
        int nb = g * 16 + q * 4;
        Wh2s[(nb + 0) * 520 + k] = __float2half_rn(v.x);
        Wh2s[(nb + 1) * 520 + k] = __float2half_rn(v.y);
        Wh2s[(nb + 2) * 520 + k] = __float2half_rn(v.z);
        Wh2s[(nb + 3) * 520 + k] = __float2half_rn(v.w);
    }
    #pragma unroll
    for (int i = 0; i < 16; i++) {
        int idx = tid + i * 256;
        int n = idx >> 6, q = idx & 63;
        int g = n >> 4, hh = n & 15;
        cp16(sb + OFF_WX + n * 1040 + q * 16,
             W2T + ((size_t)g * Hsz + h0 + hh) * 512 + q * 8);
    }
    CP_COMMIT();
    CP_WAIT(0);
    __syncthreads();

    // t-invariant addresses
    uint32_t abase[2];               // split-K recurrent A frags
    #pragma unroll
    for (int mt = 0; mt < 2; mt++)
        abase[mt] = sb + OFF_AS + (wm0 + mt * 16 + l7 + l8 * 8) * 1040 + l16 * 16 + kh * 512;
    uint32_t bbase2[4];              // Wh2 frags (SMEM)
    #pragma unroll
    for (int nt = 0; nt < 4; nt++)
        bbase2[nt] = sb + (wn0 + nt * 8 + l7) * 1040 + l8 * 16 + kh * 512;
    // producer: full-K tiling
    const int wn0p = (wid >> 1) * 16;
    uint32_t pabase[2], pxbase[2];
    int gc2[2];
    float2 bsv2[2];
    #pragma unroll
    for (int mt = 0; mt < 2; mt++)
        pabase[mt] = sb + OFF_AS + (wm0 + mt * 16 + l7 + l8 * 8) * 1040 + l16 * 16;
    #pragma unroll
    for (int nt = 0; nt < 2; nt++) {
        pxbase[nt] = sb + OFF_WX + (wn0p + nt * 8 + l7) * 1040 + l8 * 16;
        int n = wn0p + nt * 8 + tig * 2;
        int g = n >> 4, hh = n & 15;
        gc2[nt] = g * Hsz + h0 + hh;
        bsv2[nt] = make_float2(bias2[gc2[nt]], bias2[gc2[nt] + 1]);
    }

    const int rr = tid >> 2;
    const int hq = (tid & 3) * 4;
    float cr1[4] = {0.f, 0.f, 0.f, 0.f};
    float cr2[4] = {0.f, 0.f, 0.f, 0.f};

    auto stageA = [&](const __half* hp) {
        #pragma unroll
        for (int i = 0; i < 16; i++) {
            int f4 = tid + i * 256;
            int row = f4 >> 6, u = f4 & 63;
            cp16(sb + OFF_AS + row * 1040 + u * 16, hp + (size_t)row * Hsz + u * 8);
        }
        CP_COMMIT();
        CP_WAIT(0);
    };

    // gates on zs + zxu -> cr + fp16 out (writes to hout row)
    auto gates = [&](uint2* zxu, float* cr, __half* hout) {
        const float* z0 = &zs0[rr * PZ];
        const __half* z1 = &zs1[rr * PZ1];
        float zxa[4][4];
        #pragma unroll
        for (int g = 0; g < 4; g++) {
            __half2* zh = (__half2*)&zxu[g];
            float2 lo = __half22float2(zh[0]);
            float2 hi = __half22float2(zh[1]);
            zxa[g][0] = lo.x; zxa[g][1] = lo.y; zxa[g][2] = hi.x; zxa[g][3] = hi.y;
        }
        __half hv[4];
        #pragma unroll
        for (int j = 0; j < 4; j++) {
            float zg = z0[hq + j]      + __half2float(z1[hq + j])      + zxa[0][j];
            float zi = z0[16 + hq + j] + __half2float(z1[16 + hq + j]) + zxa[1][j];
            float zf = z0[32 + hq + j] + __half2float(z1[32 + hq + j]) + zxa[2][j];
            float zo = z0[48 + hq + j] + __half2float(z1[48 + hq + j]) + zxa[3][j];
            float gg = tanha(zg);
            float ii = sigf(zi);
            float ff = sigf(zf);
            float oo = sigf(zo);
            float cn = __fmaf_rn(gg, ii, cr[j] * ff);
            cr[j] = cn;
            hv[j] = __float2half_rn(tanha(cn) * oo);
        }
        *(uint2*)hout = *(uint2*)hv;
    };

    auto zstage = [&](float (*acc)[4]) {
        #pragma unroll
        for (int u = 0; u < 8; u++) {
            int mt = u >> 2, nt = u & 3;
            int row = wm0 + mt * 16 + gid, col = wn0 + nt * 8 + tig * 2;
            if (kh == 0) {
                *(float2*)&zs0[row * PZ + col]       = make_float2(acc[u][0], acc[u][1]);
                *(float2*)&zs0[(row + 8) * PZ + col] = make_float2(acc[u][2], acc[u][3]);
            } else {
                *(__half2*)&zs1[row * PZ1 + col]       = __floats2half2_rn(acc[u][0], acc[u][1]);
                *(__half2*)&zs1[(row + 8) * PZ1 + col] = __floats2half2_rn(acc[u][2], acc[u][3]);
            }
        }
    };

    #pragma unroll 1
    for (int e = 0; e <= 257; e++) {
        if (e > 0) {
            if (tid == 0) bar_spin(&bar[grp], 32u * (unsigned)e);
            __syncthreads();
        }

        // stage A <- h1(e)
        if (e <= 256) {
            stageA(h1s + (size_t)e * (Bsz * Hsz) + (size_t)m0 * Hsz);
            __syncthreads();
        }

        // layer 1 step e
        if (e <= 255) {
            uint2 zxu[4];
            const __half* zxp = Zx1 + (size_t)e * (Bsz * NG) + (size_t)(m0 + rr) * NG + h0 + hq;
            #pragma unroll
            for (int g = 0; g < 4; g++) zxu[g] = __ldcs((const uint2*)(zxp + g * Hsz));

            float acc[8][4] = {};
            #pragma unroll
            for (int ks = 0; ks < 16; ks++) {
                uint32_t a[2][4];
                ldsm4(a[0], abase[0] + ks * 32);
                ldsm4(a[1], abase[1] + ks * 32);
                #pragma unroll
                for (int mt = 0; mt < 2; mt++)
                    #pragma unroll
                    for (int nt = 0; nt < 4; nt++)
                        mma16(acc[mt * 4 + nt], a[mt], breg[nt][ks]);
            }
            zstage(acc);
            __syncthreads();
            gates(zxu, cr1,
                  h1s + (size_t)(e + 1) * (Bsz * Hsz) + (size_t)(m0 + rr) * Hsz + h0 + hq);
        }

        // producer: Zx2(e-1) from staged h1(e)
        if (e >= 1 && e <= 256) {
            float za[4][4] = {};
            #pragma unroll 8
            for (int ks = 0; ks < 32; ks++) {
                uint32_t a[2][4], b[2][2];
                ldsm4(a[0], pabase[0] + ks * 32);
                ldsm4(a[1], pabase[1] + ks * 32);
                ldsm2(b[0], pxbase[0] + ks * 32);
                ldsm2(b[1], pxbase[1] + ks * 32);
                mma16(za[0], a[0], b[0]); mma16(za[1], a[0], b[1]);
                mma16(za[2], a[1], b[0]); mma16(za[3], a[1], b[1]);
            }
            __half* zb = Zx2 + ((size_t)(e - 1) * Bsz + m0) * NG;
            #pragma unroll
            for (int u = 0; u < 4; u++) {
                int mt = u >> 1, nt = u & 1;
                int row = wm0 + mt * 16 + gid;
                *(__half2*)&zb[(size_t)row * NG + gc2[nt]] =
                    __floats2half2_rn(za[u][0] + bsv2[nt].x, za[u][1] + bsv2[nt].y);
                *(__half2*)&zb[(size_t)(row + 8) * NG + gc2[nt]] =
                    __floats2half2_rn(za[u][2] + bsv2[nt].x, za[u][3] + bsv2[nt].y);
            }
        }
        __syncthreads();   // A + zs consumers done

        // layer 2 step e-2
        if (e >= 2) {
            stageA(h2s + (size_t)(e - 2) * (Bsz * Hsz) + (size_t)m0 * Hsz);
            __syncthreads();

            uint2 zxu[4];
            const __half* zxp = Zx2 + (size_t)(e - 2) * (Bsz * NG) + (size_t)(m0 + rr) * NG + h0 + hq;
            #pragma unroll
            for (int g = 0; g < 4; g++) zxu[g] = __ldcg((const uint2*)(zxp + g * Hsz));

            float acc[8][4] = {};
            #pragma unroll
            for (int ks = 0; ks < 16; ks++) {
                uint32_t a[2][4], b[4][2];
                ldsm4(a[0], abase[0] + ks * 32);
                ldsm4(a[1], abase[1] + ks * 32);
                #pragma unroll
                for (int nt = 0; nt < 4; nt++) ldsm2(b[nt], bbase2[nt] + ks * 32);
                #pragma unroll
                for (int mt = 0; mt < 2; mt++)
                    #pragma unroll
                    for (int nt = 0; nt < 4; nt++)
                        mma16(acc[mt * 4 + nt], a[mt], b[nt]);
            }
            zstage(acc);
            __syncthreads();
            gates(zxu, cr2,
                  h2s + (size_t)(e - 1) * (Bsz * Hsz) + (size_t)(m0 + rr) * Hsz + h0 + hq);
        }

        if (e < 257) {
            __syncthreads();
            if (tid == 0) bar_arrive(&bar[grp]);
        }
    }
}

// ---------------- final projection ----------------
__global__ void proj_kernel(const __half* __restrict__ h2,
                            const float* __restrict__ Wph,
                            const float* __restrict__ bp,
                            float* __restrict__ out) {
    int idx = blockIdx.x * blockDim.x + threadIdx.x;
    if (idx >= Bsz * Csz) return;
    int b = idx / Csz, cc = idx % Csz;
    float s = bp[cc];
    for (int k = 0; k < Hsz; k++)
        s += __half2float(h2[(size_t)b * Hsz + k]) * Wph[(size_t)k * Csz + cc];
    out[idx] = s;
}

// ---------------- launch ----------------
extern "C" void kernel_launch(void* const* d_in, const int* in_sizes, int n_in,
                              void* d_out, int out_size) {
    const float* x   = (const float*)d_in[0];
    const float* Wx1 = (const float*)d_in[1];
    const float* Wh1 = (const float*)d_in[2];
    const float* b1  = (const float*)d_in[3];
    const float* Wx2 = (const float*)d_in[4];
    const float* Wh2 = (const float*)d_in[5];
    const float* b2  = (const float*)d_in[6];
    const float* Wph = (const float*)d_in[7];
    const float* bp  = (const float*)d_in[8];
    float* out = (float*)d_out;

    __half *Zx1, *Zx2, *h1, *h2, *xT, *W1T, *W2T;
    unsigned* bar;
    cudaGetSymbolAddress((void**)&Zx1, g_Zx1);
    cudaGetSymbolAddress((void**)&Zx2, g_Zx2);
    cudaGetSymbolAddress((void**)&h1,  g_h1);
    cudaGetSymbolAddress((void**)&h2,  g_h2);
    cudaGetSymbolAddress((void**)&xT,  g_xT);
    cudaGetSymbolAddress((void**)&W1T, g_W1T);
    cudaGetSymbolAddress((void**)&W2T, g_W2T);
    cudaGetSymbolAddress((void**)&bar, g_bar);

    cudaFuncSetAttribute(lstm_fused, cudaFuncAttributeMaxDynamicSharedMemorySize, PSM);
    cudaFuncSetAttribute(gemm_h2, cudaFuncAttributeMaxDynamicSharedMemorySize, GSM);

    init_kernel<<<(Bsz * Hsz + 255) / 256, 256>>>();

    prep_x<<<(Tt * Bsz * 16 + 255) / 256, 256>>>(x, xT);
    prep_w<<<(4 * Hsz * (Isz / 2) + 255) / 256, 256>>>(Wx1, W1T, Isz);
    prep_w<<<(4 * Hsz * (Hsz / 2) + 255) / 256, 256>>>(Wx2, W2T, Hsz);

    // Phase 1: Zx1 = x @ Wx1 + b1
    gemm_h2<<<dim3(NG / 128, (Tt * Bsz) / 128), 256, GSM>>>(xT, W1T, b1, Zx1, Isz);

    // Phase 2: fused 2-layer recurrence (258 epochs, 1 barrier each)
    lstm_fused<<<dim3(Hsz / 16, Bsz / 64), 256, PSM>>>(
        Zx1, Wh1, Wh2, h1, h2, bar, W2T, b2, Zx2);

    // Phase 3: projection
    proj_kernel<<<(Bsz * Csz + 255) / 256, 256>>>(
        h2 + (size_t)Tt * Bsz * Hsz, Wph, bp, out);
}